// round 2
// baseline (speedup 1.0000x reference)
#include <cuda_runtime.h>
#include <math.h>

#define Tn 2048
#define Cn 384
#define Hn 6
#define HDn 64
#define Bn 2
#define BHn 12
#define ROWS 4096      // B*T
#define C1 385         // C+1
#define N3 1152        // 3C
#define N4 1536        // 4C
#define LOGT 7.62461899f   // ln(2048)

// ---------------- scratch (no allocs allowed) ----------------
__device__ __align__(16) float g_xn[ROWS * C1];
__device__ __align__(16) float g_qkv[ROWS * N3];
__device__ __align__(16) float g_c[(size_t)BHn * Tn * Tn];   // 201 MB
__device__ float g_u[BHn * Tn];
__device__ float g_v[BHn * Tn];
__device__ __align__(16) float g_y[ROWS * Cn];
__device__ __align__(16) float g_h[ROWS * Cn];
__device__ __align__(16) float g_hn[ROWS * C1];
__device__ __align__(16) float g_m[ROWS * N4];

// ---------------- LayerNorm over (x, t) -> width 385 ----------------
__global__ void ln_kernel(const float* __restrict__ x, const float* __restrict__ t,
                          const float* __restrict__ w, const float* __restrict__ bb,
                          float* __restrict__ out) {
    int row = blockIdx.x;
    int tid = threadIdx.x;
    __shared__ float sx[C1];
    __shared__ float red[256];
    float s1 = 0.f;
    for (int c = tid; c < C1; c += 256) {
        float v = (c < Cn) ? x[(size_t)row * Cn + c] : t[0];
        sx[c] = v;
        s1 += v;
    }
    red[tid] = s1; __syncthreads();
    for (int o = 128; o > 0; o >>= 1) { if (tid < o) red[tid] += red[tid + o]; __syncthreads(); }
    float mean = red[0] * (1.f / C1);
    __syncthreads();
    float s2 = 0.f;
    for (int c = tid; c < C1; c += 256) { float d = sx[c] - mean; s2 += d * d; }
    red[tid] = s2; __syncthreads();
    for (int o = 128; o > 0; o >>= 1) { if (tid < o) red[tid] += red[tid + o]; __syncthreads(); }
    float rs = rsqrtf(red[0] * (1.f / C1) + 1e-5f);
    for (int c = tid; c < C1; c += 256)
        out[(size_t)row * C1 + c] = (sx[c] - mean) * rs * w[c] + bb[c];
}

// ---------------- generic fp32 GEMM: C = act(A@B + bias) ----------------
// A: MxK row-major, B: KxN row-major. M,N multiples of 64. act: 0 none, 1 exact gelu
__global__ void gemm64(const float* __restrict__ A, const float* __restrict__ B,
                       const float* __restrict__ bias, float* __restrict__ Cm,
                       int M, int N, int K, int act) {
    __shared__ float As[16][72];
    __shared__ float Bs[16][72];
    int tid = threadIdx.x;
    int tx = tid & 15, ty = tid >> 4;
    int bm = blockIdx.y * 64, bn = blockIdx.x * 64;
    float acc[4][4] = {};
    for (int kt = 0; kt < K; kt += 16) {
        {   // A tile 64x16 -> As[kk][m]
            int r = tid >> 2;
            int ko = (tid & 3) * 4;
            const float* Ap = A + (size_t)(bm + r) * K + kt + ko;
            #pragma unroll
            for (int z = 0; z < 4; z++) {
                float v = (kt + ko + z < K) ? Ap[z] : 0.f;
                As[ko + z][r] = v;
            }
        }
        {   // B tile 16x64 -> Bs[kk][n]
            int kk = tid >> 4;
            int no = (tid & 15) * 4;
            bool ok = (kt + kk < K);
            const float* Bp = B + (size_t)(kt + kk) * N + bn + no;
            #pragma unroll
            for (int z = 0; z < 4; z++)
                Bs[kk][no + z] = ok ? Bp[z] : 0.f;
        }
        __syncthreads();
        #pragma unroll
        for (int kk = 0; kk < 16; kk++) {
            float a0 = As[kk][ty * 4 + 0];
            float a1 = As[kk][ty * 4 + 1];
            float a2 = As[kk][ty * 4 + 2];
            float a3 = As[kk][ty * 4 + 3];
            float b0 = Bs[kk][tx * 4 + 0];
            float b1 = Bs[kk][tx * 4 + 1];
            float b2 = Bs[kk][tx * 4 + 2];
            float b3 = Bs[kk][tx * 4 + 3];
            acc[0][0] += a0 * b0; acc[0][1] += a0 * b1; acc[0][2] += a0 * b2; acc[0][3] += a0 * b3;
            acc[1][0] += a1 * b0; acc[1][1] += a1 * b1; acc[1][2] += a1 * b2; acc[1][3] += a1 * b3;
            acc[2][0] += a2 * b0; acc[2][1] += a2 * b1; acc[2][2] += a2 * b2; acc[2][3] += a2 * b3;
            acc[3][0] += a3 * b0; acc[3][1] += a3 * b1; acc[3][2] += a3 * b2; acc[3][3] += a3 * b3;
        }
        __syncthreads();
    }
    #pragma unroll
    for (int i = 0; i < 4; i++) {
        #pragma unroll
        for (int j = 0; j < 4; j++) {
            int n = bn + tx * 4 + j;
            float v = acc[i][j] + bias[n];
            if (act == 1) v = 0.5f * v * (1.f + erff(v * 0.70710678118654752f));
            Cm[(size_t)(bm + ty * 4 + i) * N + n] = v;
        }
    }
}

// ---------------- attention scores + causal softmax -> g_c (probabilities) ----------------
__global__ void attn_softmax() {
    int i = blockIdx.x;
    int bh = blockIdx.y;
    int b = bh / Hn, h = bh % Hn;
    int tid = threadIdx.x;
    __shared__ float sq[HDn];
    __shared__ float srow[Tn];
    __shared__ float red[256];
    const float* qp = g_qkv + ((size_t)(b * Tn + i)) * N3 + h * HDn;
    if (tid < HDn) sq[tid] = qp[tid];
    __syncthreads();
    for (int j = tid; j <= i; j += 256) {
        const float4* kp = (const float4*)(g_qkv + ((size_t)(b * Tn + j)) * N3 + Cn + h * HDn);
        float d = 0.f;
        #pragma unroll
        for (int z = 0; z < 16; z++) {
            float4 kv = kp[z];
            d += sq[z * 4] * kv.x + sq[z * 4 + 1] * kv.y + sq[z * 4 + 2] * kv.z + sq[z * 4 + 3] * kv.w;
        }
        srow[j] = d * 0.125f;
    }
    __syncthreads();
    float mx = -INFINITY;
    for (int j = tid; j <= i; j += 256) mx = fmaxf(mx, srow[j]);
    red[tid] = mx; __syncthreads();
    for (int o = 128; o > 0; o >>= 1) { if (tid < o) red[tid] = fmaxf(red[tid], red[tid + o]); __syncthreads(); }
    mx = red[0]; __syncthreads();
    float sum = 0.f;
    for (int j = tid; j <= i; j += 256) { float e = __expf(srow[j] - mx); srow[j] = e; sum += e; }
    red[tid] = sum; __syncthreads();
    for (int o = 128; o > 0; o >>= 1) { if (tid < o) red[tid] += red[tid + o]; __syncthreads(); }
    float inv = 1.f / red[0];
    float* crow = g_c + ((size_t)bh * Tn + i) * Tn;
    for (int j = tid; j < Tn; j += 256) crow[j] = (j <= i) ? srow[j] * inv : 0.f;
}

// ---------------- Sinkhorn row pass: u_i = -logT - lse_j(c_ij + v_j) ----------------
__global__ void sink_row(int first) {
    int i = blockIdx.x;
    int bh = blockIdx.y;
    int tid = threadIdx.x;
    const float* crow = g_c + ((size_t)bh * Tn + i) * Tn;
    const float* vv = g_v + bh * Tn;
    float m = -INFINITY, s = 0.f;
    for (int j = tid; j < Tn; j += 256) {
        float x = crow[j] + (first ? 0.f : vv[j]);
        if (x > m) { s = s * __expf(m - x) + 1.f; m = x; } else s += __expf(x - m);
    }
    __shared__ float sm[256], ss[256];
    sm[tid] = m; ss[tid] = s; __syncthreads();
    for (int o = 128; o > 0; o >>= 1) {
        if (tid < o) {
            float m1 = sm[tid], m2 = sm[tid + o];
            float s1 = ss[tid], s2 = ss[tid + o];
            float mm = fmaxf(m1, m2);
            sm[tid] = mm;
            ss[tid] = s1 * __expf(m1 - mm) + s2 * __expf(m2 - mm);
        }
        __syncthreads();
    }
    if (tid == 0) g_u[bh * Tn + i] = -LOGT - (sm[0] + logf(ss[0]));
}

// ---------------- Sinkhorn col pass: v_j = -logT - lse_i(c_ij + u_i) ----------------
__global__ void sink_col() {
    int bh = blockIdx.y;
    int tid = threadIdx.x;
    int j = blockIdx.x * 256 + tid;
    __shared__ float su[Tn];
    for (int i = tid; i < Tn; i += 256) su[i] = g_u[bh * Tn + i];
    __syncthreads();
    const float* cb = g_c + (size_t)bh * Tn * Tn + j;
    float m = -INFINITY, s = 0.f;
    float xb[8];
    for (int i = 0; i < Tn; i += 8) {
        #pragma unroll
        for (int z = 0; z < 8; z++) xb[z] = cb[(size_t)(i + z) * Tn] + su[i + z];
        #pragma unroll
        for (int z = 0; z < 8; z++) {
            float x = xb[z];
            if (x > m) { s = s * __expf(m - x) + 1.f; m = x; } else s += __expf(x - m);
        }
    }
    g_v[bh * Tn + j] = -LOGT - (m + logf(s));
}

// ---------------- y = (exp(c+u+v)*T) @ V ; 16 rows per block ----------------
__global__ void pi_v_kernel() {
    int bh = blockIdx.y;
    int b = bh / Hn, h = bh % Hn;
    int i0 = blockIdx.x * 16;
    int tid = threadIdx.x;
    __shared__ float sv[Tn];
    __shared__ float su[16];
    __shared__ float spi[16][64];
    __shared__ float sV[64][64];
    for (int j = tid; j < Tn; j += 256) sv[j] = g_v[bh * Tn + j];
    if (tid < 16) su[tid] = g_u[bh * Tn + i0 + tid];
    __syncthreads();
    int d = tid & 63, r0 = tid >> 6;   // r0 in 0..3
    float acc0 = 0.f, acc1 = 0.f, acc2 = 0.f, acc3 = 0.f;
    const float* Vbase = g_qkv + ((size_t)b * Tn) * N3 + 2 * Cn + h * HDn;
    const float* Cbase = g_c + ((size_t)bh * Tn + i0) * Tn;
    for (int jc = 0; jc < Tn; jc += 64) {
        for (int idx = tid; idx < 4096; idx += 256) {
            int jj = idx >> 6, dd = idx & 63;
            sV[jj][dd] = Vbase[(size_t)(jc + jj) * N3 + dd];
        }
        for (int idx = tid; idx < 1024; idx += 256) {
            int r = idx >> 6, jj = idx & 63;
            spi[r][jj] = __expf(Cbase[(size_t)r * Tn + jc + jj] + su[r] + sv[jc + jj]) * 2048.f;
        }
        __syncthreads();
        #pragma unroll
        for (int jj = 0; jj < 64; jj++) {
            float vv = sV[jj][d];
            acc0 += spi[r0][jj] * vv;
            acc1 += spi[r0 + 4][jj] * vv;
            acc2 += spi[r0 + 8][jj] * vv;
            acc3 += spi[r0 + 12][jj] * vv;
        }
        __syncthreads();
    }
    size_t base = ((size_t)(b * Tn) + i0) * Cn + h * HDn + d;
    g_y[base + (size_t)(r0)      * Cn] = acc0;
    g_y[base + (size_t)(r0 + 4)  * Cn] = acc1;
    g_y[base + (size_t)(r0 + 8)  * Cn] = acc2;
    g_y[base + (size_t)(r0 + 12) * Cn] = acc3;
}

// ---------------- launch ----------------
extern "C" void kernel_launch(void* const* d_in, const int* in_sizes, int n_in,
                              void* d_out, int out_size) {
    const float* x      = (const float*)d_in[0];
    const float* t      = (const float*)d_in[1];
    const float* ln1_w  = (const float*)d_in[2];
    const float* ln1_b  = (const float*)d_in[3];
    const float* attn_w = (const float*)d_in[4];
    const float* attn_b = (const float*)d_in[5];
    const float* proj_w = (const float*)d_in[6];
    const float* proj_b = (const float*)d_in[7];
    const float* ln2_w  = (const float*)d_in[8];
    const float* ln2_b  = (const float*)d_in[9];
    const float* fc_w   = (const float*)d_in[10];
    const float* fc_b   = (const float*)d_in[11];
    const float* fc2_w  = (const float*)d_in[12];
    const float* fc2_b  = (const float*)d_in[13];
    float* out = (float*)d_out;

    float *p_xn, *p_qkv, *p_y, *p_h, *p_hn, *p_m;
    cudaGetSymbolAddress((void**)&p_xn,  g_xn);
    cudaGetSymbolAddress((void**)&p_qkv, g_qkv);
    cudaGetSymbolAddress((void**)&p_y,   g_y);
    cudaGetSymbolAddress((void**)&p_h,   g_h);
    cudaGetSymbolAddress((void**)&p_hn,  g_hn);
    cudaGetSymbolAddress((void**)&p_m,   g_m);

    // attention sub-block
    ln_kernel<<<ROWS, 256>>>(x, t, ln1_w, ln1_b, p_xn);
    gemm64<<<dim3(N3 / 64, ROWS / 64), 256>>>(p_xn, attn_w, attn_b, p_qkv, ROWS, N3, C1, 0);
    attn_softmax<<<dim3(Tn, BHn), 256>>>();

    // sinkhorn: 6 iterations = 3x (row, col)
    sink_row<<<dim3(Tn, BHn), 256>>>(1);
    sink_col<<<dim3(Tn / 256, BHn), 256>>>();
    sink_row<<<dim3(Tn, BHn), 256>>>(0);
    sink_col<<<dim3(Tn / 256, BHn), 256>>>();
    sink_row<<<dim3(Tn, BHn), 256>>>(0);
    sink_col<<<dim3(Tn / 256, BHn), 256>>>();

    pi_v_kernel<<<dim3(Tn / 16, BHn), 256>>>();
    gemm64<<<dim3(Cn / 64, ROWS / 64), 256>>>(p_y, proj_w, proj_b, p_h, ROWS, Cn, Cn, 0);

    // MLP sub-block
    ln_kernel<<<ROWS, 256>>>(p_h, t, ln2_w, ln2_b, p_hn);
    gemm64<<<dim3(N4 / 64, ROWS / 64), 256>>>(p_hn, fc_w, fc_b, p_m, ROWS, N4, C1, 1);
    gemm64<<<dim3(Cn / 64, ROWS / 64), 256>>>(p_m, fc2_w, fc2_b, out, ROWS, Cn, N4, 0);
}

// round 3
// speedup vs baseline: 1.6943x; 1.6943x over previous
#include <cuda_runtime.h>
#include <cuda_fp16.h>
#include <math.h>

#define Tn 2048
#define Cn 384
#define Hn 6
#define HDn 64
#define Bn 2
#define BHn 12
#define ROWS 4096      // B*T
#define C1 385         // C+1
#define N3 1152        // 3C
#define N4 1536        // 4C
#define LOGT 7.62461899f   // ln(2048)

// ---------------- scratch (no allocs allowed) ----------------
__device__ __align__(16) float g_xn[ROWS * C1];
__device__ __align__(16) float g_qkv[ROWS * N3];
__device__ __align__(16) float g_s[(size_t)BHn * Tn * Tn];     // fp32 scores, 201MB
__device__ __align__(16) __half g_c[(size_t)BHn * Tn * Tn];    // fp16 probs, 100MB
__device__ float g_u[BHn * Tn];
__device__ float g_v[BHn * Tn];
__device__ __align__(16) float g_y[ROWS * Cn];
__device__ __align__(16) float g_h[ROWS * Cn];
__device__ __align__(16) float g_hn[ROWS * C1];
__device__ __align__(16) float g_m[ROWS * N4];

// ---------------- LayerNorm over (x, t) -> width 385 ----------------
__global__ void ln_kernel(const float* __restrict__ x, const float* __restrict__ t,
                          const float* __restrict__ w, const float* __restrict__ bb,
                          float* __restrict__ out) {
    int row = blockIdx.x;
    int tid = threadIdx.x;
    __shared__ float sx[C1];
    __shared__ float red[256];
    float s1 = 0.f;
    for (int c = tid; c < C1; c += 256) {
        float v = (c < Cn) ? x[(size_t)row * Cn + c] : t[0];
        sx[c] = v;
        s1 += v;
    }
    red[tid] = s1; __syncthreads();
    for (int o = 128; o > 0; o >>= 1) { if (tid < o) red[tid] += red[tid + o]; __syncthreads(); }
    float mean = red[0] * (1.f / C1);
    __syncthreads();
    float s2 = 0.f;
    for (int c = tid; c < C1; c += 256) { float d = sx[c] - mean; s2 += d * d; }
    red[tid] = s2; __syncthreads();
    for (int o = 128; o > 0; o >>= 1) { if (tid < o) red[tid] += red[tid + o]; __syncthreads(); }
    float rs = rsqrtf(red[0] * (1.f / C1) + 1e-5f);
    for (int c = tid; c < C1; c += 256)
        out[(size_t)row * C1 + c] = (sx[c] - mean) * rs * w[c] + bb[c];
}

// ---------------- fp32 GEMM 128x128 tile, 8x8/thread ----------------
// A: MxK row-major, B: KxN row-major. M,N multiples of 128. act: 0 none, 1 exact gelu
__global__ void gemm128(const float* __restrict__ A, const float* __restrict__ B,
                        const float* __restrict__ bias, float* __restrict__ Cm,
                        int M, int N, int K, int act) {
    __shared__ float As[16][132];
    __shared__ float Bs[16][132];
    int tid = threadIdx.x;
    int tx = tid & 15, ty = tid >> 4;
    int bm = blockIdx.y * 128, bn = blockIdx.x * 128;
    float acc[8][8] = {};
    for (int kt = 0; kt < K; kt += 16) {
        {   // A tile 128x16 -> As[k][m]  (scalar: K may be odd-strided)
            int m = tid >> 1, k0 = (tid & 1) * 8;
            const float* Ap = A + (size_t)(bm + m) * K + kt + k0;
            #pragma unroll
            for (int z = 0; z < 8; z++)
                As[k0 + z][m] = (kt + k0 + z < K) ? Ap[z] : 0.f;
        }
        {   // B tile 16x128 -> Bs[k][n] (vector)
            int kk = tid >> 4;
            int no = (tid & 15) * 8;
            bool ok = (kt + kk < K);
            const float4* Bp = (const float4*)(B + (size_t)(kt + kk) * N + bn + no);
            float4 z4 = make_float4(0.f, 0.f, 0.f, 0.f);
            *(float4*)&Bs[kk][no]     = ok ? Bp[0] : z4;
            *(float4*)&Bs[kk][no + 4] = ok ? Bp[1] : z4;
        }
        __syncthreads();
        #pragma unroll
        for (int kk = 0; kk < 16; kk++) {
            float4 a0 = *(const float4*)&As[kk][ty * 4];
            float4 a1 = *(const float4*)&As[kk][ty * 4 + 64];
            float4 b0 = *(const float4*)&Bs[kk][tx * 4];
            float4 b1 = *(const float4*)&Bs[kk][tx * 4 + 64];
            float a[8] = {a0.x, a0.y, a0.z, a0.w, a1.x, a1.y, a1.z, a1.w};
            float b[8] = {b0.x, b0.y, b0.z, b0.w, b1.x, b1.y, b1.z, b1.w};
            #pragma unroll
            for (int i = 0; i < 8; i++)
                #pragma unroll
                for (int j = 0; j < 8; j++)
                    acc[i][j] += a[i] * b[j];
        }
        __syncthreads();
    }
    #pragma unroll
    for (int i = 0; i < 8; i++) {
        int m = bm + ty * 4 + ((i < 4) ? i : 60 + i);
        #pragma unroll
        for (int j = 0; j < 8; j++) {
            int n = bn + tx * 4 + ((j < 4) ? j : 60 + j);
            float v = acc[i][j] + bias[n];
            if (act == 1) v = 0.5f * v * (1.f + erff(v * 0.70710678118654752f));
            Cm[(size_t)m * N + n] = v;
        }
    }
}

// ---------------- attention scores: s = q@k^T * 0.125, causal tile-skip ----------------
__global__ void score128() {
    int jt = blockIdx.x, it = blockIdx.y, bh = blockIdx.z;
    if (jt > it) return;
    int b = bh / Hn, h = bh % Hn;
    const float* Q  = g_qkv + (size_t)b * Tn * N3 + h * HDn;
    const float* Kp = g_qkv + (size_t)b * Tn * N3 + Cn + h * HDn;
    __shared__ float Qs[16][132];
    __shared__ float Ks[16][132];
    int tid = threadIdx.x;
    int tx = tid & 15, ty = tid >> 4;
    float acc[8][8] = {};
    int m = tid >> 1, k0 = (tid & 1) * 8;
    for (int kt = 0; kt < HDn; kt += 16) {
        {
            const float4* Qp = (const float4*)(Q + (size_t)(it * 128 + m) * N3 + kt + k0);
            float4 q0 = Qp[0], q1 = Qp[1];
            Qs[k0 + 0][m] = q0.x; Qs[k0 + 1][m] = q0.y; Qs[k0 + 2][m] = q0.z; Qs[k0 + 3][m] = q0.w;
            Qs[k0 + 4][m] = q1.x; Qs[k0 + 5][m] = q1.y; Qs[k0 + 6][m] = q1.z; Qs[k0 + 7][m] = q1.w;
            const float4* Kq = (const float4*)(Kp + (size_t)(jt * 128 + m) * N3 + kt + k0);
            float4 c0 = Kq[0], c1 = Kq[1];
            Ks[k0 + 0][m] = c0.x; Ks[k0 + 1][m] = c0.y; Ks[k0 + 2][m] = c0.z; Ks[k0 + 3][m] = c0.w;
            Ks[k0 + 4][m] = c1.x; Ks[k0 + 5][m] = c1.y; Ks[k0 + 6][m] = c1.z; Ks[k0 + 7][m] = c1.w;
        }
        __syncthreads();
        #pragma unroll
        for (int kk = 0; kk < 16; kk++) {
            float4 a0 = *(const float4*)&Qs[kk][ty * 4];
            float4 a1 = *(const float4*)&Qs[kk][ty * 4 + 64];
            float4 b0 = *(const float4*)&Ks[kk][tx * 4];
            float4 b1 = *(const float4*)&Ks[kk][tx * 4 + 64];
            float a[8] = {a0.x, a0.y, a0.z, a0.w, a1.x, a1.y, a1.z, a1.w};
            float b[8] = {b0.x, b0.y, b0.z, b0.w, b1.x, b1.y, b1.z, b1.w};
            #pragma unroll
            for (int i = 0; i < 8; i++)
                #pragma unroll
                for (int j = 0; j < 8; j++)
                    acc[i][j] += a[i] * b[j];
        }
        __syncthreads();
    }
    float* srow = g_s + (size_t)bh * Tn * Tn;
    #pragma unroll
    for (int i = 0; i < 8; i++) {
        int gi = it * 128 + ty * 4 + ((i < 4) ? i : 60 + i);
        #pragma unroll
        for (int j = 0; j < 8; j++) {
            int gj = jt * 128 + tx * 4 + ((j < 4) ? j : 60 + j);
            srow[(size_t)gi * Tn + gj] = acc[i][j] * 0.125f;
        }
    }
}

// ---------------- softmax per row + fp16 store + first sinkhorn row pass ----------------
__global__ void softmax_u1() {
    int i = blockIdx.x, bh = blockIdx.y;
    int tid = threadIdx.x;
    const float* srow = g_s + ((size_t)bh * Tn + i) * Tn;
    __half* crow = g_c + ((size_t)bh * Tn + i) * Tn;
    __shared__ float sp[Tn];
    __shared__ float red[256];
    float mx = -INFINITY;
    for (int j = tid; j <= i; j += 256) { float v = srow[j]; sp[j] = v; mx = fmaxf(mx, v); }
    red[tid] = mx; __syncthreads();
    for (int o = 128; o > 0; o >>= 1) { if (tid < o) red[tid] = fmaxf(red[tid], red[tid + o]); __syncthreads(); }
    mx = red[0]; __syncthreads();
    float sum = 0.f;
    for (int j = tid; j <= i; j += 256) { float e = __expf(sp[j] - mx); sp[j] = e; sum += e; }
    red[tid] = sum; __syncthreads();
    for (int o = 128; o > 0; o >>= 1) { if (tid < o) red[tid] += red[tid + o]; __syncthreads(); }
    float inv = 1.f / red[0];
    __syncthreads();
    // write probs (fp16) and accumulate sum of exp(prob) for u1
    float se = 0.f;
    __half2* crow2 = (__half2*)crow;
    for (int jp = tid; jp < Tn / 2; jp += 256) {
        int j0 = jp * 2, j1 = j0 + 1;
        float p0 = (j0 <= i) ? sp[j0] * inv : 0.f;
        float p1 = (j1 <= i) ? sp[j1] * inv : 0.f;
        crow2[jp] = __floats2half2_rn(p0, p1);
        if (j0 <= i) se += __expf(p0);
        if (j1 <= i) se += __expf(p1);
    }
    red[tid] = se; __syncthreads();
    for (int o = 128; o > 0; o >>= 1) { if (tid < o) red[tid] += red[tid + o]; __syncthreads(); }
    if (tid == 0)
        g_u[bh * Tn + i] = -LOGT - __logf(red[0] + (float)(Tn - 1 - i));
}

// ---------------- Sinkhorn row pass: u_i = -logT - log(sum_j exp(c_ij + v_j)) ----------------
// 4 rows per block; branch-free (args bounded, no max needed in fp32)
__global__ void sink_row_f() {
    int r0 = blockIdx.x * 4, bh = blockIdx.y;
    int tid = threadIdx.x;
    __shared__ float sv[Tn];
    __shared__ float red[256];
    for (int j = tid; j < Tn; j += 256) sv[j] = g_v[bh * Tn + j];
    __syncthreads();
    for (int r = 0; r < 4; r++) {
        int i = r0 + r;
        const __half* crow = g_c + ((size_t)bh * Tn + i) * Tn;
        const uint4* cv = (const uint4*)crow;
        uint4 pk = cv[tid];   // 8 halfs
        const __half* hp = (const __half*)&pk;
        float s = 0.f;
        int jb = tid * 8;
        #pragma unroll
        for (int z = 0; z < 8; z++)
            s += __expf(__half2float(hp[z]) + sv[jb + z]);
        red[tid] = s; __syncthreads();
        for (int o = 128; o > 0; o >>= 1) { if (tid < o) red[tid] += red[tid + o]; __syncthreads(); }
        if (tid == 0) g_u[bh * Tn + i] = -LOGT - __logf(red[0]);
        __syncthreads();
    }
}

// ---------------- Sinkhorn col pass: v_j = -logT - log(sum_i exp(c_ij + u_i)) ----------------
// each thread owns 2 adjacent columns (half2 loads)
__global__ void sink_col_f() {
    int bh = blockIdx.y;
    int tid = threadIdx.x;
    int j0 = (blockIdx.x * 256 + tid) * 2;
    __shared__ float su[Tn];
    for (int i = tid; i < Tn; i += 256) su[i] = g_u[bh * Tn + i];
    __syncthreads();
    const __half* cb = g_c + (size_t)bh * Tn * Tn + j0;
    float s0 = 0.f, s1 = 0.f;
    #pragma unroll 4
    for (int i = 0; i < Tn; i++) {
        __half2 hh = *(const __half2*)(cb + (size_t)i * Tn);
        float2 f = __half22float2(hh);
        float ui = su[i];
        s0 += __expf(f.x + ui);
        s1 += __expf(f.y + ui);
    }
    g_v[bh * Tn + j0]     = -LOGT - __logf(s0);
    g_v[bh * Tn + j0 + 1] = -LOGT - __logf(s1);
}

// ---------------- y = (exp(c+u+v)*T) @ V ; 16 rows per block ----------------
__global__ void pi_v_kernel() {
    int bh = blockIdx.y;
    int b = bh / Hn, h = bh % Hn;
    int i0 = blockIdx.x * 16;
    int tid = threadIdx.x;
    __shared__ float sv[Tn];
    __shared__ float su[16];
    __shared__ float spi[16][64];
    __shared__ float sV[64][64];
    for (int j = tid; j < Tn; j += 256) sv[j] = g_v[bh * Tn + j];
    if (tid < 16) su[tid] = g_u[bh * Tn + i0 + tid];
    __syncthreads();
    int d = tid & 63, r0 = tid >> 6;   // r0 in 0..3
    float acc0 = 0.f, acc1 = 0.f, acc2 = 0.f, acc3 = 0.f;
    const float* Vbase = g_qkv + ((size_t)b * Tn) * N3 + 2 * Cn + h * HDn;
    const __half* Cbase = g_c + ((size_t)bh * Tn + i0) * Tn;
    for (int jc = 0; jc < Tn; jc += 64) {
        for (int idx = tid; idx < 4096; idx += 256) {
            int jj = idx >> 6, dd = idx & 63;
            sV[jj][dd] = Vbase[(size_t)(jc + jj) * N3 + dd];
        }
        for (int idx = tid; idx < 1024; idx += 256) {
            int r = idx >> 6, jj = idx & 63;
            float cc = __half2float(Cbase[(size_t)r * Tn + jc + jj]);
            spi[r][jj] = __expf(cc + su[r] + sv[jc + jj]) * 2048.f;
        }
        __syncthreads();
        #pragma unroll
        for (int jj = 0; jj < 64; jj++) {
            float vv = sV[jj][d];
            acc0 += spi[r0][jj] * vv;
            acc1 += spi[r0 + 4][jj] * vv;
            acc2 += spi[r0 + 8][jj] * vv;
            acc3 += spi[r0 + 12][jj] * vv;
        }
        __syncthreads();
    }
    size_t base = ((size_t)(b * Tn) + i0) * Cn + h * HDn + d;
    g_y[base + (size_t)(r0)      * Cn] = acc0;
    g_y[base + (size_t)(r0 + 4)  * Cn] = acc1;
    g_y[base + (size_t)(r0 + 8)  * Cn] = acc2;
    g_y[base + (size_t)(r0 + 12) * Cn] = acc3;
}

// ---------------- launch ----------------
extern "C" void kernel_launch(void* const* d_in, const int* in_sizes, int n_in,
                              void* d_out, int out_size) {
    const float* x      = (const float*)d_in[0];
    const float* t      = (const float*)d_in[1];
    const float* ln1_w  = (const float*)d_in[2];
    const float* ln1_b  = (const float*)d_in[3];
    const float* attn_w = (const float*)d_in[4];
    const float* attn_b = (const float*)d_in[5];
    const float* proj_w = (const float*)d_in[6];
    const float* proj_b = (const float*)d_in[7];
    const float* ln2_w  = (const float*)d_in[8];
    const float* ln2_b  = (const float*)d_in[9];
    const float* fc_w   = (const float*)d_in[10];
    const float* fc_b   = (const float*)d_in[11];
    const float* fc2_w  = (const float*)d_in[12];
    const float* fc2_b  = (const float*)d_in[13];
    float* out = (float*)d_out;

    float *p_xn, *p_qkv, *p_y, *p_h, *p_hn, *p_m;
    cudaGetSymbolAddress((void**)&p_xn,  g_xn);
    cudaGetSymbolAddress((void**)&p_qkv, g_qkv);
    cudaGetSymbolAddress((void**)&p_y,   g_y);
    cudaGetSymbolAddress((void**)&p_h,   g_h);
    cudaGetSymbolAddress((void**)&p_hn,  g_hn);
    cudaGetSymbolAddress((void**)&p_m,   g_m);

    // attention sub-block
    ln_kernel<<<ROWS, 256>>>(x, t, ln1_w, ln1_b, p_xn);
    gemm128<<<dim3(N3 / 128, ROWS / 128), 256>>>(p_xn, attn_w, attn_b, p_qkv, ROWS, N3, C1, 0);
    score128<<<dim3(Tn / 128, Tn / 128, BHn), 256>>>();
    softmax_u1<<<dim3(Tn, BHn), 256>>>();

    // sinkhorn remaining 5 passes: col,row,col,row,col
    sink_col_f<<<dim3(Tn / 512, BHn), 256>>>();
    sink_row_f<<<dim3(Tn / 4, BHn), 256>>>();
    sink_col_f<<<dim3(Tn / 512, BHn), 256>>>();
    sink_row_f<<<dim3(Tn / 4, BHn), 256>>>();
    sink_col_f<<<dim3(Tn / 512, BHn), 256>>>();

    pi_v_kernel<<<dim3(Tn / 16, BHn), 256>>>();
    gemm128<<<dim3(Cn / 128, ROWS / 128), 256>>>(p_y, proj_w, proj_b, p_h, ROWS, Cn, Cn, 0);

    // MLP sub-block
    ln_kernel<<<ROWS, 256>>>(p_h, t, ln2_w, ln2_b, p_hn);
    gemm128<<<dim3(N4 / 128, ROWS / 128), 256>>>(p_hn, fc_w, fc_b, p_m, ROWS, N4, C1, 1);
    gemm128<<<dim3(Cn / 128, ROWS / 128), 256>>>(p_m, fc2_w, fc2_b, out, ROWS, Cn, N4, 0);
}

// round 4
// speedup vs baseline: 2.2652x; 1.3369x over previous
#include <cuda_runtime.h>
#include <cuda_fp16.h>
#include <math.h>

#define Tn 2048
#define Cn 384
#define Hn 6
#define HDn 64
#define Bn 2
#define BHn 12
#define ROWS 4096      // B*T
#define C1 385         // C+1
#define N3 1152        // 3C
#define N4 1536        // 4C
#define LOGT 7.62461899f   // ln(2048)

// ---------------- scratch (no allocs allowed) ----------------
__device__ __align__(16) float g_xn[ROWS * C1];
__device__ __align__(16) float g_qkv[ROWS * N3];
__device__ __align__(16) float g_s[(size_t)BHn * Tn * Tn];     // fp32 scores
__device__ __align__(16) __half g_c[(size_t)BHn * Tn * Tn];    // fp16 Em1 = exp(prob)-1 (0 above diag)
__device__ float g_u[BHn * Tn];
__device__ float g_v[BHn * Tn];
__device__ float g_eu[BHn * Tn];
__device__ float g_ev[BHn * Tn];
__device__ float g_eutot[BHn];
__device__ float g_evtot[BHn];
__device__ float g_wtot[BHn * HDn];
__device__ __align__(16) float g_y[ROWS * Cn];
__device__ __align__(16) float g_h[ROWS * Cn];
__device__ __align__(16) float g_hn[ROWS * C1];
__device__ __align__(16) float g_m[ROWS * N4];

// ---------------- f32x2 helpers ----------------
__device__ __forceinline__ unsigned long long pk_dup(float a) {
    unsigned long long r;
    asm("mov.b64 %0,{%1,%1};" : "=l"(r) : "f"(a));
    return r;
}
__device__ __forceinline__ void fma2(unsigned long long& acc, unsigned long long a, unsigned long long b) {
    asm("fma.rn.f32x2 %0,%1,%2,%0;" : "+l"(acc) : "l"(a), "l"(b));
}
__device__ __forceinline__ float2 upk(unsigned long long x) {
    float2 f;
    asm("mov.b64 {%0,%1},%2;" : "=f"(f.x), "=f"(f.y) : "l"(x));
    return f;
}

// ---------------- LayerNorm over (x, t) -> width 385 ----------------
__global__ void ln_kernel(const float* __restrict__ x, const float* __restrict__ t,
                          const float* __restrict__ w, const float* __restrict__ bb,
                          float* __restrict__ out) {
    int row = blockIdx.x;
    int tid = threadIdx.x;
    __shared__ float sx[C1];
    __shared__ float red[256];
    float s1 = 0.f;
    for (int c = tid; c < C1; c += 256) {
        float v = (c < Cn) ? x[(size_t)row * Cn + c] : t[0];
        sx[c] = v;
        s1 += v;
    }
    red[tid] = s1; __syncthreads();
    for (int o = 128; o > 0; o >>= 1) { if (tid < o) red[tid] += red[tid + o]; __syncthreads(); }
    float mean = red[0] * (1.f / C1);
    __syncthreads();
    float s2 = 0.f;
    for (int c = tid; c < C1; c += 256) { float d = sx[c] - mean; s2 += d * d; }
    red[tid] = s2; __syncthreads();
    for (int o = 128; o > 0; o >>= 1) { if (tid < o) red[tid] += red[tid + o]; __syncthreads(); }
    float rs = rsqrtf(red[0] * (1.f / C1) + 1e-5f);
    for (int c = tid; c < C1; c += 256)
        out[(size_t)row * C1 + c] = (sx[c] - mean) * rs * w[c] + bb[c];
}

// ---------------- fp32 GEMM 128x128 tile, 8x8/thread, f32x2 FMA ----------------
__global__ void gemm128(const float* __restrict__ A, const float* __restrict__ B,
                        const float* __restrict__ bias, float* __restrict__ Cm,
                        int M, int N, int K, int act) {
    __shared__ float As[16][132];
    __shared__ float Bs[16][132];
    int tid = threadIdx.x;
    int tx = tid & 15, ty = tid >> 4;
    int bm = blockIdx.y * 128, bn = blockIdx.x * 128;
    unsigned long long acc2[8][4] = {};
    for (int kt = 0; kt < K; kt += 16) {
        {   // A tile 128x16 -> As[k][m]
            int m = tid >> 1, k0 = (tid & 1) * 8;
            const float* Ap = A + (size_t)(bm + m) * K + kt + k0;
            #pragma unroll
            for (int z = 0; z < 8; z++)
                As[k0 + z][m] = (kt + k0 + z < K) ? Ap[z] : 0.f;
        }
        {   // B tile 16x128 -> Bs[k][n]
            int kk = tid >> 4;
            int no = (tid & 15) * 8;
            bool ok = (kt + kk < K);
            const float4* Bp = (const float4*)(B + (size_t)(kt + kk) * N + bn + no);
            float4 z4 = make_float4(0.f, 0.f, 0.f, 0.f);
            *(float4*)&Bs[kk][no]     = ok ? Bp[0] : z4;
            *(float4*)&Bs[kk][no + 4] = ok ? Bp[1] : z4;
        }
        __syncthreads();
        #pragma unroll
        for (int kk = 0; kk < 16; kk++) {
            float4 a0 = *(const float4*)&As[kk][ty * 4];
            float4 a1 = *(const float4*)&As[kk][ty * 4 + 64];
            float a[8] = {a0.x, a0.y, a0.z, a0.w, a1.x, a1.y, a1.z, a1.w};
            const unsigned long long* bp0 = (const unsigned long long*)&Bs[kk][tx * 4];
            const unsigned long long* bp1 = (const unsigned long long*)&Bs[kk][tx * 4 + 64];
            unsigned long long bq[4] = {bp0[0], bp0[1], bp1[0], bp1[1]};
            #pragma unroll
            for (int i = 0; i < 8; i++) {
                unsigned long long ap = pk_dup(a[i]);
                fma2(acc2[i][0], ap, bq[0]);
                fma2(acc2[i][1], ap, bq[1]);
                fma2(acc2[i][2], ap, bq[2]);
                fma2(acc2[i][3], ap, bq[3]);
            }
        }
        __syncthreads();
    }
    #pragma unroll
    for (int i = 0; i < 8; i++) {
        int m = bm + ty * 4 + ((i < 4) ? i : 60 + i);
        #pragma unroll
        for (int jp = 0; jp < 4; jp++) {
            float2 f = upk(acc2[i][jp]);
            int jj0 = 2 * jp;
            int n0 = bn + tx * 4 + ((jj0 < 4) ? jj0 : 60 + jj0);
            float v0 = f.x + bias[n0];
            float v1 = f.y + bias[n0 + 1];
            if (act == 1) {
                v0 = 0.5f * v0 * (1.f + erff(v0 * 0.70710678118654752f));
                v1 = 0.5f * v1 * (1.f + erff(v1 * 0.70710678118654752f));
            }
            Cm[(size_t)m * N + n0] = v0;
            Cm[(size_t)m * N + n0 + 1] = v1;
        }
    }
}

// ---------------- attention scores (lower tiles only), f32x2 FMA ----------------
__global__ void score128() {
    int jt = blockIdx.x, it = blockIdx.y, bh = blockIdx.z;
    if (jt > it) return;
    int b = bh / Hn, h = bh % Hn;
    const float* Q  = g_qkv + (size_t)b * Tn * N3 + h * HDn;
    const float* Kp = g_qkv + (size_t)b * Tn * N3 + Cn + h * HDn;
    __shared__ float Qs[16][132];
    __shared__ float Ks[16][132];
    int tid = threadIdx.x;
    int tx = tid & 15, ty = tid >> 4;
    unsigned long long acc2[8][4] = {};
    int m = tid >> 1, k0 = (tid & 1) * 8;
    for (int kt = 0; kt < HDn; kt += 16) {
        {
            const float4* Qp = (const float4*)(Q + (size_t)(it * 128 + m) * N3 + kt + k0);
            float4 q0 = Qp[0], q1 = Qp[1];
            Qs[k0 + 0][m] = q0.x; Qs[k0 + 1][m] = q0.y; Qs[k0 + 2][m] = q0.z; Qs[k0 + 3][m] = q0.w;
            Qs[k0 + 4][m] = q1.x; Qs[k0 + 5][m] = q1.y; Qs[k0 + 6][m] = q1.z; Qs[k0 + 7][m] = q1.w;
            const float4* Kq = (const float4*)(Kp + (size_t)(jt * 128 + m) * N3 + kt + k0);
            float4 c0 = Kq[0], c1 = Kq[1];
            Ks[k0 + 0][m] = c0.x; Ks[k0 + 1][m] = c0.y; Ks[k0 + 2][m] = c0.z; Ks[k0 + 3][m] = c0.w;
            Ks[k0 + 4][m] = c1.x; Ks[k0 + 5][m] = c1.y; Ks[k0 + 6][m] = c1.z; Ks[k0 + 7][m] = c1.w;
        }
        __syncthreads();
        #pragma unroll
        for (int kk = 0; kk < 16; kk++) {
            float4 a0 = *(const float4*)&Qs[kk][ty * 4];
            float4 a1 = *(const float4*)&Qs[kk][ty * 4 + 64];
            float a[8] = {a0.x, a0.y, a0.z, a0.w, a1.x, a1.y, a1.z, a1.w};
            const unsigned long long* bp0 = (const unsigned long long*)&Ks[kk][tx * 4];
            const unsigned long long* bp1 = (const unsigned long long*)&Ks[kk][tx * 4 + 64];
            unsigned long long bq[4] = {bp0[0], bp0[1], bp1[0], bp1[1]};
            #pragma unroll
            for (int i = 0; i < 8; i++) {
                unsigned long long ap = pk_dup(a[i]);
                fma2(acc2[i][0], ap, bq[0]);
                fma2(acc2[i][1], ap, bq[1]);
                fma2(acc2[i][2], ap, bq[2]);
                fma2(acc2[i][3], ap, bq[3]);
            }
        }
        __syncthreads();
    }
    float* srow = g_s + (size_t)bh * Tn * Tn;
    #pragma unroll
    for (int i = 0; i < 8; i++) {
        int gi = it * 128 + ty * 4 + ((i < 4) ? i : 60 + i);
        #pragma unroll
        for (int jp = 0; jp < 4; jp++) {
            float2 f = upk(acc2[i][jp]);
            int jj0 = 2 * jp;
            int gj = jt * 128 + tx * 4 + ((jj0 < 4) ? jj0 : 60 + jj0);
            srow[(size_t)gi * Tn + gj] = f.x * 0.125f;
            srow[(size_t)gi * Tn + gj + 1] = f.y * 0.125f;
        }
    }
}

// ---------------- softmax per row -> Em1 fp16 (lower tri, zero-padded to 8) + u1, eu ----------------
__global__ void softmax_u1() {
    int i = blockIdx.x, bh = blockIdx.y;
    int tid = threadIdx.x;
    const float* srow = g_s + ((size_t)bh * Tn + i) * Tn;
    __half2* crow2 = (__half2*)(g_c + ((size_t)bh * Tn + i) * Tn);
    __shared__ float sp[Tn];
    __shared__ float red[256];
    float mx = -INFINITY;
    for (int j = tid; j <= i; j += 256) { float v = srow[j]; sp[j] = v; mx = fmaxf(mx, v); }
    red[tid] = mx; __syncthreads();
    for (int o = 128; o > 0; o >>= 1) { if (tid < o) red[tid] = fmaxf(red[tid], red[tid + o]); __syncthreads(); }
    mx = red[0]; __syncthreads();
    float sum = 0.f;
    for (int j = tid; j <= i; j += 256) { float e = __expf(sp[j] - mx); sp[j] = e; sum += e; }
    red[tid] = sum; __syncthreads();
    for (int o = 128; o > 0; o >>= 1) { if (tid < o) red[tid] += red[tid + o]; __syncthreads(); }
    float inv = 1.f / red[0];
    __syncthreads();
    // write Em1 = exp(p)-1 for j<=i, zeros padding to 8-boundary; accumulate sum(Em1)
    float se = 0.f;
    int lim2 = ((i + 8) >> 3) * 4;   // half2 count covering padded region
    for (int jp = tid; jp < lim2; jp += 256) {
        int j0 = jp * 2, j1 = j0 + 1;
        float e0 = (j0 <= i) ? (__expf(sp[j0] * inv) - 1.f) : 0.f;
        float e1 = (j1 <= i) ? (__expf(sp[j1] * inv) - 1.f) : 0.f;
        crow2[jp] = __floats2half2_rn(e0, e1);
        se += e0 + e1;
    }
    red[tid] = se; __syncthreads();
    for (int o = 128; o > 0; o >>= 1) { if (tid < o) red[tid] += red[tid + o]; __syncthreads(); }
    if (tid == 0) {
        float u = -LOGT - __logf(red[0] + (float)Tn);
        g_u[bh * Tn + i] = u;
        g_eu[bh * Tn + i] = __expf(u);
    }
}

// ---------------- reduce a [BHn][Tn] vector to per-bh totals ----------------
__global__ void tot_kernel(const float* __restrict__ vec, float* __restrict__ tot) {
    int bh = blockIdx.x, tid = threadIdx.x;
    __shared__ float red[256];
    float s = 0.f;
    for (int i = tid; i < Tn; i += 256) s += vec[bh * Tn + i];
    red[tid] = s; __syncthreads();
    for (int o = 128; o > 0; o >>= 1) { if (tid < o) red[tid] += red[tid + o]; __syncthreads(); }
    if (tid == 0) tot[bh] = red[0];
}

// ---------------- Sinkhorn row pass: u_i = -logT - log(dot(Em1_i, ev) + evtot) ----------------
__global__ void sink_row_f() {
    int r0 = blockIdx.x * 8, bh = blockIdx.y;
    int tid = threadIdx.x;
    __shared__ float sev[Tn];
    __shared__ float red[256];
    int jmax = r0 + 8;
    for (int j = tid; j < jmax; j += 256) sev[j] = g_ev[bh * Tn + j];
    float evtot = g_evtot[bh];
    __syncthreads();
    for (int r = 0; r < 8; r++) {
        int i = r0 + r;
        const uint4* cv = (const uint4*)(g_c + ((size_t)bh * Tn + i) * Tn);
        int nv = (i + 8) >> 3;
        float s = 0.f;
        for (int vi = tid; vi < nv; vi += 256) {
            uint4 pk = cv[vi];
            const __half2* hp = (const __half2*)&pk;
            int jb = vi * 8;
            #pragma unroll
            for (int z = 0; z < 4; z++) {
                float2 f = __half22float2(hp[z]);
                s += f.x * sev[jb + 2 * z] + f.y * sev[jb + 2 * z + 1];
            }
        }
        red[tid] = s; __syncthreads();
        for (int o = 128; o > 0; o >>= 1) { if (tid < o) red[tid] += red[tid + o]; __syncthreads(); }
        if (tid == 0) {
            float u = -LOGT - __logf(red[0] + evtot);
            g_u[bh * Tn + i] = u;
            g_eu[bh * Tn + i] = __expf(u);
        }
        __syncthreads();
    }
}

// ---------------- Sinkhorn col pass: v_j = -logT - log(dotcol(Em1_:,j, eu) + eutot) ----------------
__global__ void sink_col_f() {
    int bh = blockIdx.y;
    int tid = threadIdx.x;
    int j0 = (blockIdx.x * 256 + tid) * 2;
    int ibase = blockIdx.x * 512;
    __shared__ float seu[Tn];
    for (int i = tid; i < Tn - ibase; i += 256) seu[i] = g_eu[bh * Tn + ibase + i];
    float eutot = g_eutot[bh];
    __syncthreads();
    const __half* cb = g_c + (size_t)bh * Tn * Tn + j0;
    float s0 = 0.f, s1 = 0.f;
    #pragma unroll 4
    for (int i = j0; i < Tn; i++) {
        __half2 hh = *(const __half2*)(cb + (size_t)i * Tn);
        float2 f = __half22float2(hh);
        float ui = seu[i - ibase];
        s0 += f.x * ui;
        s1 += f.y * ui;
    }
    float v0 = -LOGT - __logf(s0 + eutot);
    float v1 = -LOGT - __logf(s1 + eutot);
    g_v[bh * Tn + j0]     = v0;
    g_v[bh * Tn + j0 + 1] = v1;
    g_ev[bh * Tn + j0]     = __expf(v0);
    g_ev[bh * Tn + j0 + 1] = __expf(v1);
}

// ---------------- Wtot_d = sum_j ev_j * V_jd (per bh) ----------------
__global__ void wtot_kernel() {
    int bh = blockIdx.x;
    int b = bh / Hn, h = bh % Hn;
    int tid = threadIdx.x;
    int d = tid & 63, rr = tid >> 6;
    const float* Vbase = g_qkv + (size_t)b * Tn * N3 + 2 * Cn + h * HDn;
    float acc = 0.f;
    for (int i = rr; i < Tn; i += 4)
        acc += g_ev[bh * Tn + i] * Vbase[(size_t)i * N3 + d];
    __shared__ float red[256];
    red[tid] = acc; __syncthreads();
    if (tid < 128) red[tid] += red[tid + 128];
    __syncthreads();
    if (tid < 64) g_wtot[bh * HDn + tid] = red[tid] + red[tid + 64];
}

// ---------------- y_i = T*eu_i*(sum_{j<=i} Em1*ev*V + Wtot) ; 16 rows/block ----------------
__global__ void pi_v_kernel() {
    int bh = blockIdx.y;
    int b = bh / Hn, h = bh % Hn;
    int i0 = blockIdx.x * 16;
    int tid = threadIdx.x;
    __shared__ float sev[Tn];
    __shared__ float spi[16][64];
    __shared__ float sV[64][64];
    int jmaxt = i0 + 16;
    for (int j = tid; j < jmaxt; j += 256) sev[j] = g_ev[bh * Tn + j];
    __syncthreads();
    int d = tid & 63, r0 = tid >> 6;
    float acc0 = 0.f, acc1 = 0.f, acc2 = 0.f, acc3 = 0.f;
    const float* Vbase = g_qkv + (size_t)b * Tn * N3 + 2 * Cn + h * HDn;
    const __half* Cbase = g_c + ((size_t)bh * Tn + i0) * Tn;
    int jend = ((i0 + 16 + 63) >> 6) << 6;
    for (int jc = 0; jc < jend; jc += 64) {
        for (int idx = tid; idx < 4096; idx += 256) {
            int jj = idx >> 6, dd = idx & 63;
            sV[jj][dd] = Vbase[(size_t)(jc + jj) * N3 + dd];
        }
        for (int idx = tid; idx < 1024; idx += 256) {
            int r = idx >> 6, jj = idx & 63;
            int j = jc + jj;
            float e = 0.f;
            if (j <= i0 + r) e = __half2float(Cbase[(size_t)r * Tn + j]);
            spi[r][jj] = e * sev[j];
        }
        __syncthreads();
        #pragma unroll
        for (int jj = 0; jj < 64; jj++) {
            float vv = sV[jj][d];
            acc0 += spi[r0][jj] * vv;
            acc1 += spi[r0 + 4][jj] * vv;
            acc2 += spi[r0 + 8][jj] * vv;
            acc3 += spi[r0 + 12][jj] * vv;
        }
        __syncthreads();
    }
    float wt = g_wtot[bh * HDn + d];
    size_t base = ((size_t)(b * Tn) + i0) * Cn + h * HDn + d;
    g_y[base + (size_t)(r0)      * Cn] = (acc0 + wt) * 2048.f * g_eu[bh * Tn + i0 + r0];
    g_y[base + (size_t)(r0 + 4)  * Cn] = (acc1 + wt) * 2048.f * g_eu[bh * Tn + i0 + r0 + 4];
    g_y[base + (size_t)(r0 + 8)  * Cn] = (acc2 + wt) * 2048.f * g_eu[bh * Tn + i0 + r0 + 8];
    g_y[base + (size_t)(r0 + 12) * Cn] = (acc3 + wt) * 2048.f * g_eu[bh * Tn + i0 + r0 + 12];
}

// ---------------- launch ----------------
extern "C" void kernel_launch(void* const* d_in, const int* in_sizes, int n_in,
                              void* d_out, int out_size) {
    const float* x      = (const float*)d_in[0];
    const float* t      = (const float*)d_in[1];
    const float* ln1_w  = (const float*)d_in[2];
    const float* ln1_b  = (const float*)d_in[3];
    const float* attn_w = (const float*)d_in[4];
    const float* attn_b = (const float*)d_in[5];
    const float* proj_w = (const float*)d_in[6];
    const float* proj_b = (const float*)d_in[7];
    const float* ln2_w  = (const float*)d_in[8];
    const float* ln2_b  = (const float*)d_in[9];
    const float* fc_w   = (const float*)d_in[10];
    const float* fc_b   = (const float*)d_in[11];
    const float* fc2_w  = (const float*)d_in[12];
    const float* fc2_b  = (const float*)d_in[13];
    float* out = (float*)d_out;

    float *p_xn, *p_qkv, *p_y, *p_h, *p_hn, *p_m, *p_eu, *p_ev, *p_eutot, *p_evtot;
    cudaGetSymbolAddress((void**)&p_xn,  g_xn);
    cudaGetSymbolAddress((void**)&p_qkv, g_qkv);
    cudaGetSymbolAddress((void**)&p_y,   g_y);
    cudaGetSymbolAddress((void**)&p_h,   g_h);
    cudaGetSymbolAddress((void**)&p_hn,  g_hn);
    cudaGetSymbolAddress((void**)&p_m,   g_m);
    cudaGetSymbolAddress((void**)&p_eu,  g_eu);
    cudaGetSymbolAddress((void**)&p_ev,  g_ev);
    cudaGetSymbolAddress((void**)&p_eutot, g_eutot);
    cudaGetSymbolAddress((void**)&p_evtot, g_evtot);

    // attention sub-block
    ln_kernel<<<ROWS, 256>>>(x, t, ln1_w, ln1_b, p_xn);
    gemm128<<<dim3(N3 / 128, ROWS / 128), 256>>>(p_xn, attn_w, attn_b, p_qkv, ROWS, N3, C1, 0);
    score128<<<dim3(Tn / 128, Tn / 128, BHn), 256>>>();
    softmax_u1<<<dim3(Tn, BHn), 256>>>();
    tot_kernel<<<BHn, 256>>>(p_eu, p_eutot);

    // sinkhorn remaining 5 passes: col,row,col,row,col
    sink_col_f<<<dim3(Tn / 512, BHn), 256>>>();
    tot_kernel<<<BHn, 256>>>(p_ev, p_evtot);
    sink_row_f<<<dim3(Tn / 8, BHn), 256>>>();
    tot_kernel<<<BHn, 256>>>(p_eu, p_eutot);
    sink_col_f<<<dim3(Tn / 512, BHn), 256>>>();
    tot_kernel<<<BHn, 256>>>(p_ev, p_evtot);
    sink_row_f<<<dim3(Tn / 8, BHn), 256>>>();
    tot_kernel<<<BHn, 256>>>(p_eu, p_eutot);
    sink_col_f<<<dim3(Tn / 512, BHn), 256>>>();
    wtot_kernel<<<BHn, 256>>>();

    pi_v_kernel<<<dim3(Tn / 16, BHn), 256>>>();
    gemm128<<<dim3(Cn / 128, ROWS / 128), 256>>>(p_y, proj_w, proj_b, p_h, ROWS, Cn, Cn, 0);

    // MLP sub-block
    ln_kernel<<<ROWS, 256>>>(p_h, t, ln2_w, ln2_b, p_hn);
    gemm128<<<dim3(N4 / 128, ROWS / 128), 256>>>(p_hn, fc_w, fc_b, p_m, ROWS, N4, C1, 1);
    gemm128<<<dim3(Cn / 128, ROWS / 128), 256>>>(p_m, fc2_w, fc2_b, out, ROWS, Cn, N4, 0);
}

// round 5
// speedup vs baseline: 2.6723x; 1.1797x over previous
#include <cuda_runtime.h>
#include <cuda_fp16.h>
#include <cuda_bf16.h>
#include <math.h>

#define Tn 2048
#define Cn 384
#define Hn 6
#define HDn 64
#define Bn 2
#define BHn 12
#define ROWS 4096      // B*T
#define C1 385         // C+1
#define N3 1152        // 3C
#define N4 1536        // 4C
#define LOGT 7.62461899f   // ln(2048)

// ---------------- scratch ----------------
__device__ __align__(16) float g_xn[ROWS * C1];
__device__ __align__(16) float g_qkv[ROWS * N3];
__device__ __align__(16) float g_s[(size_t)BHn * Tn * Tn];     // fp32 scores
__device__ __align__(16) __half g_c[(size_t)BHn * Tn * Tn];    // fp16 Em1 = exp(prob)-1
__device__ float g_u[BHn * Tn];
__device__ float g_v[BHn * Tn];
__device__ float g_eu[BHn * Tn];
__device__ float g_ev[BHn * Tn];
__device__ float g_eutot[BHn];
__device__ float g_evtot[BHn];
__device__ float g_wtot[BHn * HDn];
__device__ __align__(16) float g_y[ROWS * Cn];
__device__ __align__(16) float g_h[ROWS * Cn];
__device__ __align__(16) float g_hn[ROWS * C1];
__device__ __align__(16) float g_m[ROWS * N4];

// ---------------- f32x2 helpers ----------------
__device__ __forceinline__ unsigned long long pk_dup(float a) {
    unsigned long long r;
    asm("mov.b64 %0,{%1,%1};" : "=l"(r) : "f"(a));
    return r;
}
__device__ __forceinline__ void fma2(unsigned long long& acc, unsigned long long a, unsigned long long b) {
    asm("fma.rn.f32x2 %0,%1,%2,%0;" : "+l"(acc) : "l"(a), "l"(b));
}
__device__ __forceinline__ float2 upk(unsigned long long x) {
    float2 f;
    asm("mov.b64 {%0,%1},%2;" : "=f"(f.x), "=f"(f.y) : "l"(x));
    return f;
}

// ---------------- mma/ldmatrix helpers ----------------
__device__ __forceinline__ void ldmx4(unsigned addr, unsigned& r0, unsigned& r1, unsigned& r2, unsigned& r3) {
    asm volatile("ldmatrix.sync.aligned.m8n8.x4.shared.b16 {%0,%1,%2,%3},[%4];"
                 : "=r"(r0), "=r"(r1), "=r"(r2), "=r"(r3) : "r"(addr));
}
__device__ __forceinline__ void ldmx4t(unsigned addr, unsigned& r0, unsigned& r1, unsigned& r2, unsigned& r3) {
    asm volatile("ldmatrix.sync.aligned.m8n8.x4.trans.shared.b16 {%0,%1,%2,%3},[%4];"
                 : "=r"(r0), "=r"(r1), "=r"(r2), "=r"(r3) : "r"(addr));
}
__device__ __forceinline__ void mma_bf16(float* c, unsigned a0, unsigned a1, unsigned a2, unsigned a3,
                                         unsigned b0, unsigned b1) {
    asm volatile("mma.sync.aligned.m16n8k16.row.col.f32.bf16.bf16.f32 "
                 "{%0,%1,%2,%3},{%4,%5,%6,%7},{%8,%9},{%0,%1,%2,%3};"
                 : "+f"(c[0]), "+f"(c[1]), "+f"(c[2]), "+f"(c[3])
                 : "r"(a0), "r"(a1), "r"(a2), "r"(a3), "r"(b0), "r"(b1));
}

// ---------------- LayerNorm over (x, t) -> width 385 ----------------
__global__ void ln_kernel(const float* __restrict__ x, const float* __restrict__ t,
                          const float* __restrict__ w, const float* __restrict__ bb,
                          float* __restrict__ out) {
    int row = blockIdx.x;
    int tid = threadIdx.x;
    __shared__ float sx[C1];
    __shared__ float red[256];
    float s1 = 0.f;
    for (int c = tid; c < C1; c += 256) {
        float v = (c < Cn) ? x[(size_t)row * Cn + c] : t[0];
        sx[c] = v;
        s1 += v;
    }
    red[tid] = s1; __syncthreads();
    for (int o = 128; o > 0; o >>= 1) { if (tid < o) red[tid] += red[tid + o]; __syncthreads(); }
    float mean = red[0] * (1.f / C1);
    __syncthreads();
    float s2 = 0.f;
    for (int c = tid; c < C1; c += 256) { float d = sx[c] - mean; s2 += d * d; }
    red[tid] = s2; __syncthreads();
    for (int o = 128; o > 0; o >>= 1) { if (tid < o) red[tid] += red[tid + o]; __syncthreads(); }
    float rs = rsqrtf(red[0] * (1.f / C1) + 1e-5f);
    for (int c = tid; c < C1; c += 256)
        out[(size_t)row * C1 + c] = (sx[c] - mean) * rs * w[c] + bb[c];
}

// ---------------- TC GEMM: 128x128 tile, bf16 split (hi+lo), fp32-accurate ----------------
// A: MxK row-major fp32, B: KxN row-major fp32. M,N multiples of 128.
__global__ void __launch_bounds__(256) gemm_tc(const float* __restrict__ A, const float* __restrict__ B,
                                               const float* __restrict__ bias, float* __restrict__ Cm,
                                               int M, int N, int K, int act) {
    __shared__ __nv_bfloat16 sAh[128][40];
    __shared__ __nv_bfloat16 sAl[128][40];
    __shared__ __nv_bfloat16 sBh[32][136];
    __shared__ __nv_bfloat16 sBl[32][136];
    int tid = threadIdx.x;
    int wid = tid >> 5, lane = tid & 31;
    int wm = wid & 3, wn = wid >> 2;
    int bm = blockIdx.y * 128, bn = blockIdx.x * 128;

    float acc[2][8][4] = {};

    unsigned aH = (unsigned)__cvta_generic_to_shared(&sAh[0][0]);
    unsigned aL = (unsigned)__cvta_generic_to_shared(&sAl[0][0]);
    unsigned bHb = (unsigned)__cvta_generic_to_shared(&sBh[0][0]);
    unsigned bLb = (unsigned)__cvta_generic_to_shared(&sBl[0][0]);

    for (int kt = 0; kt < K; kt += 32) {
        // load A 128x32 (fp32 -> bf16 hi/lo)
        #pragma unroll
        for (int z = 0; z < 16; z++) {
            int e = z * 256 + tid;
            int m = e >> 5, k = e & 31;
            float v = (kt + k < K) ? A[(size_t)(bm + m) * K + kt + k] : 0.f;
            __nv_bfloat16 hi = __float2bfloat16(v);
            sAh[m][k] = hi;
            sAl[m][k] = __float2bfloat16(v - __bfloat162float(hi));
        }
        // load B 32x128
        #pragma unroll
        for (int z = 0; z < 16; z++) {
            int e = z * 256 + tid;
            int k = e >> 7, n = e & 127;
            float v = (kt + k < K) ? B[(size_t)(kt + k) * N + bn + n] : 0.f;
            __nv_bfloat16 hi = __float2bfloat16(v);
            sBh[k][n] = hi;
            sBl[k][n] = __float2bfloat16(v - __bfloat162float(hi));
        }
        __syncthreads();
        #pragma unroll
        for (int kh = 0; kh < 32; kh += 16) {
            unsigned ah[2][4], al[2][4];
            #pragma unroll
            for (int mt = 0; mt < 2; mt++) {
                int m0 = wm * 32 + mt * 16;
                unsigned off = ((unsigned)((m0 + (lane & 15)) * 40 + kh + (lane >> 4) * 8)) * 2;
                ldmx4(aH + off, ah[mt][0], ah[mt][1], ah[mt][2], ah[mt][3]);
                ldmx4(aL + off, al[mt][0], al[mt][1], al[mt][2], al[mt][3]);
            }
            #pragma unroll
            for (int np = 0; np < 4; np++) {
                int n0 = wn * 64 + np * 16;
                unsigned boff = ((unsigned)((kh + (lane & 7) + 8 * ((lane >> 3) & 1)) * 136 + n0 + 8 * (lane >> 4))) * 2;
                unsigned bh0, bh1, bh2, bh3, bl0, bl1, bl2, bl3;
                ldmx4t(bHb + boff, bh0, bh1, bh2, bh3);
                ldmx4t(bLb + boff, bl0, bl1, bl2, bl3);
                #pragma unroll
                for (int mt = 0; mt < 2; mt++) {
                    mma_bf16(acc[mt][2 * np],     ah[mt][0], ah[mt][1], ah[mt][2], ah[mt][3], bh0, bh1);
                    mma_bf16(acc[mt][2 * np],     ah[mt][0], ah[mt][1], ah[mt][2], ah[mt][3], bl0, bl1);
                    mma_bf16(acc[mt][2 * np],     al[mt][0], al[mt][1], al[mt][2], al[mt][3], bh0, bh1);
                    mma_bf16(acc[mt][2 * np + 1], ah[mt][0], ah[mt][1], ah[mt][2], ah[mt][3], bh2, bh3);
                    mma_bf16(acc[mt][2 * np + 1], ah[mt][0], ah[mt][1], ah[mt][2], ah[mt][3], bl2, bl3);
                    mma_bf16(acc[mt][2 * np + 1], al[mt][0], al[mt][1], al[mt][2], al[mt][3], bh2, bh3);
                }
            }
        }
        __syncthreads();
    }
    // epilogue
    #pragma unroll
    for (int mt = 0; mt < 2; mt++) {
        #pragma unroll
        for (int nt = 0; nt < 8; nt++) {
            float* cc = acc[mt][nt];
            int r = bm + wm * 32 + mt * 16 + (lane >> 2);
            int cn = bn + wn * 64 + nt * 8 + (lane & 3) * 2;
            float b0 = bias[cn], b1 = bias[cn + 1];
            float v0 = cc[0] + b0, v1 = cc[1] + b1;
            float v2 = cc[2] + b0, v3 = cc[3] + b1;
            if (act == 1) {
                v0 = 0.5f * v0 * (1.f + erff(v0 * 0.70710678f));
                v1 = 0.5f * v1 * (1.f + erff(v1 * 0.70710678f));
                v2 = 0.5f * v2 * (1.f + erff(v2 * 0.70710678f));
                v3 = 0.5f * v3 * (1.f + erff(v3 * 0.70710678f));
            }
            Cm[(size_t)r * N + cn] = v0;
            Cm[(size_t)r * N + cn + 1] = v1;
            Cm[(size_t)(r + 8) * N + cn] = v2;
            Cm[(size_t)(r + 8) * N + cn + 1] = v3;
        }
    }
}

// ---------------- attention scores (lower tiles only), f32x2 FMA ----------------
__global__ void score128() {
    int jt = blockIdx.x, it = blockIdx.y, bh = blockIdx.z;
    if (jt > it) return;
    int b = bh / Hn, h = bh % Hn;
    const float* Q  = g_qkv + (size_t)b * Tn * N3 + h * HDn;
    const float* Kp = g_qkv + (size_t)b * Tn * N3 + Cn + h * HDn;
    __shared__ float Qs[16][132];
    __shared__ float Ks[16][132];
    int tid = threadIdx.x;
    int tx = tid & 15, ty = tid >> 4;
    unsigned long long acc2[8][4] = {};
    int m = tid >> 1, k0 = (tid & 1) * 8;
    for (int kt = 0; kt < HDn; kt += 16) {
        {
            const float4* Qp = (const float4*)(Q + (size_t)(it * 128 + m) * N3 + kt + k0);
            float4 q0 = Qp[0], q1 = Qp[1];
            Qs[k0 + 0][m] = q0.x; Qs[k0 + 1][m] = q0.y; Qs[k0 + 2][m] = q0.z; Qs[k0 + 3][m] = q0.w;
            Qs[k0 + 4][m] = q1.x; Qs[k0 + 5][m] = q1.y; Qs[k0 + 6][m] = q1.z; Qs[k0 + 7][m] = q1.w;
            const float4* Kq = (const float4*)(Kp + (size_t)(jt * 128 + m) * N3 + kt + k0);
            float4 c0 = Kq[0], c1 = Kq[1];
            Ks[k0 + 0][m] = c0.x; Ks[k0 + 1][m] = c0.y; Ks[k0 + 2][m] = c0.z; Ks[k0 + 3][m] = c0.w;
            Ks[k0 + 4][m] = c1.x; Ks[k0 + 5][m] = c1.y; Ks[k0 + 6][m] = c1.z; Ks[k0 + 7][m] = c1.w;
        }
        __syncthreads();
        #pragma unroll
        for (int kk = 0; kk < 16; kk++) {
            float4 a0 = *(const float4*)&Qs[kk][ty * 4];
            float4 a1 = *(const float4*)&Qs[kk][ty * 4 + 64];
            float a[8] = {a0.x, a0.y, a0.z, a0.w, a1.x, a1.y, a1.z, a1.w};
            const unsigned long long* bp0 = (const unsigned long long*)&Ks[kk][tx * 4];
            const unsigned long long* bp1 = (const unsigned long long*)&Ks[kk][tx * 4 + 64];
            unsigned long long bq[4] = {bp0[0], bp0[1], bp1[0], bp1[1]};
            #pragma unroll
            for (int i = 0; i < 8; i++) {
                unsigned long long ap = pk_dup(a[i]);
                fma2(acc2[i][0], ap, bq[0]);
                fma2(acc2[i][1], ap, bq[1]);
                fma2(acc2[i][2], ap, bq[2]);
                fma2(acc2[i][3], ap, bq[3]);
            }
        }
        __syncthreads();
    }
    float* srow = g_s + (size_t)bh * Tn * Tn;
    #pragma unroll
    for (int i = 0; i < 8; i++) {
        int gi = it * 128 + ty * 4 + ((i < 4) ? i : 60 + i);
        #pragma unroll
        for (int jp = 0; jp < 4; jp++) {
            float2 f = upk(acc2[i][jp]);
            int jj0 = 2 * jp;
            int gj = jt * 128 + tx * 4 + ((jj0 < 4) ? jj0 : 60 + jj0);
            srow[(size_t)gi * Tn + gj] = f.x * 0.125f;
            srow[(size_t)gi * Tn + gj + 1] = f.y * 0.125f;
        }
    }
}

// ---------------- softmax per row -> Em1 fp16 + u1, eu (no max pass; args tiny) ----------------
__global__ void softmax_u1() {
    int i = blockIdx.x, bh = blockIdx.y;
    int tid = threadIdx.x;
    const float* srow = g_s + ((size_t)bh * Tn + i) * Tn;
    __half2* crow2 = (__half2*)(g_c + ((size_t)bh * Tn + i) * Tn);
    __shared__ float sp[Tn];
    __shared__ float red[256];
    float sum = 0.f;
    for (int j = tid; j <= i; j += 256) {
        float e = __expf(fminf(srow[j], 60.f));
        sp[j] = e;
        sum += e;
    }
    red[tid] = sum; __syncthreads();
    for (int o = 128; o > 0; o >>= 1) { if (tid < o) red[tid] += red[tid + o]; __syncthreads(); }
    float inv = 1.f / red[0];
    __syncthreads();
    float se = 0.f;
    int lim2 = ((i + 8) >> 3) * 4;
    for (int jp = tid; jp < lim2; jp += 256) {
        int j0 = jp * 2, j1 = j0 + 1;
        float e0 = (j0 <= i) ? (__expf(sp[j0] * inv) - 1.f) : 0.f;
        float e1 = (j1 <= i) ? (__expf(sp[j1] * inv) - 1.f) : 0.f;
        crow2[jp] = __floats2half2_rn(e0, e1);
        se += e0 + e1;
    }
    red[tid] = se; __syncthreads();
    for (int o = 128; o > 0; o >>= 1) { if (tid < o) red[tid] += red[tid + o]; __syncthreads(); }
    if (tid == 0) {
        float u = -LOGT - __logf(red[0] + (float)Tn);
        g_u[bh * Tn + i] = u;
        g_eu[bh * Tn + i] = __expf(u);
    }
}

// ---------------- per-bh totals ----------------
__global__ void tot_kernel(const float* __restrict__ vec, float* __restrict__ tot) {
    int bh = blockIdx.x, tid = threadIdx.x;
    __shared__ float red[256];
    float s = 0.f;
    for (int i = tid; i < Tn; i += 256) s += vec[bh * Tn + i];
    red[tid] = s; __syncthreads();
    for (int o = 128; o > 0; o >>= 1) { if (tid < o) red[tid] += red[tid + o]; __syncthreads(); }
    if (tid == 0) tot[bh] = red[0];
}

// ---------------- Sinkhorn row pass ----------------
__global__ void sink_row_f() {
    int r0 = blockIdx.x * 8, bh = blockIdx.y;
    int tid = threadIdx.x;
    __shared__ float sev[Tn];
    __shared__ float red[256];
    int jmax = r0 + 8;
    for (int j = tid; j < jmax; j += 256) sev[j] = g_ev[bh * Tn + j];
    float evtot = g_evtot[bh];
    __syncthreads();
    for (int r = 0; r < 8; r++) {
        int i = r0 + r;
        const uint4* cv = (const uint4*)(g_c + ((size_t)bh * Tn + i) * Tn);
        int nv = (i + 8) >> 3;
        float s = 0.f;
        for (int vi = tid; vi < nv; vi += 256) {
            uint4 pk = cv[vi];
            const __half2* hp = (const __half2*)&pk;
            int jb = vi * 8;
            #pragma unroll
            for (int z = 0; z < 4; z++) {
                float2 f = __half22float2(hp[z]);
                s += f.x * sev[jb + 2 * z] + f.y * sev[jb + 2 * z + 1];
            }
        }
        red[tid] = s; __syncthreads();
        for (int o = 128; o > 0; o >>= 1) { if (tid < o) red[tid] += red[tid + o]; __syncthreads(); }
        if (tid == 0) {
            float u = -LOGT - __logf(red[0] + evtot);
            g_u[bh * Tn + i] = u;
            g_eu[bh * Tn + i] = __expf(u);
        }
        __syncthreads();
    }
}

// ---------------- Sinkhorn col pass ----------------
__global__ void sink_col_f() {
    int bh = blockIdx.y;
    int tid = threadIdx.x;
    int j0 = (blockIdx.x * 256 + tid) * 2;
    int ibase = blockIdx.x * 512;
    __shared__ float seu[Tn];
    for (int i = tid; i < Tn - ibase; i += 256) seu[i] = g_eu[bh * Tn + ibase + i];
    float eutot = g_eutot[bh];
    __syncthreads();
    const __half* cb = g_c + (size_t)bh * Tn * Tn + j0;
    float s0 = 0.f, s1 = 0.f;
    #pragma unroll 4
    for (int i = j0; i < Tn; i++) {
        __half2 hh = *(const __half2*)(cb + (size_t)i * Tn);
        float2 f = __half22float2(hh);
        float ui = seu[i - ibase];
        s0 += f.x * ui;
        s1 += f.y * ui;
    }
    float v0 = -LOGT - __logf(s0 + eutot);
    float v1 = -LOGT - __logf(s1 + eutot);
    g_v[bh * Tn + j0]     = v0;
    g_v[bh * Tn + j0 + 1] = v1;
    g_ev[bh * Tn + j0]     = __expf(v0);
    g_ev[bh * Tn + j0 + 1] = __expf(v1);
}

// ---------------- Wtot_d = sum_j ev_j * V_jd ----------------
__global__ void wtot_kernel() {
    int bh = blockIdx.x;
    int b = bh / Hn, h = bh % Hn;
    int tid = threadIdx.x;
    int d = tid & 63, rr = tid >> 6;
    const float* Vbase = g_qkv + (size_t)b * Tn * N3 + 2 * Cn + h * HDn;
    float acc = 0.f;
    for (int i = rr; i < Tn; i += 4)
        acc += g_ev[bh * Tn + i] * Vbase[(size_t)i * N3 + d];
    __shared__ float red[256];
    red[tid] = acc; __syncthreads();
    if (tid < 128) red[tid] += red[tid + 128];
    __syncthreads();
    if (tid < 64) g_wtot[bh * HDn + tid] = red[tid] + red[tid + 64];
}

// ---------------- y_i = T*eu_i*(sum_{j<=i} Em1*ev*V + Wtot) ; 32 rows/block, f32x2 ----------------
__global__ void pi_v_kernel() {
    int bh = blockIdx.y;
    int b = bh / Hn, h = bh % Hn;
    int i0 = blockIdx.x * 32;
    int tid = threadIdx.x;
    __shared__ float sev[Tn];
    __shared__ float spi_t[64][34];   // [jj][row-in-tile]
    __shared__ float sV[64][64];
    int jend = ((i0 + 32 + 63) >> 6) << 6;
    if (jend > Tn) jend = Tn;
    for (int j = tid; j < jend; j += 256) sev[j] = g_ev[bh * Tn + j];
    __syncthreads();
    int d = tid & 63, r0 = tid >> 6;   // r0 in 0..3
    unsigned long long acc[4] = {};    // row pairs (2*(4p+r0), +1)
    const float4* Vb4 = (const float4*)(g_qkv + (size_t)b * Tn * N3 + 2 * Cn + h * HDn);
    const __half* Cbase = g_c + ((size_t)bh * Tn + i0) * Tn;
    for (int jc = 0; jc < jend; jc += 64) {
        #pragma unroll
        for (int z = 0; z < 4; z++) {
            int fi = z * 256 + tid;
            int jj = fi >> 4, dp = fi & 15;
            *(float4*)&sV[jj][dp * 4] = Vb4[(size_t)(jc + jj) * (N3 / 4) + dp];
        }
        #pragma unroll
        for (int z = 0; z < 8; z++) {
            int idx = z * 256 + tid;
            int r = idx >> 6, jj = idx & 63;
            int j = jc + jj;
            float e = 0.f;
            if (j <= i0 + r) e = __half2float(Cbase[(size_t)r * Tn + j]);
            spi_t[jj][r] = e * sev[j];
        }
        __syncthreads();
        #pragma unroll
        for (int jj = 0; jj < 64; jj++) {
            unsigned long long bv = pk_dup(sV[jj][d]);
            #pragma unroll
            for (int p = 0; p < 4; p++)
                fma2(acc[p], *(const unsigned long long*)&spi_t[jj][2 * (4 * p + r0)], bv);
        }
        __syncthreads();
    }
    float wt = g_wtot[bh * HDn + d];
    #pragma unroll
    for (int p = 0; p < 4; p++) {
        float2 f = upk(acc[p]);
        int rA = 2 * (4 * p + r0), rB = rA + 1;
        size_t base = ((size_t)(b * Tn) + i0) * Cn + h * HDn + d;
        g_y[base + (size_t)rA * Cn] = (f.x + wt) * 2048.f * g_eu[bh * Tn + i0 + rA];
        g_y[base + (size_t)rB * Cn] = (f.y + wt) * 2048.f * g_eu[bh * Tn + i0 + rB];
    }
}

// ---------------- launch ----------------
extern "C" void kernel_launch(void* const* d_in, const int* in_sizes, int n_in,
                              void* d_out, int out_size) {
    const float* x      = (const float*)d_in[0];
    const float* t      = (const float*)d_in[1];
    const float* ln1_w  = (const float*)d_in[2];
    const float* ln1_b  = (const float*)d_in[3];
    const float* attn_w = (const float*)d_in[4];
    const float* attn_b = (const float*)d_in[5];
    const float* proj_w = (const float*)d_in[6];
    const float* proj_b = (const float*)d_in[7];
    const float* ln2_w  = (const float*)d_in[8];
    const float* ln2_b  = (const float*)d_in[9];
    const float* fc_w   = (const float*)d_in[10];
    const float* fc_b   = (const float*)d_in[11];
    const float* fc2_w  = (const float*)d_in[12];
    const float* fc2_b  = (const float*)d_in[13];
    float* out = (float*)d_out;

    float *p_xn, *p_qkv, *p_y, *p_h, *p_hn, *p_m, *p_eu, *p_ev, *p_eutot, *p_evtot;
    cudaGetSymbolAddress((void**)&p_xn,  g_xn);
    cudaGetSymbolAddress((void**)&p_qkv, g_qkv);
    cudaGetSymbolAddress((void**)&p_y,   g_y);
    cudaGetSymbolAddress((void**)&p_h,   g_h);
    cudaGetSymbolAddress((void**)&p_hn,  g_hn);
    cudaGetSymbolAddress((void**)&p_m,   g_m);
    cudaGetSymbolAddress((void**)&p_eu,  g_eu);
    cudaGetSymbolAddress((void**)&p_ev,  g_ev);
    cudaGetSymbolAddress((void**)&p_eutot, g_eutot);
    cudaGetSymbolAddress((void**)&p_evtot, g_evtot);

    // attention sub-block
    ln_kernel<<<ROWS, 256>>>(x, t, ln1_w, ln1_b, p_xn);
    gemm_tc<<<dim3(N3 / 128, ROWS / 128), 256>>>(p_xn, attn_w, attn_b, p_qkv, ROWS, N3, C1, 0);
    score128<<<dim3(Tn / 128, Tn / 128, BHn), 256>>>();
    softmax_u1<<<dim3(Tn, BHn), 256>>>();
    tot_kernel<<<BHn, 256>>>(p_eu, p_eutot);

    // sinkhorn remaining 5 passes: col,row,col,row,col
    sink_col_f<<<dim3(Tn / 512, BHn), 256>>>();
    tot_kernel<<<BHn, 256>>>(p_ev, p_evtot);
    sink_row_f<<<dim3(Tn / 8, BHn), 256>>>();
    tot_kernel<<<BHn, 256>>>(p_eu, p_eutot);
    sink_col_f<<<dim3(Tn / 512, BHn), 256>>>();
    tot_kernel<<<BHn, 256>>>(p_ev, p_evtot);
    sink_row_f<<<dim3(Tn / 8, BHn), 256>>>();
    tot_kernel<<<BHn, 256>>>(p_eu, p_eutot);
    sink_col_f<<<dim3(Tn / 512, BHn), 256>>>();
    wtot_kernel<<<BHn, 256>>>();

    pi_v_kernel<<<dim3(Tn / 32, BHn), 256>>>();
    gemm_tc<<<dim3(Cn / 128, ROWS / 128), 256>>>(p_y, proj_w, proj_b, p_h, ROWS, Cn, Cn, 0);

    // MLP sub-block
    ln_kernel<<<ROWS, 256>>>(p_h, t, ln2_w, ln2_b, p_hn);
    gemm_tc<<<dim3(N4 / 128, ROWS / 128), 256>>>(p_hn, fc_w, fc_b, p_m, ROWS, N4, C1, 1);
    gemm_tc<<<dim3(Cn / 128, ROWS / 128), 256>>>(p_m, fc2_w, fc2_b, out, ROWS, Cn, N4, 0);
}

// round 7
// speedup vs baseline: 3.2342x; 1.2103x over previous
#include <cuda_runtime.h>
#include <cuda_fp16.h>
#include <cuda_bf16.h>
#include <math.h>

#define Tn 2048
#define Cn 384
#define Hn 6
#define HDn 64
#define Bn 2
#define BHn 12
#define ROWS 4096      // B*T
#define C1 385         // C+1
#define N3 1152        // 3C
#define N4 1536        // 4C
#define LOGT 7.62461899f   // ln(2048)
#define WSCALE 512.f
#define WINV   (1.f / 512.f)

// ---------------- scratch ----------------
__device__ __align__(16) float g_xn[ROWS * C1];
__device__ __align__(16) float g_qkv[ROWS * N3];
__device__ __align__(16) float g_s[(size_t)BHn * Tn * Tn];     // fp32 e=exp(s) (lower tiles)
__device__ __align__(16) __half g_c[(size_t)BHn * Tn * Tn];    // fp16 Em1, zero-padded to 128
__device__ __align__(16) __nv_bfloat16 g_qh[ROWS * Cn];
__device__ __align__(16) __nv_bfloat16 g_ql[ROWS * Cn];
__device__ __align__(16) __nv_bfloat16 g_kh[ROWS * Cn];
__device__ __align__(16) __nv_bfloat16 g_kl[ROWS * Cn];
__device__ __align__(16) __half g_wh[BHn * Tn * HDn];
__device__ __align__(16) __half g_wl[BHn * Tn * HDn];
__device__ float g_u[BHn * Tn];
__device__ float g_eu[BHn * Tn];
__device__ float g_ev[BHn * Tn];
__device__ float g_eutot[BHn];
__device__ float g_evtot[BHn];
__device__ float g_wtot[BHn * HDn];
__device__ __align__(16) float g_y[ROWS * Cn];
__device__ __align__(16) float g_h[ROWS * Cn];
__device__ __align__(16) float g_hn[ROWS * C1];
__device__ __align__(16) float g_m[ROWS * N4];

// ---------------- mma/ldmatrix helpers ----------------
__device__ __forceinline__ void ldmx4(unsigned addr, unsigned& r0, unsigned& r1, unsigned& r2, unsigned& r3) {
    asm volatile("ldmatrix.sync.aligned.m8n8.x4.shared.b16 {%0,%1,%2,%3},[%4];"
                 : "=r"(r0), "=r"(r1), "=r"(r2), "=r"(r3) : "r"(addr));
}
__device__ __forceinline__ void ldmx4t(unsigned addr, unsigned& r0, unsigned& r1, unsigned& r2, unsigned& r3) {
    asm volatile("ldmatrix.sync.aligned.m8n8.x4.trans.shared.b16 {%0,%1,%2,%3},[%4];"
                 : "=r"(r0), "=r"(r1), "=r"(r2), "=r"(r3) : "r"(addr));
}
__device__ __forceinline__ void mma_bf16(float* c, unsigned a0, unsigned a1, unsigned a2, unsigned a3,
                                         unsigned b0, unsigned b1) {
    asm volatile("mma.sync.aligned.m16n8k16.row.col.f32.bf16.bf16.f32 "
                 "{%0,%1,%2,%3},{%4,%5,%6,%7},{%8,%9},{%0,%1,%2,%3};"
                 : "+f"(c[0]), "+f"(c[1]), "+f"(c[2]), "+f"(c[3])
                 : "r"(a0), "r"(a1), "r"(a2), "r"(a3), "r"(b0), "r"(b1));
}
__device__ __forceinline__ void mma_f16(float* c, unsigned a0, unsigned a1, unsigned a2, unsigned a3,
                                        unsigned b0, unsigned b1) {
    asm volatile("mma.sync.aligned.m16n8k16.row.col.f32.f16.f16.f32 "
                 "{%0,%1,%2,%3},{%4,%5,%6,%7},{%8,%9},{%0,%1,%2,%3};"
                 : "+f"(c[0]), "+f"(c[1]), "+f"(c[2]), "+f"(c[3])
                 : "r"(a0), "r"(a1), "r"(a2), "r"(a3), "r"(b0), "r"(b1));
}

// expm1 on [0,1]: degree-8 Taylor (abs err ~3e-6, << fp16 precision of Em1)
__device__ __forceinline__ float em1p(float x) {
    float t = fmaf(x, 0.125f, 1.f);
    t = fmaf(x * 0.14285714f, t, 1.f);
    t = fmaf(x * 0.16666667f, t, 1.f);
    t = fmaf(x * 0.2f,        t, 1.f);
    t = fmaf(x * 0.25f,       t, 1.f);
    t = fmaf(x * 0.33333333f, t, 1.f);
    t = fmaf(x * 0.5f,        t, 1.f);
    return x * t;
}

// ---------------- LayerNorm over (x, t) -> width 385 ----------------
__global__ void ln_kernel(const float* __restrict__ x, const float* __restrict__ t,
                          const float* __restrict__ w, const float* __restrict__ bb,
                          float* __restrict__ out) {
    int row = blockIdx.x;
    int tid = threadIdx.x;
    __shared__ float sx[C1];
    __shared__ float red[256];
    float s1 = 0.f;
    for (int c = tid; c < C1; c += 256) {
        float v = (c < Cn) ? x[(size_t)row * Cn + c] : t[0];
        sx[c] = v;
        s1 += v;
    }
    red[tid] = s1; __syncthreads();
    for (int o = 128; o > 0; o >>= 1) { if (tid < o) red[tid] += red[tid + o]; __syncthreads(); }
    float mean = red[0] * (1.f / C1);
    __syncthreads();
    float s2 = 0.f;
    for (int c = tid; c < C1; c += 256) { float d = sx[c] - mean; s2 += d * d; }
    red[tid] = s2; __syncthreads();
    for (int o = 128; o > 0; o >>= 1) { if (tid < o) red[tid] += red[tid + o]; __syncthreads(); }
    float rs = rsqrtf(red[0] * (1.f / C1) + 1e-5f);
    for (int c = tid; c < C1; c += 256)
        out[(size_t)row * C1 + c] = (sx[c] - mean) * rs * w[c] + bb[c];
}

// ---------------- TC GEMM: 128x128 tile, bf16 split (hi+lo) ----------------
__global__ void __launch_bounds__(256) gemm_tc(const float* __restrict__ A, const float* __restrict__ B,
                                               const float* __restrict__ bias, float* __restrict__ Cm,
                                               int M, int N, int K, int act) {
    __shared__ __nv_bfloat16 sAh[128][40];
    __shared__ __nv_bfloat16 sAl[128][40];
    __shared__ __nv_bfloat16 sBh[32][136];
    __shared__ __nv_bfloat16 sBl[32][136];
    int tid = threadIdx.x;
    int wid = tid >> 5, lane = tid & 31;
    int wm = wid & 3, wn = wid >> 2;
    int bm = blockIdx.y * 128, bn = blockIdx.x * 128;

    float acc[2][8][4] = {};

    unsigned aH = (unsigned)__cvta_generic_to_shared(&sAh[0][0]);
    unsigned aL = (unsigned)__cvta_generic_to_shared(&sAl[0][0]);
    unsigned bHb = (unsigned)__cvta_generic_to_shared(&sBh[0][0]);
    unsigned bLb = (unsigned)__cvta_generic_to_shared(&sBl[0][0]);

    for (int kt = 0; kt < K; kt += 32) {
        #pragma unroll
        for (int z = 0; z < 16; z++) {
            int e = z * 256 + tid;
            int m = e >> 5, k = e & 31;
            float v = (kt + k < K) ? A[(size_t)(bm + m) * K + kt + k] : 0.f;
            __nv_bfloat16 hi = __float2bfloat16(v);
            sAh[m][k] = hi;
            sAl[m][k] = __float2bfloat16(v - __bfloat162float(hi));
        }
        #pragma unroll
        for (int z = 0; z < 16; z++) {
            int e = z * 256 + tid;
            int k = e >> 7, n = e & 127;
            float v = (kt + k < K) ? B[(size_t)(kt + k) * N + bn + n] : 0.f;
            __nv_bfloat16 hi = __float2bfloat16(v);
            sBh[k][n] = hi;
            sBl[k][n] = __float2bfloat16(v - __bfloat162float(hi));
        }
        __syncthreads();
        #pragma unroll
        for (int kh = 0; kh < 32; kh += 16) {
            unsigned ah[2][4], al[2][4];
            #pragma unroll
            for (int mt = 0; mt < 2; mt++) {
                int m0 = wm * 32 + mt * 16;
                unsigned off = ((unsigned)((m0 + (lane & 15)) * 40 + kh + (lane >> 4) * 8)) * 2;
                ldmx4(aH + off, ah[mt][0], ah[mt][1], ah[mt][2], ah[mt][3]);
                ldmx4(aL + off, al[mt][0], al[mt][1], al[mt][2], al[mt][3]);
            }
            #pragma unroll
            for (int np = 0; np < 4; np++) {
                int n0 = wn * 64 + np * 16;
                unsigned boff = ((unsigned)((kh + (lane & 7) + 8 * ((lane >> 3) & 1)) * 136 + n0 + 8 * (lane >> 4))) * 2;
                unsigned bh0, bh1, bh2, bh3, bl0, bl1, bl2, bl3;
                ldmx4t(bHb + boff, bh0, bh1, bh2, bh3);
                ldmx4t(bLb + boff, bl0, bl1, bl2, bl3);
                #pragma unroll
                for (int mt = 0; mt < 2; mt++) {
                    mma_bf16(acc[mt][2 * np],     ah[mt][0], ah[mt][1], ah[mt][2], ah[mt][3], bh0, bh1);
                    mma_bf16(acc[mt][2 * np],     ah[mt][0], ah[mt][1], ah[mt][2], ah[mt][3], bl0, bl1);
                    mma_bf16(acc[mt][2 * np],     al[mt][0], al[mt][1], al[mt][2], al[mt][3], bh0, bh1);
                    mma_bf16(acc[mt][2 * np + 1], ah[mt][0], ah[mt][1], ah[mt][2], ah[mt][3], bh2, bh3);
                    mma_bf16(acc[mt][2 * np + 1], ah[mt][0], ah[mt][1], ah[mt][2], ah[mt][3], bl2, bl3);
                    mma_bf16(acc[mt][2 * np + 1], al[mt][0], al[mt][1], al[mt][2], al[mt][3], bh2, bh3);
                }
            }
        }
        __syncthreads();
    }
    #pragma unroll
    for (int mt = 0; mt < 2; mt++) {
        #pragma unroll
        for (int nt = 0; nt < 8; nt++) {
            float* cc = acc[mt][nt];
            int r = bm + wm * 32 + mt * 16 + (lane >> 2);
            int cn = bn + wn * 64 + nt * 8 + (lane & 3) * 2;
            float b0 = bias[cn], b1 = bias[cn + 1];
            float v0 = cc[0] + b0, v1 = cc[1] + b1;
            float v2 = cc[2] + b0, v3 = cc[3] + b1;
            if (act == 1) {
                v0 = 0.5f * v0 * (1.f + erff(v0 * 0.70710678f));
                v1 = 0.5f * v1 * (1.f + erff(v1 * 0.70710678f));
                v2 = 0.5f * v2 * (1.f + erff(v2 * 0.70710678f));
                v3 = 0.5f * v3 * (1.f + erff(v3 * 0.70710678f));
            }
            Cm[(size_t)r * N + cn] = v0;
            Cm[(size_t)r * N + cn + 1] = v1;
            Cm[(size_t)(r + 8) * N + cn] = v2;
            Cm[(size_t)(r + 8) * N + cn + 1] = v3;
        }
    }
}

// ---------------- convert q,k -> bf16 hi/lo ----------------
__global__ void qk_conv() {
    int idx = blockIdx.x * 256 + threadIdx.x;
    if (idx >= ROWS * Cn) return;
    int row = idx / Cn, c = idx % Cn;
    float q = g_qkv[(size_t)row * N3 + c];
    float k = g_qkv[(size_t)row * N3 + Cn + c];
    __nv_bfloat16 qh = __float2bfloat16(q);
    __nv_bfloat16 kh = __float2bfloat16(k);
    g_qh[idx] = qh;
    g_ql[idx] = __float2bfloat16(q - __bfloat162float(qh));
    g_kh[idx] = kh;
    g_kl[idx] = __float2bfloat16(k - __bfloat162float(kh));
}

// ---------------- TC scores + fused exp: e = exp(q.k/8) -> g_s (lower tiles) ----------------
__global__ void __launch_bounds__(256) score_tc() {
    int jt = blockIdx.x, it = blockIdx.y, bh = blockIdx.z;
    if (jt > it) return;
    int b = bh / Hn, h = bh % Hn;
    __shared__ __nv_bfloat16 sQh[128][40], sQl[128][40], sKh[128][40], sKl[128][40];
    int tid = threadIdx.x, wid = tid >> 5, lane = tid & 31;
    int wm = wid & 3, wn = wid >> 2;
    float acc[2][8][4] = {};
    unsigned aQh = (unsigned)__cvta_generic_to_shared(&sQh[0][0]);
    unsigned aQl = (unsigned)__cvta_generic_to_shared(&sQl[0][0]);
    unsigned aKh = (unsigned)__cvta_generic_to_shared(&sKh[0][0]);
    unsigned aKl = (unsigned)__cvta_generic_to_shared(&sKl[0][0]);
    size_t qbase = ((size_t)(b * Tn + it * 128)) * Cn + h * HDn;
    size_t kbase = ((size_t)(b * Tn + jt * 128)) * Cn + h * HDn;

    for (int ks = 0; ks < 2; ks++) {
        if (ks) __syncthreads();
        #pragma unroll
        for (int z = 0; z < 2; z++) {
            int idx = z * 256 + tid;
            int r = idx >> 2, c8 = (idx & 3) * 8;
            *(uint4*)&sQh[r][c8] = *(const uint4*)(g_qh + qbase + (size_t)r * Cn + ks * 32 + c8);
            *(uint4*)&sQl[r][c8] = *(const uint4*)(g_ql + qbase + (size_t)r * Cn + ks * 32 + c8);
            *(uint4*)&sKh[r][c8] = *(const uint4*)(g_kh + kbase + (size_t)r * Cn + ks * 32 + c8);
            *(uint4*)&sKl[r][c8] = *(const uint4*)(g_kl + kbase + (size_t)r * Cn + ks * 32 + c8);
        }
        __syncthreads();
        #pragma unroll
        for (int kh = 0; kh < 32; kh += 16) {
            unsigned qh_[2][4], ql_[2][4];
            #pragma unroll
            for (int mt = 0; mt < 2; mt++) {
                unsigned off = ((unsigned)((wm * 32 + mt * 16 + (lane & 15)) * 40 + kh + 8 * (lane >> 4))) * 2;
                ldmx4(aQh + off, qh_[mt][0], qh_[mt][1], qh_[mt][2], qh_[mt][3]);
                ldmx4(aQl + off, ql_[mt][0], ql_[mt][1], ql_[mt][2], ql_[mt][3]);
            }
            #pragma unroll
            for (int nq = 0; nq < 4; nq++) {
                int n0 = wn * 64 + nq * 16;
                unsigned boff = ((unsigned)((n0 + (lane & 15)) * 40 + kh + 8 * (lane >> 4))) * 2;
                unsigned kh0, kh1, kh2, kh3, kl0, kl1, kl2, kl3;
                ldmx4(aKh + boff, kh0, kh1, kh2, kh3);
                ldmx4(aKl + boff, kl0, kl1, kl2, kl3);
                #pragma unroll
                for (int mt = 0; mt < 2; mt++) {
                    mma_bf16(acc[mt][2 * nq],     qh_[mt][0], qh_[mt][1], qh_[mt][2], qh_[mt][3], kh0, kh2);
                    mma_bf16(acc[mt][2 * nq],     qh_[mt][0], qh_[mt][1], qh_[mt][2], qh_[mt][3], kl0, kl2);
                    mma_bf16(acc[mt][2 * nq],     ql_[mt][0], ql_[mt][1], ql_[mt][2], ql_[mt][3], kh0, kh2);
                    mma_bf16(acc[mt][2 * nq + 1], qh_[mt][0], qh_[mt][1], qh_[mt][2], qh_[mt][3], kh1, kh3);
                    mma_bf16(acc[mt][2 * nq + 1], qh_[mt][0], qh_[mt][1], qh_[mt][2], qh_[mt][3], kl1, kl3);
                    mma_bf16(acc[mt][2 * nq + 1], ql_[mt][0], ql_[mt][1], ql_[mt][2], ql_[mt][3], kh1, kh3);
                }
            }
        }
    }
    float* srow = g_s + (size_t)bh * Tn * Tn;
    #pragma unroll
    for (int mt = 0; mt < 2; mt++) {
        #pragma unroll
        for (int f = 0; f < 8; f++) {
            float* cc = acc[mt][f];
            int gi = it * 128 + wm * 32 + mt * 16 + (lane >> 2);
            int gj = jt * 128 + wn * 64 + (f >> 1) * 16 + (f & 1) * 8 + 2 * (lane & 3);
            float2 e01, e23;
            e01.x = __expf(fminf(cc[0] * 0.125f, 80.f));
            e01.y = __expf(fminf(cc[1] * 0.125f, 80.f));
            e23.x = __expf(fminf(cc[2] * 0.125f, 80.f));
            e23.y = __expf(fminf(cc[3] * 0.125f, 80.f));
            *(float2*)&srow[(size_t)gi * Tn + gj] = e01;
            *(float2*)&srow[(size_t)(gi + 8) * Tn + gj] = e23;
        }
    }
}

// ---------------- per row: normalize, Em1 = expm1(p) (poly), pad to 128, u1, eu ----------------
__global__ void em1_row() {
    int i = blockIdx.x, bh = blockIdx.y;
    int tid = threadIdx.x;
    const float* erow = g_s + ((size_t)bh * Tn + i) * Tn;
    __half2* crow2 = (__half2*)(g_c + ((size_t)bh * Tn + i) * Tn);
    __shared__ float sp[Tn];
    __shared__ float red[256];
    float sum = 0.f;
    for (int j = tid; j <= i; j += 256) { float e = erow[j]; sp[j] = e; sum += e; }
    red[tid] = sum; __syncthreads();
    for (int o = 128; o > 0; o >>= 1) { if (tid < o) red[tid] += red[tid + o]; __syncthreads(); }
    float inv = 1.f / red[0];
    __syncthreads();
    float se = 0.f;
    int lim2 = (((i >> 7) + 1) << 7) >> 1;   // half2 count to 128 boundary
    for (int jp = tid; jp < lim2; jp += 256) {
        int j0 = jp * 2, j1 = j0 + 1;
        float e0 = (j0 <= i) ? em1p(sp[j0] * inv) : 0.f;
        float e1 = (j1 <= i) ? em1p(sp[j1] * inv) : 0.f;
        crow2[jp] = __floats2half2_rn(e0, e1);
        se += e0 + e1;
    }
    red[tid] = se; __syncthreads();
    for (int o = 128; o > 0; o >>= 1) { if (tid < o) red[tid] += red[tid + o]; __syncthreads(); }
    if (tid == 0) {
        float u = -LOGT - __logf(red[0] + (float)Tn);
        g_u[bh * Tn + i] = u;
        g_eu[bh * Tn + i] = __expf(u);
    }
}

// ---------------- per-bh totals ----------------
__global__ void tot_kernel(const float* __restrict__ vec, float* __restrict__ tot) {
    int bh = blockIdx.x, tid = threadIdx.x;
    __shared__ float red[256];
    float s = 0.f;
    for (int i = tid; i < Tn; i += 256) s += vec[bh * Tn + i];
    red[tid] = s; __syncthreads();
    for (int o = 128; o > 0; o >>= 1) { if (tid < o) red[tid] += red[tid + o]; __syncthreads(); }
    if (tid == 0) tot[bh] = red[0];
}

// ---------------- Sinkhorn row pass ----------------
__global__ void sink_row_f() {
    int r0 = blockIdx.x * 8, bh = blockIdx.y;
    int tid = threadIdx.x;
    __shared__ float sev[Tn];
    __shared__ float red[256];
    int jmax = r0 + 8;
    for (int j = tid; j < jmax; j += 256) sev[j] = g_ev[bh * Tn + j];
    float evtot = g_evtot[bh];
    __syncthreads();
    for (int r = 0; r < 8; r++) {
        int i = r0 + r;
        const uint4* cv = (const uint4*)(g_c + ((size_t)bh * Tn + i) * Tn);
        int nv = (i + 8) >> 3;
        float s = 0.f;
        for (int vi = tid; vi < nv; vi += 256) {
            uint4 pk = cv[vi];
            const __half2* hp = (const __half2*)&pk;
            int jb = vi * 8;
            #pragma unroll
            for (int z = 0; z < 4; z++) {
                float2 f = __half22float2(hp[z]);
                s += f.x * sev[jb + 2 * z] + f.y * sev[jb + 2 * z + 1];
            }
        }
        red[tid] = s; __syncthreads();
        for (int o = 128; o > 0; o >>= 1) { if (tid < o) red[tid] += red[tid + o]; __syncthreads(); }
        if (tid == 0) {
            float u = -LOGT - __logf(red[0] + evtot);
            g_u[bh * Tn + i] = u;
            g_eu[bh * Tn + i] = __expf(u);
        }
        __syncthreads();
    }
}

// ---------------- Sinkhorn col pass ----------------
__global__ void sink_col_f() {
    int bh = blockIdx.y;
    int tid = threadIdx.x;
    int j0 = (blockIdx.x * 256 + tid) * 2;
    int ibase = blockIdx.x * 512;
    __shared__ float seu[Tn];
    for (int i = tid; i < Tn - ibase; i += 256) seu[i] = g_eu[bh * Tn + ibase + i];
    float eutot = g_eutot[bh];
    __syncthreads();
    const __half* cb = g_c + (size_t)bh * Tn * Tn + j0;
    float s0 = 0.f, s1 = 0.f;
    #pragma unroll 4
    for (int i = j0; i < Tn; i++) {
        __half2 hh = *(const __half2*)(cb + (size_t)i * Tn);
        float2 f = __half22float2(hh);
        float ui = seu[i - ibase];
        s0 += f.x * ui;
        s1 += f.y * ui;
    }
    float v0 = -LOGT - __logf(s0 + eutot);
    float v1 = -LOGT - __logf(s1 + eutot);
    g_ev[bh * Tn + j0]     = __expf(v0);
    g_ev[bh * Tn + j0 + 1] = __expf(v1);
}

// ---------------- zero wtot ----------------
__global__ void zero_wtot() {
    int i = blockIdx.x * 256 + threadIdx.x;
    if (i < BHn * HDn) g_wtot[i] = 0.f;
}

// ---------------- W = ev*V*512 -> fp16 hi/lo; Wtot (fp32, unscaled) ----------------
__global__ void w_kernel() {
    int jt = blockIdx.x, bh = blockIdx.y;
    int b = bh / Hn, h = bh % Hn;
    int tid = threadIdx.x;
    int d = tid & 63, r0 = tid >> 6;
    float part = 0.f;
    for (int r = r0; r < 128; r += 4) {
        int j = jt * 128 + r;
        float ev = g_ev[bh * Tn + j];
        float v = g_qkv[((size_t)(b * Tn + j)) * N3 + 2 * Cn + h * HDn + d];
        float w = ev * v;
        part += w;
        float ws = fminf(fmaxf(w * WSCALE, -32768.f), 32768.f);
        __half hi = __float2half(ws);
        g_wh[((size_t)bh * Tn + j) * HDn + d] = hi;
        g_wl[((size_t)bh * Tn + j) * HDn + d] = __float2half(ws - __half2float(hi));
    }
    __shared__ float red[256];
    red[tid] = part; __syncthreads();
    if (tid < 128) red[tid] += red[tid + 128];
    __syncthreads();
    if (tid < 64) atomicAdd(&g_wtot[bh * HDn + tid], red[tid] + red[tid + 64]);
}

// ---------------- pi@V via fp16 TC: y_i = T*eu_i*(sum Em1*W/512 + Wtot) ----------------
__global__ void __launch_bounds__(256) pi_v_tc() {
    int bh = blockIdx.y;
    int b = bh / Hn, h = bh % Hn;
    int it = gridDim.x - 1 - blockIdx.x;   // heavy blocks first
    int i0 = it * 128;
    __shared__ __half sA[128][72];
    __shared__ __half sWh[64][72], sWl[64][72];
    int tid = threadIdx.x, wid = tid >> 5, lane = tid & 31;
    int wm = wid & 3, wn = wid >> 2;
    float acc[2][4][4] = {};
    unsigned aA = (unsigned)__cvta_generic_to_shared(&sA[0][0]);
    unsigned aWh = (unsigned)__cvta_generic_to_shared(&sWh[0][0]);
    unsigned aWl = (unsigned)__cvta_generic_to_shared(&sWl[0][0]);

    for (int jc = 0; jc < i0 + 128; jc += 64) {
        if (jc) __syncthreads();
        #pragma unroll
        for (int z = 0; z < 4; z++) {
            int idx = z * 256 + tid;
            int r = idx >> 3, c8 = (idx & 7) * 8;
            *(uint4*)&sA[r][c8] = *(const uint4*)(g_c + ((size_t)bh * Tn + i0 + r) * Tn + jc + c8);
        }
        #pragma unroll
        for (int z = 0; z < 2; z++) {
            int idx = z * 256 + tid;
            int r = idx >> 3, c8 = (idx & 7) * 8;
            *(uint4*)&sWh[r][c8] = *(const uint4*)(g_wh + ((size_t)bh * Tn + jc + r) * HDn + c8);
            *(uint4*)&sWl[r][c8] = *(const uint4*)(g_wl + ((size_t)bh * Tn + jc + r) * HDn + c8);
        }
        __syncthreads();
        #pragma unroll
        for (int kh = 0; kh < 64; kh += 16) {
            unsigned a_[2][4];
            #pragma unroll
            for (int mt = 0; mt < 2; mt++) {
                unsigned off = ((unsigned)((wm * 32 + mt * 16 + (lane & 15)) * 72 + kh + 8 * (lane >> 4))) * 2;
                ldmx4(aA + off, a_[mt][0], a_[mt][1], a_[mt][2], a_[mt][3]);
            }
            #pragma unroll
            for (int nq = 0; nq < 2; nq++) {
                int n0 = wn * 32 + nq * 16;
                unsigned boff = ((unsigned)((kh + (lane & 7) + 8 * ((lane >> 3) & 1)) * 72 + n0 + 8 * (lane >> 4))) * 2;
                unsigned bh0, bh1, bh2, bh3, bl0, bl1, bl2, bl3;
                ldmx4t(aWh + boff, bh0, bh1, bh2, bh3);
                ldmx4t(aWl + boff, bl0, bl1, bl2, bl3);
                #pragma unroll
                for (int mt = 0; mt < 2; mt++) {
                    mma_f16(acc[mt][2 * nq],     a_[mt][0], a_[mt][1], a_[mt][2], a_[mt][3], bh0, bh1);
                    mma_f16(acc[mt][2 * nq],     a_[mt][0], a_[mt][1], a_[mt][2], a_[mt][3], bl0, bl1);
                    mma_f16(acc[mt][2 * nq + 1], a_[mt][0], a_[mt][1], a_[mt][2], a_[mt][3], bh2, bh3);
                    mma_f16(acc[mt][2 * nq + 1], a_[mt][0], a_[mt][1], a_[mt][2], a_[mt][3], bl2, bl3);
                }
            }
        }
    }
    #pragma unroll
    for (int mt = 0; mt < 2; mt++) {
        #pragma unroll
        for (int f = 0; f < 4; f++) {
            float* cc = acc[mt][f];
            int r = i0 + wm * 32 + mt * 16 + (lane >> 2);
            int d = wn * 32 + f * 8 + 2 * (lane & 3);
            float wt0 = g_wtot[bh * HDn + d], wt1 = g_wtot[bh * HDn + d + 1];
            float eu0 = g_eu[bh * Tn + r] * 2048.f;
            float eu1 = g_eu[bh * Tn + r + 8] * 2048.f;
            size_t base = ((size_t)(b * Tn) + r) * Cn + h * HDn + d;
            g_y[base]     = (cc[0] * WINV + wt0) * eu0;
            g_y[base + 1] = (cc[1] * WINV + wt1) * eu0;
            g_y[base + (size_t)8 * Cn]     = (cc[2] * WINV + wt0) * eu1;
            g_y[base + (size_t)8 * Cn + 1] = (cc[3] * WINV + wt1) * eu1;
        }
    }
}

// ---------------- launch ----------------
extern "C" void kernel_launch(void* const* d_in, const int* in_sizes, int n_in,
                              void* d_out, int out_size) {
    const float* x      = (const float*)d_in[0];
    const float* t      = (const float*)d_in[1];
    const float* ln1_w  = (const float*)d_in[2];
    const float* ln1_b  = (const float*)d_in[3];
    const float* attn_w = (const float*)d_in[4];
    const float* attn_b = (const float*)d_in[5];
    const float* proj_w = (const float*)d_in[6];
    const float* proj_b = (const float*)d_in[7];
    const float* ln2_w  = (const float*)d_in[8];
    const float* ln2_b  = (const float*)d_in[9];
    const float* fc_w   = (const float*)d_in[10];
    const float* fc_b   = (const float*)d_in[11];
    const float* fc2_w  = (const float*)d_in[12];
    const float* fc2_b  = (const float*)d_in[13];
    float* out = (float*)d_out;

    float *p_xn, *p_qkv, *p_y, *p_h, *p_hn, *p_m, *p_eu, *p_ev, *p_eutot, *p_evtot;
    cudaGetSymbolAddress((void**)&p_xn,  g_xn);
    cudaGetSymbolAddress((void**)&p_qkv, g_qkv);
    cudaGetSymbolAddress((void**)&p_y,   g_y);
    cudaGetSymbolAddress((void**)&p_h,   g_h);
    cudaGetSymbolAddress((void**)&p_hn,  g_hn);
    cudaGetSymbolAddress((void**)&p_m,   g_m);
    cudaGetSymbolAddress((void**)&p_eu,  g_eu);
    cudaGetSymbolAddress((void**)&p_ev,  g_ev);
    cudaGetSymbolAddress((void**)&p_eutot, g_eutot);
    cudaGetSymbolAddress((void**)&p_evtot, g_evtot);

    // attention sub-block
    ln_kernel<<<ROWS, 256>>>(x, t, ln1_w, ln1_b, p_xn);
    gemm_tc<<<dim3(N3 / 128, ROWS / 128), 256>>>(p_xn, attn_w, attn_b, p_qkv, ROWS, N3, C1, 0);
    qk_conv<<<(ROWS * Cn + 255) / 256, 256>>>();
    score_tc<<<dim3(Tn / 128, Tn / 128, BHn), 256>>>();
    em1_row<<<dim3(Tn, BHn), 256>>>();
    tot_kernel<<<BHn, 256>>>(p_eu, p_eutot);

    // sinkhorn remaining 5 passes: col,row,col,row,col
    sink_col_f<<<dim3(Tn / 512, BHn), 256>>>();
    tot_kernel<<<BHn, 256>>>(p_ev, p_evtot);
    sink_row_f<<<dim3(Tn / 8, BHn), 256>>>();
    tot_kernel<<<BHn, 256>>>(p_eu, p_eutot);
    sink_col_f<<<dim3(Tn / 512, BHn), 256>>>();
    tot_kernel<<<BHn, 256>>>(p_ev, p_evtot);
    sink_row_f<<<dim3(Tn / 8, BHn), 256>>>();
    tot_kernel<<<BHn, 256>>>(p_eu, p_eutot);
    sink_col_f<<<dim3(Tn / 512, BHn), 256>>>();

    zero_wtot<<<(BHn * HDn + 255) / 256, 256>>>();
    w_kernel<<<dim3(Tn / 128, BHn), 256>>>();
    pi_v_tc<<<dim3(Tn / 128, BHn), 256>>>();
    gemm_tc<<<dim3(Cn / 128, ROWS / 128), 256>>>(p_y, proj_w, proj_b, p_h, ROWS, Cn, Cn, 0);

    // MLP sub-block
    ln_kernel<<<ROWS, 256>>>(p_h, t, ln2_w, ln2_b, p_hn);
    gemm_tc<<<dim3(N4 / 128, ROWS / 128), 256>>>(p_hn, fc_w, fc_b, p_m, ROWS, N4, C1, 1);
    gemm_tc<<<dim3(Cn / 128, ROWS / 128), 256>>>(p_m, fc2_w, fc2_b, out, ROWS, Cn, N4, 0);
}

// round 8
// speedup vs baseline: 3.4630x; 1.0708x over previous
#include <cuda_runtime.h>
#include <cuda_fp16.h>
#include <cuda_bf16.h>
#include <math.h>

#define Tn 2048
#define Cn 384
#define Hn 6
#define HDn 64
#define Bn 2
#define BHn 12
#define ROWS 4096      // B*T
#define C1 385         // C+1
#define KA_LN 416      // C1 padded to 32
#define N3 1152        // 3C
#define N4 1536        // 4C
#define LOGT 7.62461899f   // ln(2048)
#define WSCALE 512.f
#define WINV   (1.f / 512.f)

// ---------------- scratch ----------------
__device__ __align__(16) float g_qkv[ROWS * N3];
__device__ __align__(16) float g_s[(size_t)BHn * Tn * Tn];     // fp32 e=exp(s) (lower tiles)
__device__ __align__(16) __half g_c[(size_t)BHn * Tn * Tn];    // fp16 Em1, zero-padded to 128
__device__ __align__(16) __nv_bfloat16 g_qh[ROWS * Cn];
__device__ __align__(16) __nv_bfloat16 g_ql[ROWS * Cn];
__device__ __align__(16) __nv_bfloat16 g_kh[ROWS * Cn];
__device__ __align__(16) __nv_bfloat16 g_kl[ROWS * Cn];
__device__ __align__(16) __half g_wh[BHn * Tn * HDn];
__device__ __align__(16) __half g_wl[BHn * Tn * HDn];
__device__ float g_u[BHn * Tn];
__device__ float g_eu[BHn * Tn];
__device__ float g_ev[BHn * Tn];
__device__ float g_eutot[BHn];
__device__ float g_evtot[BHn];
__device__ float g_wtot[BHn * HDn];
__device__ __align__(16) float g_y[ROWS * Cn];
__device__ __align__(16) float g_h[ROWS * Cn];
// bf16 GEMM operand buffers
__device__ __align__(16) __nv_bfloat16 g_ah[ROWS * N4];   // A hi (max stride 1536)
__device__ __align__(16) __nv_bfloat16 g_al[ROWS * N4];
__device__ __align__(16) __nv_bfloat16 g_a2h[ROWS * N4];  // fc output hi
__device__ __align__(16) __nv_bfloat16 g_a2l[ROWS * N4];
__device__ __align__(16) __nv_bfloat16 g_bh[1048576];
__device__ __align__(16) __nv_bfloat16 g_bl[1048576];

// ---------------- helpers ----------------
__device__ __forceinline__ void ldmx4(unsigned addr, unsigned& r0, unsigned& r1, unsigned& r2, unsigned& r3) {
    asm volatile("ldmatrix.sync.aligned.m8n8.x4.shared.b16 {%0,%1,%2,%3},[%4];"
                 : "=r"(r0), "=r"(r1), "=r"(r2), "=r"(r3) : "r"(addr));
}
__device__ __forceinline__ void ldmx4t(unsigned addr, unsigned& r0, unsigned& r1, unsigned& r2, unsigned& r3) {
    asm volatile("ldmatrix.sync.aligned.m8n8.x4.trans.shared.b16 {%0,%1,%2,%3},[%4];"
                 : "=r"(r0), "=r"(r1), "=r"(r2), "=r"(r3) : "r"(addr));
}
__device__ __forceinline__ void mma_bf16(float* c, unsigned a0, unsigned a1, unsigned a2, unsigned a3,
                                         unsigned b0, unsigned b1) {
    asm volatile("mma.sync.aligned.m16n8k16.row.col.f32.bf16.bf16.f32 "
                 "{%0,%1,%2,%3},{%4,%5,%6,%7},{%8,%9},{%0,%1,%2,%3};"
                 : "+f"(c[0]), "+f"(c[1]), "+f"(c[2]), "+f"(c[3])
                 : "r"(a0), "r"(a1), "r"(a2), "r"(a3), "r"(b0), "r"(b1));
}
__device__ __forceinline__ void mma_f16(float* c, unsigned a0, unsigned a1, unsigned a2, unsigned a3,
                                        unsigned b0, unsigned b1) {
    asm volatile("mma.sync.aligned.m16n8k16.row.col.f32.f16.f16.f32 "
                 "{%0,%1,%2,%3},{%4,%5,%6,%7},{%8,%9},{%0,%1,%2,%3};"
                 : "+f"(c[0]), "+f"(c[1]), "+f"(c[2]), "+f"(c[3])
                 : "r"(a0), "r"(a1), "r"(a2), "r"(a3), "r"(b0), "r"(b1));
}
__device__ __forceinline__ void cpa16(unsigned dst, const void* src) {
    asm volatile("cp.async.cg.shared.global [%0],[%1],16;" :: "r"(dst), "l"(src));
}
#define CPA_COMMIT asm volatile("cp.async.commit_group;")
#define CPA_WAIT1  asm volatile("cp.async.wait_group 1;")

// expm1 on [0,1]: degree-8 Taylor
__device__ __forceinline__ float em1p(float x) {
    float t = fmaf(x, 0.125f, 1.f);
    t = fmaf(x * 0.14285714f, t, 1.f);
    t = fmaf(x * 0.16666667f, t, 1.f);
    t = fmaf(x * 0.2f,        t, 1.f);
    t = fmaf(x * 0.25f,       t, 1.f);
    t = fmaf(x * 0.33333333f, t, 1.f);
    t = fmaf(x * 0.5f,        t, 1.f);
    return x * t;
}

// ---------------- LayerNorm over (x, t) -> bf16 hi/lo, stride KA_LN, zero pad ----------------
__global__ void ln_bf(const float* __restrict__ x, const float* __restrict__ t,
                      const float* __restrict__ w, const float* __restrict__ bb,
                      __nv_bfloat16* __restrict__ oh, __nv_bfloat16* __restrict__ ol) {
    int row = blockIdx.x;
    int tid = threadIdx.x;
    __shared__ float sx[C1];
    __shared__ float red[256];
    float s1 = 0.f;
    for (int c = tid; c < C1; c += 256) {
        float v = (c < Cn) ? x[(size_t)row * Cn + c] : t[0];
        sx[c] = v;
        s1 += v;
    }
    red[tid] = s1; __syncthreads();
    for (int o = 128; o > 0; o >>= 1) { if (tid < o) red[tid] += red[tid + o]; __syncthreads(); }
    float mean = red[0] * (1.f / C1);
    __syncthreads();
    float s2 = 0.f;
    for (int c = tid; c < C1; c += 256) { float d = sx[c] - mean; s2 += d * d; }
    red[tid] = s2; __syncthreads();
    for (int o = 128; o > 0; o >>= 1) { if (tid < o) red[tid] += red[tid + o]; __syncthreads(); }
    float rs = rsqrtf(red[0] * (1.f / C1) + 1e-5f);
    for (int c = tid; c < C1; c += 256) {
        float v = (sx[c] - mean) * rs * w[c] + bb[c];
        __nv_bfloat16 hi = __float2bfloat16(v);
        oh[(size_t)row * KA_LN + c] = hi;
        ol[(size_t)row * KA_LN + c] = __float2bfloat16(v - __bfloat162float(hi));
    }
    if (tid < KA_LN - C1) {
        oh[(size_t)row * KA_LN + C1 + tid] = __float2bfloat16(0.f);
        ol[(size_t)row * KA_LN + C1 + tid] = __float2bfloat16(0.f);
    }
}

// ---------------- fp32 -> bf16 hi/lo (contiguous, count mult of 4) ----------------
__global__ void conv_a(const float* __restrict__ src, __nv_bfloat16* __restrict__ oh,
                       __nv_bfloat16* __restrict__ ol, int count4) {
    int idx = blockIdx.x * 256 + threadIdx.x;
    if (idx >= count4) return;
    float4 v = ((const float4*)src)[idx];
    __nv_bfloat16 h0 = __float2bfloat16(v.x), h1 = __float2bfloat16(v.y);
    __nv_bfloat16 h2 = __float2bfloat16(v.z), h3 = __float2bfloat16(v.w);
    __nv_bfloat16 hbuf[4] = {h0, h1, h2, h3};
    __nv_bfloat16 lbuf[4] = {
        __float2bfloat16(v.x - __bfloat162float(h0)), __float2bfloat16(v.y - __bfloat162float(h1)),
        __float2bfloat16(v.z - __bfloat162float(h2)), __float2bfloat16(v.w - __bfloat162float(h3))};
    *(uint2*)(oh + (size_t)idx * 4) = *(uint2*)hbuf;
    *(uint2*)(ol + (size_t)idx * 4) = *(uint2*)lbuf;
}

// ---------------- weight fp32 KxN -> bf16 hi/lo KaxN (zero rows K..Ka) ----------------
__global__ void conv_b(const float* __restrict__ w, __nv_bfloat16* __restrict__ oh,
                       __nv_bfloat16* __restrict__ ol, int K, int Ka, int N) {
    int idx = blockIdx.x * 256 + threadIdx.x;
    if (idx * 4 >= Ka * N) return;
    int row = (idx * 4) / N;
    float4 v = (row < K) ? ((const float4*)w)[idx] : make_float4(0.f, 0.f, 0.f, 0.f);
    __nv_bfloat16 h0 = __float2bfloat16(v.x), h1 = __float2bfloat16(v.y);
    __nv_bfloat16 h2 = __float2bfloat16(v.z), h3 = __float2bfloat16(v.w);
    __nv_bfloat16 hbuf[4] = {h0, h1, h2, h3};
    __nv_bfloat16 lbuf[4] = {
        __float2bfloat16(v.x - __bfloat162float(h0)), __float2bfloat16(v.y - __bfloat162float(h1)),
        __float2bfloat16(v.z - __bfloat162float(h2)), __float2bfloat16(v.w - __bfloat162float(h3))};
    *(uint2*)(oh + (size_t)idx * 4) = *(uint2*)hbuf;
    *(uint2*)(ol + (size_t)idx * 4) = *(uint2*)lbuf;
}

// ---------------- pipelined bf16 GEMM: 128x128 tile, cp.async 2-stage ----------------
// obf=0: out fp32 to outF. obf=1: gelu already applied per act; out bf16 hi/lo to oAh/oAl.
__global__ void __launch_bounds__(256) gemm_bf(const __nv_bfloat16* __restrict__ Ah,
                                               const __nv_bfloat16* __restrict__ Al,
                                               const __nv_bfloat16* __restrict__ Bh,
                                               const __nv_bfloat16* __restrict__ Bl,
                                               const float* __restrict__ bias,
                                               float* __restrict__ outF,
                                               __nv_bfloat16* __restrict__ oAh,
                                               __nv_bfloat16* __restrict__ oAl,
                                               int M, int N, int Ka, int act, int obf) {
    extern __shared__ __nv_bfloat16 dyn[];
    __nv_bfloat16* sA = dyn;            // [st][hl][128*40]
    __nv_bfloat16* sB = dyn + 4 * 5120; // [st][hl][32*136]
    int tid = threadIdx.x;
    int wid = tid >> 5, lane = tid & 31;
    int wm = wid & 3, wn = wid >> 2;
    int bm = blockIdx.y * 128, bn = blockIdx.x * 128;
    float acc[2][8][4] = {};
    unsigned sAu = (unsigned)__cvta_generic_to_shared(sA);
    unsigned sBu = (unsigned)__cvta_generic_to_shared(sB);

    int nk = Ka >> 5;
    // async load of k-tile kt into stage st
    auto load_stage = [&](int kt, int st) {
        unsigned aH = sAu + (st * 2 + 0) * 5120 * 2;
        unsigned aL = sAu + (st * 2 + 1) * 5120 * 2;
        unsigned bH = sBu + (st * 2 + 0) * 4352 * 2;
        unsigned bL = sBu + (st * 2 + 1) * 4352 * 2;
        int k0 = kt * 32;
        #pragma unroll
        for (int z = 0; z < 2; z++) {
            int idx = z * 256 + tid;
            int row = idx >> 2, cq = (idx & 3) * 8;
            const __nv_bfloat16* pa = Ah + (size_t)(bm + row) * Ka + k0 + cq;
            const __nv_bfloat16* pl = Al + (size_t)(bm + row) * Ka + k0 + cq;
            cpa16(aH + (row * 40 + cq) * 2, pa);
            cpa16(aL + (row * 40 + cq) * 2, pl);
        }
        #pragma unroll
        for (int z = 0; z < 2; z++) {
            int idx = z * 256 + tid;
            int row = idx >> 4, cq = (idx & 15) * 8;
            const __nv_bfloat16* pb = Bh + (size_t)(k0 + row) * N + bn + cq;
            const __nv_bfloat16* pl = Bl + (size_t)(k0 + row) * N + bn + cq;
            cpa16(bH + (row * 136 + cq) * 2, pb);
            cpa16(bL + (row * 136 + cq) * 2, pl);
        }
    };

    load_stage(0, 0);
    CPA_COMMIT;
    for (int kt = 0; kt < nk; kt++) {
        int cur = kt & 1;
        if (kt + 1 < nk) load_stage(kt + 1, cur ^ 1);
        CPA_COMMIT;
        CPA_WAIT1;
        __syncthreads();
        unsigned aH = sAu + (cur * 2 + 0) * 5120 * 2;
        unsigned aL = sAu + (cur * 2 + 1) * 5120 * 2;
        unsigned bH = sBu + (cur * 2 + 0) * 4352 * 2;
        unsigned bL = sBu + (cur * 2 + 1) * 4352 * 2;
        #pragma unroll
        for (int kh = 0; kh < 32; kh += 16) {
            unsigned ah[2][4], al[2][4];
            #pragma unroll
            for (int mt = 0; mt < 2; mt++) {
                unsigned off = ((unsigned)((wm * 32 + mt * 16 + (lane & 15)) * 40 + kh + (lane >> 4) * 8)) * 2;
                ldmx4(aH + off, ah[mt][0], ah[mt][1], ah[mt][2], ah[mt][3]);
                ldmx4(aL + off, al[mt][0], al[mt][1], al[mt][2], al[mt][3]);
            }
            #pragma unroll
            for (int np = 0; np < 4; np++) {
                int n0 = wn * 64 + np * 16;
                unsigned boff = ((unsigned)((kh + (lane & 7) + 8 * ((lane >> 3) & 1)) * 136 + n0 + 8 * (lane >> 4))) * 2;
                unsigned bh0, bh1, bh2, bh3, bl0, bl1, bl2, bl3;
                ldmx4t(bH + boff, bh0, bh1, bh2, bh3);
                ldmx4t(bL + boff, bl0, bl1, bl2, bl3);
                #pragma unroll
                for (int mt = 0; mt < 2; mt++) {
                    mma_bf16(acc[mt][2 * np],     ah[mt][0], ah[mt][1], ah[mt][2], ah[mt][3], bh0, bh1);
                    mma_bf16(acc[mt][2 * np],     ah[mt][0], ah[mt][1], ah[mt][2], ah[mt][3], bl0, bl1);
                    mma_bf16(acc[mt][2 * np],     al[mt][0], al[mt][1], al[mt][2], al[mt][3], bh0, bh1);
                    mma_bf16(acc[mt][2 * np + 1], ah[mt][0], ah[mt][1], ah[mt][2], ah[mt][3], bh2, bh3);
                    mma_bf16(acc[mt][2 * np + 1], ah[mt][0], ah[mt][1], ah[mt][2], ah[mt][3], bl2, bl3);
                    mma_bf16(acc[mt][2 * np + 1], al[mt][0], al[mt][1], al[mt][2], al[mt][3], bh2, bh3);
                }
            }
        }
        __syncthreads();
    }
    #pragma unroll
    for (int mt = 0; mt < 2; mt++) {
        #pragma unroll
        for (int nt = 0; nt < 8; nt++) {
            float* cc = acc[mt][nt];
            int r = bm + wm * 32 + mt * 16 + (lane >> 2);
            int cn = bn + wn * 64 + nt * 8 + (lane & 3) * 2;
            float b0 = bias[cn], b1 = bias[cn + 1];
            float v0 = cc[0] + b0, v1 = cc[1] + b1;
            float v2 = cc[2] + b0, v3 = cc[3] + b1;
            if (act == 1) {
                v0 = 0.5f * v0 * (1.f + erff(v0 * 0.70710678f));
                v1 = 0.5f * v1 * (1.f + erff(v1 * 0.70710678f));
                v2 = 0.5f * v2 * (1.f + erff(v2 * 0.70710678f));
                v3 = 0.5f * v3 * (1.f + erff(v3 * 0.70710678f));
            }
            if (obf) {
                __nv_bfloat16 h0 = __float2bfloat16(v0), h1 = __float2bfloat16(v1);
                __nv_bfloat16 h2 = __float2bfloat16(v2), h3 = __float2bfloat16(v3);
                oAh[(size_t)r * N + cn] = h0;
                oAh[(size_t)r * N + cn + 1] = h1;
                oAh[(size_t)(r + 8) * N + cn] = h2;
                oAh[(size_t)(r + 8) * N + cn + 1] = h3;
                oAl[(size_t)r * N + cn] = __float2bfloat16(v0 - __bfloat162float(h0));
                oAl[(size_t)r * N + cn + 1] = __float2bfloat16(v1 - __bfloat162float(h1));
                oAl[(size_t)(r + 8) * N + cn] = __float2bfloat16(v2 - __bfloat162float(h2));
                oAl[(size_t)(r + 8) * N + cn + 1] = __float2bfloat16(v3 - __bfloat162float(h3));
            } else {
                outF[(size_t)r * N + cn] = v0;
                outF[(size_t)r * N + cn + 1] = v1;
                outF[(size_t)(r + 8) * N + cn] = v2;
                outF[(size_t)(r + 8) * N + cn + 1] = v3;
            }
        }
    }
}

// ---------------- convert q,k -> bf16 hi/lo ----------------
__global__ void qk_conv() {
    int idx = blockIdx.x * 256 + threadIdx.x;
    if (idx >= ROWS * Cn) return;
    int row = idx / Cn, c = idx % Cn;
    float q = g_qkv[(size_t)row * N3 + c];
    float k = g_qkv[(size_t)row * N3 + Cn + c];
    __nv_bfloat16 qh = __float2bfloat16(q);
    __nv_bfloat16 kh = __float2bfloat16(k);
    g_qh[idx] = qh;
    g_ql[idx] = __float2bfloat16(q - __bfloat162float(qh));
    g_kh[idx] = kh;
    g_kl[idx] = __float2bfloat16(k - __bfloat162float(kh));
}

// ---------------- TC scores + fused exp ----------------
__global__ void __launch_bounds__(256) score_tc() {
    int jt = blockIdx.x, it = blockIdx.y, bh = blockIdx.z;
    if (jt > it) return;
    int b = bh / Hn, h = bh % Hn;
    __shared__ __nv_bfloat16 sQh[128][40], sQl[128][40], sKh[128][40], sKl[128][40];
    int tid = threadIdx.x, wid = tid >> 5, lane = tid & 31;
    int wm = wid & 3, wn = wid >> 2;
    float acc[2][8][4] = {};
    unsigned aQh = (unsigned)__cvta_generic_to_shared(&sQh[0][0]);
    unsigned aQl = (unsigned)__cvta_generic_to_shared(&sQl[0][0]);
    unsigned aKh = (unsigned)__cvta_generic_to_shared(&sKh[0][0]);
    unsigned aKl = (unsigned)__cvta_generic_to_shared(&sKl[0][0]);
    size_t qbase = ((size_t)(b * Tn + it * 128)) * Cn + h * HDn;
    size_t kbase = ((size_t)(b * Tn + jt * 128)) * Cn + h * HDn;

    for (int ks = 0; ks < 2; ks++) {
        if (ks) __syncthreads();
        #pragma unroll
        for (int z = 0; z < 2; z++) {
            int idx = z * 256 + tid;
            int r = idx >> 2, c8 = (idx & 3) * 8;
            *(uint4*)&sQh[r][c8] = *(const uint4*)(g_qh + qbase + (size_t)r * Cn + ks * 32 + c8);
            *(uint4*)&sQl[r][c8] = *(const uint4*)(g_ql + qbase + (size_t)r * Cn + ks * 32 + c8);
            *(uint4*)&sKh[r][c8] = *(const uint4*)(g_kh + kbase + (size_t)r * Cn + ks * 32 + c8);
            *(uint4*)&sKl[r][c8] = *(const uint4*)(g_kl + kbase + (size_t)r * Cn + ks * 32 + c8);
        }
        __syncthreads();
        #pragma unroll
        for (int kh = 0; kh < 32; kh += 16) {
            unsigned qh_[2][4], ql_[2][4];
            #pragma unroll
            for (int mt = 0; mt < 2; mt++) {
                unsigned off = ((unsigned)((wm * 32 + mt * 16 + (lane & 15)) * 40 + kh + 8 * (lane >> 4))) * 2;
                ldmx4(aQh + off, qh_[mt][0], qh_[mt][1], qh_[mt][2], qh_[mt][3]);
                ldmx4(aQl + off, ql_[mt][0], ql_[mt][1], ql_[mt][2], ql_[mt][3]);
            }
            #pragma unroll
            for (int nq = 0; nq < 4; nq++) {
                int n0 = wn * 64 + nq * 16;
                unsigned boff = ((unsigned)((n0 + (lane & 15)) * 40 + kh + 8 * (lane >> 4))) * 2;
                unsigned kh0, kh1, kh2, kh3, kl0, kl1, kl2, kl3;
                ldmx4(aKh + boff, kh0, kh1, kh2, kh3);
                ldmx4(aKl + boff, kl0, kl1, kl2, kl3);
                #pragma unroll
                for (int mt = 0; mt < 2; mt++) {
                    mma_bf16(acc[mt][2 * nq],     qh_[mt][0], qh_[mt][1], qh_[mt][2], qh_[mt][3], kh0, kh2);
                    mma_bf16(acc[mt][2 * nq],     qh_[mt][0], qh_[mt][1], qh_[mt][2], qh_[mt][3], kl0, kl2);
                    mma_bf16(acc[mt][2 * nq],     ql_[mt][0], ql_[mt][1], ql_[mt][2], ql_[mt][3], kh0, kh2);
                    mma_bf16(acc[mt][2 * nq + 1], qh_[mt][0], qh_[mt][1], qh_[mt][2], qh_[mt][3], kh1, kh3);
                    mma_bf16(acc[mt][2 * nq + 1], qh_[mt][0], qh_[mt][1], qh_[mt][2], qh_[mt][3], kl1, kl3);
                    mma_bf16(acc[mt][2 * nq + 1], ql_[mt][0], ql_[mt][1], ql_[mt][2], ql_[mt][3], kh1, kh3);
                }
            }
        }
    }
    float* srow = g_s + (size_t)bh * Tn * Tn;
    #pragma unroll
    for (int mt = 0; mt < 2; mt++) {
        #pragma unroll
        for (int f = 0; f < 8; f++) {
            float* cc = acc[mt][f];
            int gi = it * 128 + wm * 32 + mt * 16 + (lane >> 2);
            int gj = jt * 128 + wn * 64 + (f >> 1) * 16 + (f & 1) * 8 + 2 * (lane & 3);
            float2 e01, e23;
            e01.x = __expf(fminf(cc[0] * 0.125f, 80.f));
            e01.y = __expf(fminf(cc[1] * 0.125f, 80.f));
            e23.x = __expf(fminf(cc[2] * 0.125f, 80.f));
            e23.y = __expf(fminf(cc[3] * 0.125f, 80.f));
            *(float2*)&srow[(size_t)gi * Tn + gj] = e01;
            *(float2*)&srow[(size_t)(gi + 8) * Tn + gj] = e23;
        }
    }
}

// ---------------- per row: normalize, Em1 poly, pad to 128, u1, eu ----------------
__global__ void em1_row() {
    int i = blockIdx.x, bh = blockIdx.y;
    int tid = threadIdx.x;
    const float* erow = g_s + ((size_t)bh * Tn + i) * Tn;
    __half2* crow2 = (__half2*)(g_c + ((size_t)bh * Tn + i) * Tn);
    __shared__ float sp[Tn];
    __shared__ float red[256];
    float sum = 0.f;
    for (int j = tid; j <= i; j += 256) { float e = erow[j]; sp[j] = e; sum += e; }
    red[tid] = sum; __syncthreads();
    for (int o = 128; o > 0; o >>= 1) { if (tid < o) red[tid] += red[tid + o]; __syncthreads(); }
    float inv = 1.f / red[0];
    __syncthreads();
    float se = 0.f;
    int lim2 = (((i >> 7) + 1) << 7) >> 1;
    for (int jp = tid; jp < lim2; jp += 256) {
        int j0 = jp * 2, j1 = j0 + 1;
        float e0 = (j0 <= i) ? em1p(sp[j0] * inv) : 0.f;
        float e1 = (j1 <= i) ? em1p(sp[j1] * inv) : 0.f;
        crow2[jp] = __floats2half2_rn(e0, e1);
        se += e0 + e1;
    }
    red[tid] = se; __syncthreads();
    for (int o = 128; o > 0; o >>= 1) { if (tid < o) red[tid] += red[tid + o]; __syncthreads(); }
    if (tid == 0) {
        float u = -LOGT - __logf(red[0] + (float)Tn);
        g_u[bh * Tn + i] = u;
        g_eu[bh * Tn + i] = __expf(u);
    }
}

// ---------------- per-bh totals ----------------
__global__ void tot_kernel(const float* __restrict__ vec, float* __restrict__ tot) {
    int bh = blockIdx.x, tid = threadIdx.x;
    __shared__ float red[256];
    float s = 0.f;
    for (int i = tid; i < Tn; i += 256) s += vec[bh * Tn + i];
    red[tid] = s; __syncthreads();
    for (int o = 128; o > 0; o >>= 1) { if (tid < o) red[tid] += red[tid + o]; __syncthreads(); }
    if (tid == 0) tot[bh] = red[0];
}

// ---------------- Sinkhorn row pass ----------------
__global__ void sink_row_f() {
    int r0 = blockIdx.x * 8, bh = blockIdx.y;
    int tid = threadIdx.x;
    __shared__ float sev[Tn];
    __shared__ float red[256];
    int jmax = r0 + 8;
    for (int j = tid; j < jmax; j += 256) sev[j] = g_ev[bh * Tn + j];
    float evtot = g_evtot[bh];
    __syncthreads();
    for (int r = 0; r < 8; r++) {
        int i = r0 + r;
        const uint4* cv = (const uint4*)(g_c + ((size_t)bh * Tn + i) * Tn);
        int nv = (i + 8) >> 3;
        float s = 0.f;
        for (int vi = tid; vi < nv; vi += 256) {
            uint4 pk = cv[vi];
            const __half2* hp = (const __half2*)&pk;
            int jb = vi * 8;
            #pragma unroll
            for (int z = 0; z < 4; z++) {
                float2 f = __half22float2(hp[z]);
                s += f.x * sev[jb + 2 * z] + f.y * sev[jb + 2 * z + 1];
            }
        }
        red[tid] = s; __syncthreads();
        for (int o = 128; o > 0; o >>= 1) { if (tid < o) red[tid] += red[tid + o]; __syncthreads(); }
        if (tid == 0) {
            float u = -LOGT - __logf(red[0] + evtot);
            g_u[bh * Tn + i] = u;
            g_eu[bh * Tn + i] = __expf(u);
        }
        __syncthreads();
    }
}

// ---------------- Sinkhorn col pass ----------------
__global__ void sink_col_f() {
    int bh = blockIdx.y;
    int tid = threadIdx.x;
    int j0 = (blockIdx.x * 256 + tid) * 2;
    int ibase = blockIdx.x * 512;
    __shared__ float seu[Tn];
    for (int i = tid; i < Tn - ibase; i += 256) seu[i] = g_eu[bh * Tn + ibase + i];
    float eutot = g_eutot[bh];
    __syncthreads();
    const __half* cb = g_c + (size_t)bh * Tn * Tn + j0;
    float s0 = 0.f, s1 = 0.f;
    #pragma unroll 4
    for (int i = j0; i < Tn; i++) {
        __half2 hh = *(const __half2*)(cb + (size_t)i * Tn);
        float2 f = __half22float2(hh);
        float ui = seu[i - ibase];
        s0 += f.x * ui;
        s1 += f.y * ui;
    }
    float v0 = -LOGT - __logf(s0 + eutot);
    float v1 = -LOGT - __logf(s1 + eutot);
    g_ev[bh * Tn + j0]     = __expf(v0);
    g_ev[bh * Tn + j0 + 1] = __expf(v1);
}

// ---------------- zero wtot ----------------
__global__ void zero_wtot() {
    int i = blockIdx.x * 256 + threadIdx.x;
    if (i < BHn * HDn) g_wtot[i] = 0.f;
}

// ---------------- W = ev*V*512 -> fp16 hi/lo; Wtot ----------------
__global__ void w_kernel() {
    int jt = blockIdx.x, bh = blockIdx.y;
    int b = bh / Hn, h = bh % Hn;
    int tid = threadIdx.x;
    int d = tid & 63, r0 = tid >> 6;
    float part = 0.f;
    for (int r = r0; r < 128; r += 4) {
        int j = jt * 128 + r;
        float ev = g_ev[bh * Tn + j];
        float v = g_qkv[((size_t)(b * Tn + j)) * N3 + 2 * Cn + h * HDn + d];
        float w = ev * v;
        part += w;
        float ws = fminf(fmaxf(w * WSCALE, -32768.f), 32768.f);
        __half hi = __float2half(ws);
        g_wh[((size_t)bh * Tn + j) * HDn + d] = hi;
        g_wl[((size_t)bh * Tn + j) * HDn + d] = __float2half(ws - __half2float(hi));
    }
    __shared__ float red[256];
    red[tid] = part; __syncthreads();
    if (tid < 128) red[tid] += red[tid + 128];
    __syncthreads();
    if (tid < 64) atomicAdd(&g_wtot[bh * HDn + tid], red[tid] + red[tid + 64]);
}

// ---------------- pi@V via fp16 TC ----------------
__global__ void __launch_bounds__(256) pi_v_tc() {
    int bh = blockIdx.y;
    int b = bh / Hn, h = bh % Hn;
    int it = gridDim.x - 1 - blockIdx.x;
    int i0 = it * 128;
    __shared__ __half sA[128][72];
    __shared__ __half sWh[64][72], sWl[64][72];
    int tid = threadIdx.x, wid = tid >> 5, lane = tid & 31;
    int wm = wid & 3, wn = wid >> 2;
    float acc[2][4][4] = {};
    unsigned aA = (unsigned)__cvta_generic_to_shared(&sA[0][0]);
    unsigned aWh = (unsigned)__cvta_generic_to_shared(&sWh[0][0]);
    unsigned aWl = (unsigned)__cvta_generic_to_shared(&sWl[0][0]);

    for (int jc = 0; jc < i0 + 128; jc += 64) {
        if (jc) __syncthreads();
        #pragma unroll
        for (int z = 0; z < 4; z++) {
            int idx = z * 256 + tid;
            int r = idx >> 3, c8 = (idx & 7) * 8;
            *(uint4*)&sA[r][c8] = *(const uint4*)(g_c + ((size_t)bh * Tn + i0 + r) * Tn + jc + c8);
        }
        #pragma unroll
        for (int z = 0; z < 2; z++) {
            int idx = z * 256 + tid;
            int r = idx >> 3, c8 = (idx & 7) * 8;
            *(uint4*)&sWh[r][c8] = *(const uint4*)(g_wh + ((size_t)bh * Tn + jc + r) * HDn + c8);
            *(uint4*)&sWl[r][c8] = *(const uint4*)(g_wl + ((size_t)bh * Tn + jc + r) * HDn + c8);
        }
        __syncthreads();
        #pragma unroll
        for (int kh = 0; kh < 64; kh += 16) {
            unsigned a_[2][4];
            #pragma unroll
            for (int mt = 0; mt < 2; mt++) {
                unsigned off = ((unsigned)((wm * 32 + mt * 16 + (lane & 15)) * 72 + kh + 8 * (lane >> 4))) * 2;
                ldmx4(aA + off, a_[mt][0], a_[mt][1], a_[mt][2], a_[mt][3]);
            }
            #pragma unroll
            for (int nq = 0; nq < 2; nq++) {
                int n0 = wn * 32 + nq * 16;
                unsigned boff = ((unsigned)((kh + (lane & 7) + 8 * ((lane >> 3) & 1)) * 72 + n0 + 8 * (lane >> 4))) * 2;
                unsigned bh0, bh1, bh2, bh3, bl0, bl1, bl2, bl3;
                ldmx4t(aWh + boff, bh0, bh1, bh2, bh3);
                ldmx4t(aWl + boff, bl0, bl1, bl2, bl3);
                #pragma unroll
                for (int mt = 0; mt < 2; mt++) {
                    mma_f16(acc[mt][2 * nq],     a_[mt][0], a_[mt][1], a_[mt][2], a_[mt][3], bh0, bh1);
                    mma_f16(acc[mt][2 * nq],     a_[mt][0], a_[mt][1], a_[mt][2], a_[mt][3], bl0, bl1);
                    mma_f16(acc[mt][2 * nq + 1], a_[mt][0], a_[mt][1], a_[mt][2], a_[mt][3], bh2, bh3);
                    mma_f16(acc[mt][2 * nq + 1], a_[mt][0], a_[mt][1], a_[mt][2], a_[mt][3], bl2, bl3);
                }
            }
        }
    }
    #pragma unroll
    for (int mt = 0; mt < 2; mt++) {
        #pragma unroll
        for (int f = 0; f < 4; f++) {
            float* cc = acc[mt][f];
            int r = i0 + wm * 32 + mt * 16 + (lane >> 2);
            int d = wn * 32 + f * 8 + 2 * (lane & 3);
            float wt0 = g_wtot[bh * HDn + d], wt1 = g_wtot[bh * HDn + d + 1];
            float eu0 = g_eu[bh * Tn + r] * 2048.f;
            float eu1 = g_eu[bh * Tn + r + 8] * 2048.f;
            size_t base = ((size_t)(b * Tn) + r) * Cn + h * HDn + d;
            g_y[base]     = (cc[0] * WINV + wt0) * eu0;
            g_y[base + 1] = (cc[1] * WINV + wt1) * eu0;
            g_y[base + (size_t)8 * Cn]     = (cc[2] * WINV + wt0) * eu1;
            g_y[base + (size_t)8 * Cn + 1] = (cc[3] * WINV + wt1) * eu1;
        }
    }
}

// ---------------- launch ----------------
extern "C" void kernel_launch(void* const* d_in, const int* in_sizes, int n_in,
                              void* d_out, int out_size) {
    const float* x      = (const float*)d_in[0];
    const float* t      = (const float*)d_in[1];
    const float* ln1_w  = (const float*)d_in[2];
    const float* ln1_b  = (const float*)d_in[3];
    const float* attn_w = (const float*)d_in[4];
    const float* attn_b = (const float*)d_in[5];
    const float* proj_w = (const float*)d_in[6];
    const float* proj_b = (const float*)d_in[7];
    const float* ln2_w  = (const float*)d_in[8];
    const float* ln2_b  = (const float*)d_in[9];
    const float* fc_w   = (const float*)d_in[10];
    const float* fc_b   = (const float*)d_in[11];
    const float* fc2_w  = (const float*)d_in[12];
    const float* fc2_b  = (const float*)d_in[13];
    float* out = (float*)d_out;

    float *p_qkv, *p_y, *p_h, *p_eu, *p_ev, *p_eutot, *p_evtot;
    __nv_bfloat16 *p_ah, *p_al, *p_a2h, *p_a2l, *p_bh, *p_bl;
    cudaGetSymbolAddress((void**)&p_qkv, g_qkv);
    cudaGetSymbolAddress((void**)&p_y,   g_y);
    cudaGetSymbolAddress((void**)&p_h,   g_h);
    cudaGetSymbolAddress((void**)&p_eu,  g_eu);
    cudaGetSymbolAddress((void**)&p_ev,  g_ev);
    cudaGetSymbolAddress((void**)&p_eutot, g_eutot);
    cudaGetSymbolAddress((void**)&p_evtot, g_evtot);
    cudaGetSymbolAddress((void**)&p_ah,  g_ah);
    cudaGetSymbolAddress((void**)&p_al,  g_al);
    cudaGetSymbolAddress((void**)&p_a2h, g_a2h);
    cudaGetSymbolAddress((void**)&p_a2l, g_a2l);
    cudaGetSymbolAddress((void**)&p_bh,  g_bh);
    cudaGetSymbolAddress((void**)&p_bl,  g_bl);

    static int smem_set = 0;
    const int GSM = 75776;
    if (!smem_set) {
        cudaFuncSetAttribute(gemm_bf, cudaFuncAttributeMaxDynamicSharedMemorySize, GSM);
        smem_set = 1;
    }

    // ---- attention sub-block ----
    ln_bf<<<ROWS, 256>>>(x, t, ln1_w, ln1_b, p_ah, p_al);
    conv_b<<<(KA_LN * N3 / 4 + 255) / 256, 256>>>(attn_w, p_bh, p_bl, C1, KA_LN, N3);
    gemm_bf<<<dim3(N3 / 128, ROWS / 128), 256, GSM>>>(p_ah, p_al, p_bh, p_bl, attn_b,
                                                      p_qkv, nullptr, nullptr, ROWS, N3, KA_LN, 0, 0);
    qk_conv<<<(ROWS * Cn + 255) / 256, 256>>>();
    score_tc<<<dim3(Tn / 128, Tn / 128, BHn), 256>>>();
    em1_row<<<dim3(Tn, BHn), 256>>>();
    tot_kernel<<<BHn, 256>>>(p_eu, p_eutot);

    // sinkhorn remaining 5 passes
    sink_col_f<<<dim3(Tn / 512, BHn), 256>>>();
    tot_kernel<<<BHn, 256>>>(p_ev, p_evtot);
    sink_row_f<<<dim3(Tn / 8, BHn), 256>>>();
    tot_kernel<<<BHn, 256>>>(p_eu, p_eutot);
    sink_col_f<<<dim3(Tn / 512, BHn), 256>>>();
    tot_kernel<<<BHn, 256>>>(p_ev, p_evtot);
    sink_row_f<<<dim3(Tn / 8, BHn), 256>>>();
    tot_kernel<<<BHn, 256>>>(p_eu, p_eutot);
    sink_col_f<<<dim3(Tn / 512, BHn), 256>>>();

    zero_wtot<<<(BHn * HDn + 255) / 256, 256>>>();
    w_kernel<<<dim3(Tn / 128, BHn), 256>>>();
    pi_v_tc<<<dim3(Tn / 128, BHn), 256>>>();

    // proj
    conv_a<<<(ROWS * Cn / 4 + 255) / 256, 256>>>(p_y, p_ah, p_al, ROWS * Cn / 4);
    conv_b<<<(Cn * Cn / 4 + 255) / 256, 256>>>(proj_w, p_bh, p_bl, Cn, Cn, Cn);
    gemm_bf<<<dim3(Cn / 128, ROWS / 128), 256, GSM>>>(p_ah, p_al, p_bh, p_bl, proj_b,
                                                      p_h, nullptr, nullptr, ROWS, Cn, Cn, 0, 0);

    // ---- MLP sub-block ----
    ln_bf<<<ROWS, 256>>>(p_h, t, ln2_w, ln2_b, p_ah, p_al);
    conv_b<<<(KA_LN * N4 / 4 + 255) / 256, 256>>>(fc_w, p_bh, p_bl, C1, KA_LN, N4);
    gemm_bf<<<dim3(N4 / 128, ROWS / 128), 256, GSM>>>(p_ah, p_al, p_bh, p_bl, fc_b,
                                                      nullptr, p_a2h, p_a2l, ROWS, N4, KA_LN, 1, 1);
    conv_b<<<(N4 * Cn / 4 + 255) / 256, 256>>>(fc2_w, p_bh, p_bl, N4, N4, Cn);
    gemm_bf<<<dim3(Cn / 128, ROWS / 128), 256, GSM>>>(p_a2h, p_a2l, p_bh, p_bl, fc2_b,
                                                      out, nullptr, nullptr, ROWS, Cn, N4, 0, 0);
}

// round 9
// speedup vs baseline: 5.5394x; 1.5996x over previous
#include <cuda_runtime.h>
#include <cuda_fp16.h>
#include <cuda_bf16.h>
#include <math.h>

#define Tn 2048
#define Cn 384
#define Hn 6
#define HDn 64
#define Bn 2
#define BHn 12
#define ROWS 4096      // B*T
#define C1 385         // C+1
#define KA_LN 416      // C1 padded to 32
#define N3 1152        // 3C
#define N4 1536        // 4C
#define LOGT 7.62461899f   // ln(2048)
#define WSCALE 512.f
#define WINV   (1.f / 512.f)

// ---------------- scratch ----------------
__device__ __align__(16) float g_qkv[ROWS * N3];
__device__ __align__(16) __half g_e[(size_t)BHn * Tn * Tn];    // fp16 e=exp(score) lower tri (zero elsewhere)
__device__ __align__(16) __half g_c[(size_t)BHn * Tn * Tn];    // fp16 Em1 (zero-init padding relied upon)
__device__ __align__(16) __nv_bfloat16 g_qh[ROWS * Cn];
__device__ __align__(16) __nv_bfloat16 g_ql[ROWS * Cn];
__device__ __align__(16) __nv_bfloat16 g_kh[ROWS * Cn];
__device__ __align__(16) __nv_bfloat16 g_kl[ROWS * Cn];
__device__ __align__(16) __half g_wh[BHn * Tn * HDn];
__device__ __align__(16) __half g_wl[BHn * Tn * HDn];
__device__ float g_rowsum[BHn * Tn];
__device__ float g_eu[BHn * Tn];
__device__ float g_ev[BHn * Tn];
__device__ float g_eutot[BHn];
__device__ float g_evtot[BHn];
__device__ float g_wtot[BHn * HDn];
__device__ __align__(16) float g_cpart[8 * BHn * Tn];
__device__ __align__(16) float g_y[ROWS * Cn];
__device__ __align__(16) float g_h[ROWS * Cn];
__device__ __align__(16) __nv_bfloat16 g_ah[ROWS * N4];
__device__ __align__(16) __nv_bfloat16 g_al[ROWS * N4];
__device__ __align__(16) __nv_bfloat16 g_a2h[ROWS * N4];
__device__ __align__(16) __nv_bfloat16 g_a2l[ROWS * N4];
__device__ __align__(16) __nv_bfloat16 g_bh[1048576];
__device__ __align__(16) __nv_bfloat16 g_bl[1048576];

// ---------------- helpers ----------------
__device__ __forceinline__ void ldmx4(unsigned addr, unsigned& r0, unsigned& r1, unsigned& r2, unsigned& r3) {
    asm volatile("ldmatrix.sync.aligned.m8n8.x4.shared.b16 {%0,%1,%2,%3},[%4];"
                 : "=r"(r0), "=r"(r1), "=r"(r2), "=r"(r3) : "r"(addr));
}
__device__ __forceinline__ void ldmx4t(unsigned addr, unsigned& r0, unsigned& r1, unsigned& r2, unsigned& r3) {
    asm volatile("ldmatrix.sync.aligned.m8n8.x4.trans.shared.b16 {%0,%1,%2,%3},[%4];"
                 : "=r"(r0), "=r"(r1), "=r"(r2), "=r"(r3) : "r"(addr));
}
__device__ __forceinline__ void mma_bf16(float* c, unsigned a0, unsigned a1, unsigned a2, unsigned a3,
                                         unsigned b0, unsigned b1) {
    asm volatile("mma.sync.aligned.m16n8k16.row.col.f32.bf16.bf16.f32 "
                 "{%0,%1,%2,%3},{%4,%5,%6,%7},{%8,%9},{%0,%1,%2,%3};"
                 : "+f"(c[0]), "+f"(c[1]), "+f"(c[2]), "+f"(c[3])
                 : "r"(a0), "r"(a1), "r"(a2), "r"(a3), "r"(b0), "r"(b1));
}
__device__ __forceinline__ void mma_f16(float* c, unsigned a0, unsigned a1, unsigned a2, unsigned a3,
                                        unsigned b0, unsigned b1) {
    asm volatile("mma.sync.aligned.m16n8k16.row.col.f32.f16.f16.f32 "
                 "{%0,%1,%2,%3},{%4,%5,%6,%7},{%8,%9},{%0,%1,%2,%3};"
                 : "+f"(c[0]), "+f"(c[1]), "+f"(c[2]), "+f"(c[3])
                 : "r"(a0), "r"(a1), "r"(a2), "r"(a3), "r"(b0), "r"(b1));
}
__device__ __forceinline__ void cpa16(unsigned dst, const void* src) {
    asm volatile("cp.async.cg.shared.global [%0],[%1],16;" :: "r"(dst), "l"(src));
}
#define CPA_COMMIT asm volatile("cp.async.commit_group;")
#define CPA_WAIT1  asm volatile("cp.async.wait_group 1;")

// expm1 on [0,1]: degree-8 Taylor
__device__ __forceinline__ float em1p(float x) {
    float t = fmaf(x, 0.125f, 1.f);
    t = fmaf(x * 0.14285714f, t, 1.f);
    t = fmaf(x * 0.16666667f, t, 1.f);
    t = fmaf(x * 0.2f,        t, 1.f);
    t = fmaf(x * 0.25f,       t, 1.f);
    t = fmaf(x * 0.33333333f, t, 1.f);
    t = fmaf(x * 0.5f,        t, 1.f);
    return x * t;
}

// ---------------- zero rowsum + wtot ----------------
__global__ void zero_misc() {
    int i = blockIdx.x * 256 + threadIdx.x;
    if (i < BHn * Tn) g_rowsum[i] = 0.f;
    if (i < BHn * HDn) g_wtot[i] = 0.f;
}

// ---------------- LayerNorm -> bf16 hi/lo, stride KA_LN ----------------
__global__ void ln_bf(const float* __restrict__ x, const float* __restrict__ t,
                      const float* __restrict__ w, const float* __restrict__ bb,
                      __nv_bfloat16* __restrict__ oh, __nv_bfloat16* __restrict__ ol) {
    int row = blockIdx.x;
    int tid = threadIdx.x;
    __shared__ float sx[C1];
    __shared__ float red[256];
    float s1 = 0.f;
    for (int c = tid; c < C1; c += 256) {
        float v = (c < Cn) ? x[(size_t)row * Cn + c] : t[0];
        sx[c] = v;
        s1 += v;
    }
    red[tid] = s1; __syncthreads();
    for (int o = 128; o > 0; o >>= 1) { if (tid < o) red[tid] += red[tid + o]; __syncthreads(); }
    float mean = red[0] * (1.f / C1);
    __syncthreads();
    float s2 = 0.f;
    for (int c = tid; c < C1; c += 256) { float d = sx[c] - mean; s2 += d * d; }
    red[tid] = s2; __syncthreads();
    for (int o = 128; o > 0; o >>= 1) { if (tid < o) red[tid] += red[tid + o]; __syncthreads(); }
    float rs = rsqrtf(red[0] * (1.f / C1) + 1e-5f);
    for (int c = tid; c < C1; c += 256) {
        float v = (sx[c] - mean) * rs * w[c] + bb[c];
        __nv_bfloat16 hi = __float2bfloat16(v);
        oh[(size_t)row * KA_LN + c] = hi;
        ol[(size_t)row * KA_LN + c] = __float2bfloat16(v - __bfloat162float(hi));
    }
    if (tid < KA_LN - C1) {
        oh[(size_t)row * KA_LN + C1 + tid] = __float2bfloat16(0.f);
        ol[(size_t)row * KA_LN + C1 + tid] = __float2bfloat16(0.f);
    }
}

// ---------------- fp32 -> bf16 hi/lo (contiguous) ----------------
__global__ void conv_a(const float* __restrict__ src, __nv_bfloat16* __restrict__ oh,
                       __nv_bfloat16* __restrict__ ol, int count4) {
    int idx = blockIdx.x * 256 + threadIdx.x;
    if (idx >= count4) return;
    float4 v = ((const float4*)src)[idx];
    __nv_bfloat16 h0 = __float2bfloat16(v.x), h1 = __float2bfloat16(v.y);
    __nv_bfloat16 h2 = __float2bfloat16(v.z), h3 = __float2bfloat16(v.w);
    __nv_bfloat16 hbuf[4] = {h0, h1, h2, h3};
    __nv_bfloat16 lbuf[4] = {
        __float2bfloat16(v.x - __bfloat162float(h0)), __float2bfloat16(v.y - __bfloat162float(h1)),
        __float2bfloat16(v.z - __bfloat162float(h2)), __float2bfloat16(v.w - __bfloat162float(h3))};
    *(uint2*)(oh + (size_t)idx * 4) = *(uint2*)hbuf;
    *(uint2*)(ol + (size_t)idx * 4) = *(uint2*)lbuf;
}

// ---------------- weight fp32 KxN -> bf16 hi/lo KaxN ----------------
__global__ void conv_b(const float* __restrict__ w, __nv_bfloat16* __restrict__ oh,
                       __nv_bfloat16* __restrict__ ol, int K, int Ka, int N) {
    int idx = blockIdx.x * 256 + threadIdx.x;
    if (idx * 4 >= Ka * N) return;
    int row = (idx * 4) / N;
    float4 v = (row < K) ? ((const float4*)w)[idx] : make_float4(0.f, 0.f, 0.f, 0.f);
    __nv_bfloat16 h0 = __float2bfloat16(v.x), h1 = __float2bfloat16(v.y);
    __nv_bfloat16 h2 = __float2bfloat16(v.z), h3 = __float2bfloat16(v.w);
    __nv_bfloat16 hbuf[4] = {h0, h1, h2, h3};
    __nv_bfloat16 lbuf[4] = {
        __float2bfloat16(v.x - __bfloat162float(h0)), __float2bfloat16(v.y - __bfloat162float(h1)),
        __float2bfloat16(v.z - __bfloat162float(h2)), __float2bfloat16(v.w - __bfloat162float(h3))};
    *(uint2*)(oh + (size_t)idx * 4) = *(uint2*)hbuf;
    *(uint2*)(ol + (size_t)idx * 4) = *(uint2*)lbuf;
}

// ---------------- pipelined bf16 GEMM ----------------
// obf=0: fp32 out. obf=1: gelu + bf16 hi/lo out. obf=2: fp32 out + q/k bf16 split (qkv gemm).
__global__ void __launch_bounds__(256) gemm_bf(const __nv_bfloat16* __restrict__ Ah,
                                               const __nv_bfloat16* __restrict__ Al,
                                               const __nv_bfloat16* __restrict__ Bh,
                                               const __nv_bfloat16* __restrict__ Bl,
                                               const float* __restrict__ bias,
                                               float* __restrict__ outF,
                                               __nv_bfloat16* __restrict__ oAh,
                                               __nv_bfloat16* __restrict__ oAl,
                                               int M, int N, int Ka, int act, int obf) {
    extern __shared__ __nv_bfloat16 dyn[];
    __nv_bfloat16* sA = dyn;
    __nv_bfloat16* sB = dyn + 4 * 5120;
    int tid = threadIdx.x;
    int wid = tid >> 5, lane = tid & 31;
    int wm = wid & 3, wn = wid >> 2;
    int bm = blockIdx.y * 128, bn = blockIdx.x * 128;
    float acc[2][8][4] = {};
    unsigned sAu = (unsigned)__cvta_generic_to_shared(sA);
    unsigned sBu = (unsigned)__cvta_generic_to_shared(sB);

    int nk = Ka >> 5;
    auto load_stage = [&](int kt, int st) {
        unsigned aH = sAu + (st * 2 + 0) * 5120 * 2;
        unsigned aL = sAu + (st * 2 + 1) * 5120 * 2;
        unsigned bH = sBu + (st * 2 + 0) * 4352 * 2;
        unsigned bL = sBu + (st * 2 + 1) * 4352 * 2;
        int k0 = kt * 32;
        #pragma unroll
        for (int z = 0; z < 2; z++) {
            int idx = z * 256 + tid;
            int row = idx >> 2, cq = (idx & 3) * 8;
            cpa16(aH + (row * 40 + cq) * 2, Ah + (size_t)(bm + row) * Ka + k0 + cq);
            cpa16(aL + (row * 40 + cq) * 2, Al + (size_t)(bm + row) * Ka + k0 + cq);
        }
        #pragma unroll
        for (int z = 0; z < 2; z++) {
            int idx = z * 256 + tid;
            int row = idx >> 4, cq = (idx & 15) * 8;
            cpa16(bH + (row * 136 + cq) * 2, Bh + (size_t)(k0 + row) * N + bn + cq);
            cpa16(bL + (row * 136 + cq) * 2, Bl + (size_t)(k0 + row) * N + bn + cq);
        }
    };

    load_stage(0, 0);
    CPA_COMMIT;
    for (int kt = 0; kt < nk; kt++) {
        int cur = kt & 1;
        if (kt + 1 < nk) load_stage(kt + 1, cur ^ 1);
        CPA_COMMIT;
        CPA_WAIT1;
        __syncthreads();
        unsigned aH = sAu + (cur * 2 + 0) * 5120 * 2;
        unsigned aL = sAu + (cur * 2 + 1) * 5120 * 2;
        unsigned bH = sBu + (cur * 2 + 0) * 4352 * 2;
        unsigned bL = sBu + (cur * 2 + 1) * 4352 * 2;
        #pragma unroll
        for (int kh = 0; kh < 32; kh += 16) {
            unsigned ah[2][4], al[2][4];
            #pragma unroll
            for (int mt = 0; mt < 2; mt++) {
                unsigned off = ((unsigned)((wm * 32 + mt * 16 + (lane & 15)) * 40 + kh + (lane >> 4) * 8)) * 2;
                ldmx4(aH + off, ah[mt][0], ah[mt][1], ah[mt][2], ah[mt][3]);
                ldmx4(aL + off, al[mt][0], al[mt][1], al[mt][2], al[mt][3]);
            }
            #pragma unroll
            for (int np = 0; np < 4; np++) {
                int n0 = wn * 64 + np * 16;
                unsigned boff = ((unsigned)((kh + (lane & 7) + 8 * ((lane >> 3) & 1)) * 136 + n0 + 8 * (lane >> 4))) * 2;
                unsigned bh0, bh1, bh2, bh3, bl0, bl1, bl2, bl3;
                ldmx4t(bH + boff, bh0, bh1, bh2, bh3);
                ldmx4t(bL + boff, bl0, bl1, bl2, bl3);
                #pragma unroll
                for (int mt = 0; mt < 2; mt++) {
                    mma_bf16(acc[mt][2 * np],     ah[mt][0], ah[mt][1], ah[mt][2], ah[mt][3], bh0, bh1);
                    mma_bf16(acc[mt][2 * np],     ah[mt][0], ah[mt][1], ah[mt][2], ah[mt][3], bl0, bl1);
                    mma_bf16(acc[mt][2 * np],     al[mt][0], al[mt][1], al[mt][2], al[mt][3], bh0, bh1);
                    mma_bf16(acc[mt][2 * np + 1], ah[mt][0], ah[mt][1], ah[mt][2], ah[mt][3], bh2, bh3);
                    mma_bf16(acc[mt][2 * np + 1], ah[mt][0], ah[mt][1], ah[mt][2], ah[mt][3], bl2, bl3);
                    mma_bf16(acc[mt][2 * np + 1], al[mt][0], al[mt][1], al[mt][2], al[mt][3], bh2, bh3);
                }
            }
        }
        __syncthreads();
    }
    #pragma unroll
    for (int mt = 0; mt < 2; mt++) {
        #pragma unroll
        for (int nt = 0; nt < 8; nt++) {
            float* cc = acc[mt][nt];
            int r = bm + wm * 32 + mt * 16 + (lane >> 2);
            int cn = bn + wn * 64 + nt * 8 + (lane & 3) * 2;
            float b0 = bias[cn], b1 = bias[cn + 1];
            float v0 = cc[0] + b0, v1 = cc[1] + b1;
            float v2 = cc[2] + b0, v3 = cc[3] + b1;
            if (act == 1) {
                v0 = 0.5f * v0 * (1.f + erff(v0 * 0.70710678f));
                v1 = 0.5f * v1 * (1.f + erff(v1 * 0.70710678f));
                v2 = 0.5f * v2 * (1.f + erff(v2 * 0.70710678f));
                v3 = 0.5f * v3 * (1.f + erff(v3 * 0.70710678f));
            }
            if (obf == 1) {
                __nv_bfloat16 h0 = __float2bfloat16(v0), h1 = __float2bfloat16(v1);
                __nv_bfloat16 h2 = __float2bfloat16(v2), h3 = __float2bfloat16(v3);
                oAh[(size_t)r * N + cn] = h0;
                oAh[(size_t)r * N + cn + 1] = h1;
                oAh[(size_t)(r + 8) * N + cn] = h2;
                oAh[(size_t)(r + 8) * N + cn + 1] = h3;
                oAl[(size_t)r * N + cn] = __float2bfloat16(v0 - __bfloat162float(h0));
                oAl[(size_t)r * N + cn + 1] = __float2bfloat16(v1 - __bfloat162float(h1));
                oAl[(size_t)(r + 8) * N + cn] = __float2bfloat16(v2 - __bfloat162float(h2));
                oAl[(size_t)(r + 8) * N + cn + 1] = __float2bfloat16(v3 - __bfloat162float(h3));
            } else {
                outF[(size_t)r * N + cn] = v0;
                outF[(size_t)r * N + cn + 1] = v1;
                outF[(size_t)(r + 8) * N + cn] = v2;
                outF[(size_t)(r + 8) * N + cn + 1] = v3;
                if (obf == 2 && cn < 2 * Cn) {
                    int isK = cn >= Cn;
                    int c2 = cn - isK * Cn;
                    __nv_bfloat16* H = isK ? g_kh : g_qh;
                    __nv_bfloat16* L = isK ? g_kl : g_ql;
                    __nv_bfloat16 h0 = __float2bfloat16(v0), h1 = __float2bfloat16(v1);
                    __nv_bfloat16 h2 = __float2bfloat16(v2), h3 = __float2bfloat16(v3);
                    H[(size_t)r * Cn + c2] = h0;
                    H[(size_t)r * Cn + c2 + 1] = h1;
                    H[(size_t)(r + 8) * Cn + c2] = h2;
                    H[(size_t)(r + 8) * Cn + c2 + 1] = h3;
                    L[(size_t)r * Cn + c2] = __float2bfloat16(v0 - __bfloat162float(h0));
                    L[(size_t)r * Cn + c2 + 1] = __float2bfloat16(v1 - __bfloat162float(h1));
                    L[(size_t)(r + 8) * Cn + c2] = __float2bfloat16(v2 - __bfloat162float(h2));
                    L[(size_t)(r + 8) * Cn + c2 + 1] = __float2bfloat16(v3 - __bfloat162float(h3));
                }
            }
        }
    }
}

// ---------------- TC scores + fused exp (fp16) + inline row sums ----------------
__global__ void __launch_bounds__(256) score_tc() {
    int jt = blockIdx.x, it = blockIdx.y, bh = blockIdx.z;
    if (jt > it) return;
    int b = bh / Hn, h = bh % Hn;
    __shared__ __nv_bfloat16 sQh[128][40], sQl[128][40], sKh[128][40], sKl[128][40];
    int tid = threadIdx.x, wid = tid >> 5, lane = tid & 31;
    int wm = wid & 3, wn = wid >> 2;
    float acc[2][8][4] = {};
    unsigned aQh = (unsigned)__cvta_generic_to_shared(&sQh[0][0]);
    unsigned aQl = (unsigned)__cvta_generic_to_shared(&sQl[0][0]);
    unsigned aKh = (unsigned)__cvta_generic_to_shared(&sKh[0][0]);
    unsigned aKl = (unsigned)__cvta_generic_to_shared(&sKl[0][0]);
    size_t qbase = ((size_t)(b * Tn + it * 128)) * Cn + h * HDn;
    size_t kbase = ((size_t)(b * Tn + jt * 128)) * Cn + h * HDn;

    for (int ks = 0; ks < 2; ks++) {
        if (ks) __syncthreads();
        #pragma unroll
        for (int z = 0; z < 2; z++) {
            int idx = z * 256 + tid;
            int r = idx >> 2, c8 = (idx & 3) * 8;
            *(uint4*)&sQh[r][c8] = *(const uint4*)(g_qh + qbase + (size_t)r * Cn + ks * 32 + c8);
            *(uint4*)&sQl[r][c8] = *(const uint4*)(g_ql + qbase + (size_t)r * Cn + ks * 32 + c8);
            *(uint4*)&sKh[r][c8] = *(const uint4*)(g_kh + kbase + (size_t)r * Cn + ks * 32 + c8);
            *(uint4*)&sKl[r][c8] = *(const uint4*)(g_kl + kbase + (size_t)r * Cn + ks * 32 + c8);
        }
        __syncthreads();
        #pragma unroll
        for (int kh = 0; kh < 32; kh += 16) {
            unsigned qh_[2][4], ql_[2][4];
            #pragma unroll
            for (int mt = 0; mt < 2; mt++) {
                unsigned off = ((unsigned)((wm * 32 + mt * 16 + (lane & 15)) * 40 + kh + 8 * (lane >> 4))) * 2;
                ldmx4(aQh + off, qh_[mt][0], qh_[mt][1], qh_[mt][2], qh_[mt][3]);
                ldmx4(aQl + off, ql_[mt][0], ql_[mt][1], ql_[mt][2], ql_[mt][3]);
            }
            #pragma unroll
            for (int nq = 0; nq < 4; nq++) {
                int n0 = wn * 64 + nq * 16;
                unsigned boff = ((unsigned)((n0 + (lane & 15)) * 40 + kh + 8 * (lane >> 4))) * 2;
                unsigned kh0, kh1, kh2, kh3, kl0, kl1, kl2, kl3;
                ldmx4(aKh + boff, kh0, kh1, kh2, kh3);
                ldmx4(aKl + boff, kl0, kl1, kl2, kl3);
                #pragma unroll
                for (int mt = 0; mt < 2; mt++) {
                    mma_bf16(acc[mt][2 * nq],     qh_[mt][0], qh_[mt][1], qh_[mt][2], qh_[mt][3], kh0, kh2);
                    mma_bf16(acc[mt][2 * nq],     qh_[mt][0], qh_[mt][1], qh_[mt][2], qh_[mt][3], kl0, kl2);
                    mma_bf16(acc[mt][2 * nq],     ql_[mt][0], ql_[mt][1], ql_[mt][2], ql_[mt][3], kh0, kh2);
                    mma_bf16(acc[mt][2 * nq + 1], qh_[mt][0], qh_[mt][1], qh_[mt][2], qh_[mt][3], kh1, kh3);
                    mma_bf16(acc[mt][2 * nq + 1], qh_[mt][0], qh_[mt][1], qh_[mt][2], qh_[mt][3], kl1, kl3);
                    mma_bf16(acc[mt][2 * nq + 1], ql_[mt][0], ql_[mt][1], ql_[mt][2], ql_[mt][3], kh1, kh3);
                }
            }
        }
    }
    __half* erow = g_e + (size_t)bh * Tn * Tn;
    float rsum[2][2] = {};
    int diag = (it == jt);
    #pragma unroll
    for (int mt = 0; mt < 2; mt++) {
        #pragma unroll
        for (int f = 0; f < 8; f++) {
            float* cc = acc[mt][f];
            int gi = it * 128 + wm * 32 + mt * 16 + (lane >> 2);
            int gj = jt * 128 + wn * 64 + (f >> 1) * 16 + (f & 1) * 8 + 2 * (lane & 3);
            float e0 = __expf(fminf(cc[0] * 0.125f, 11.f));
            float e1 = __expf(fminf(cc[1] * 0.125f, 11.f));
            float e2 = __expf(fminf(cc[2] * 0.125f, 11.f));
            float e3 = __expf(fminf(cc[3] * 0.125f, 11.f));
            if (diag) {
                if (gj > gi) e0 = 0.f;
                if (gj + 1 > gi) e1 = 0.f;
                if (gj > gi + 8) e2 = 0.f;
                if (gj + 1 > gi + 8) e3 = 0.f;
            }
            rsum[mt][0] += e0 + e1;
            rsum[mt][1] += e2 + e3;
            *(__half2*)(erow + (size_t)gi * Tn + gj) = __floats2half2_rn(e0, e1);
            *(__half2*)(erow + (size_t)(gi + 8) * Tn + gj) = __floats2half2_rn(e2, e3);
        }
    }
    #pragma unroll
    for (int mt = 0; mt < 2; mt++) {
        #pragma unroll
        for (int hh = 0; hh < 2; hh++) {
            float v = rsum[mt][hh];
            v += __shfl_xor_sync(0xffffffffu, v, 1);
            v += __shfl_xor_sync(0xffffffffu, v, 2);
            if ((lane & 3) == 0) {
                int gi = it * 128 + wm * 32 + mt * 16 + (lane >> 2) + hh * 8;
                atomicAdd(&g_rowsum[bh * Tn + gi], v);
            }
        }
    }
}

// ---------------- per row: Em1 = expm1(e/rowsum), single sweep; u1, eu ----------------
__global__ void em1_row() {
    int i = blockIdx.x, bh = blockIdx.y;
    int tid = threadIdx.x;
    int lane = tid & 31, wid = tid >> 5;
    float inv = 1.f / g_rowsum[bh * Tn + i];
    const uint4* src = (const uint4*)(g_e + ((size_t)bh * Tn + i) * Tn);
    uint4* dst = (uint4*)(g_c + ((size_t)bh * Tn + i) * Tn);
    int nv = ((i >> 7) + 1) << 4;   // uint4 count to 128-boundary
    float se = 0.f;
    if (tid < nv) {
        uint4 pk = src[tid];
        const __half2* hp = (const __half2*)&pk;
        uint4 outp;
        __half2* op = (__half2*)&outp;
        #pragma unroll
        for (int z = 0; z < 4; z++) {
            float2 f = __half22float2(hp[z]);
            float a = em1p(f.x * inv);
            float bb = em1p(f.y * inv);
            se += a + bb;
            op[z] = __floats2half2_rn(a, bb);
        }
        dst[tid] = outp;
    }
    se += __shfl_xor_sync(0xffffffffu, se, 16);
    se += __shfl_xor_sync(0xffffffffu, se, 8);
    se += __shfl_xor_sync(0xffffffffu, se, 4);
    se += __shfl_xor_sync(0xffffffffu, se, 2);
    se += __shfl_xor_sync(0xffffffffu, se, 1);
    __shared__ float red[8];
    if (lane == 0) red[wid] = se;
    __syncthreads();
    if (tid == 0) {
        float s = red[0] + red[1] + red[2] + red[3] + red[4] + red[5] + red[6] + red[7];
        g_eu[bh * Tn + i] = __expf(-LOGT - __logf(s + (float)Tn));
    }
}

// ---------------- per-bh totals ----------------
__global__ void tot_kernel(const float* __restrict__ vec, float* __restrict__ tot) {
    int bh = blockIdx.x, tid = threadIdx.x;
    __shared__ float red[256];
    float s = 0.f;
    for (int i = tid; i < Tn; i += 256) s += vec[bh * Tn + i];
    red[tid] = s; __syncthreads();
    for (int o = 128; o > 0; o >>= 1) { if (tid < o) red[tid] += red[tid + o]; __syncthreads(); }
    if (tid == 0) tot[bh] = red[0];
}

// ---------------- Sinkhorn row pass ----------------
__global__ void sink_row_f() {
    int r0 = blockIdx.x * 8, bh = blockIdx.y;
    int tid = threadIdx.x;
    __shared__ float sev[Tn];
    __shared__ float red[256];
    int jmax = r0 + 8;
    for (int j = tid; j < jmax; j += 256) sev[j] = g_ev[bh * Tn + j];
    float evtot = g_evtot[bh];
    __syncthreads();
    for (int r = 0; r < 8; r++) {
        int i = r0 + r;
        const uint4* cv = (const uint4*)(g_c + ((size_t)bh * Tn + i) * Tn);
        int nv = (i + 8) >> 3;
        float s = 0.f;
        for (int vi = tid; vi < nv; vi += 256) {
            uint4 pk = cv[vi];
            const __half2* hp = (const __half2*)&pk;
            int jb = vi * 8;
            #pragma unroll
            for (int z = 0; z < 4; z++) {
                float2 f = __half22float2(hp[z]);
                s += f.x * sev[jb + 2 * z] + f.y * sev[jb + 2 * z + 1];
            }
        }
        red[tid] = s; __syncthreads();
        for (int o = 128; o > 0; o >>= 1) { if (tid < o) red[tid] += red[tid + o]; __syncthreads(); }
        if (tid == 0)
            g_eu[bh * Tn + i] = __expf(-LOGT - __logf(red[0] + evtot));
        __syncthreads();
    }
}

// ---------------- Sinkhorn col pass: partial over i-chunks ----------------
__global__ void sink_col_part() {
    int cb = blockIdx.x;    // 512-col block
    int ic = blockIdx.y;    // 256-row chunk
    int bh = blockIdx.z;
    int tid = threadIdx.x;
    int j0 = cb * 512 + tid * 2;
    int is = ic * 256;
    float* part = g_cpart + (size_t)(ic * BHn + bh) * Tn;
    if (cb * 512 >= is + 256) {   // entirely above diagonal: Em1 region all zero
        part[j0] = 0.f;
        part[j0 + 1] = 0.f;
        return;
    }
    __shared__ float seu[256];
    seu[tid] = g_eu[bh * Tn + is + tid];
    __syncthreads();
    const __half* base = g_c + (size_t)bh * Tn * Tn + j0;
    float s0 = 0.f, s1 = 0.f;
    #pragma unroll 4
    for (int r = 0; r < 256; r++) {
        __half2 hh = *(const __half2*)(base + (size_t)(is + r) * Tn);
        float2 f = __half22float2(hh);
        float ui = seu[r];
        s0 += f.x * ui;
        s1 += f.y * ui;
    }
    part[j0] = s0;
    part[j0 + 1] = s1;
}

__global__ void sink_col_fin() {
    int bh = blockIdx.y;
    int j = blockIdx.x * 256 + threadIdx.x;
    float s = 0.f;
    #pragma unroll
    for (int ic = 0; ic < 8; ic++)
        s += g_cpart[(size_t)(ic * BHn + bh) * Tn + j];
    g_ev[bh * Tn + j] = __expf(-LOGT - __logf(s + g_eutot[bh]));
}

// ---------------- W = ev*V*512 -> fp16 hi/lo; Wtot ----------------
__global__ void w_kernel() {
    int jt = blockIdx.x, bh = blockIdx.y;
    int b = bh / Hn, h = bh % Hn;
    int tid = threadIdx.x;
    int d = tid & 63, r0 = tid >> 6;
    float part = 0.f;
    for (int r = r0; r < 128; r += 4) {
        int j = jt * 128 + r;
        float ev = g_ev[bh * Tn + j];
        float v = g_qkv[((size_t)(b * Tn + j)) * N3 + 2 * Cn + h * HDn + d];
        float w = ev * v;
        part += w;
        float ws = fminf(fmaxf(w * WSCALE, -32768.f), 32768.f);
        __half hi = __float2half(ws);
        g_wh[((size_t)bh * Tn + j) * HDn + d] = hi;
        g_wl[((size_t)bh * Tn + j) * HDn + d] = __float2half(ws - __half2float(hi));
    }
    __shared__ float red[256];
    red[tid] = part; __syncthreads();
    if (tid < 128) red[tid] += red[tid + 128];
    __syncthreads();
    if (tid < 64) atomicAdd(&g_wtot[bh * HDn + tid], red[tid] + red[tid + 64]);
}

// ---------------- pi@V via fp16 TC ----------------
__global__ void __launch_bounds__(256) pi_v_tc() {
    int bh = blockIdx.y;
    int b = bh / Hn, h = bh % Hn;
    int it = gridDim.x - 1 - blockIdx.x;
    int i0 = it * 128;
    __shared__ __half sA[128][72];
    __shared__ __half sWh[64][72], sWl[64][72];
    int tid = threadIdx.x, wid = tid >> 5, lane = tid & 31;
    int wm = wid & 3, wn = wid >> 2;
    float acc[2][4][4] = {};
    unsigned aA = (unsigned)__cvta_generic_to_shared(&sA[0][0]);
    unsigned aWh = (unsigned)__cvta_generic_to_shared(&sWh[0][0]);
    unsigned aWl = (unsigned)__cvta_generic_to_shared(&sWl[0][0]);

    for (int jc = 0; jc < i0 + 128; jc += 64) {
        if (jc) __syncthreads();
        #pragma unroll
        for (int z = 0; z < 4; z++) {
            int idx = z * 256 + tid;
            int r = idx >> 3, c8 = (idx & 7) * 8;
            *(uint4*)&sA[r][c8] = *(const uint4*)(g_c + ((size_t)bh * Tn + i0 + r) * Tn + jc + c8);
        }
        #pragma unroll
        for (int z = 0; z < 2; z++) {
            int idx = z * 256 + tid;
            int r = idx >> 3, c8 = (idx & 7) * 8;
            *(uint4*)&sWh[r][c8] = *(const uint4*)(g_wh + ((size_t)bh * Tn + jc + r) * HDn + c8);
            *(uint4*)&sWl[r][c8] = *(const uint4*)(g_wl + ((size_t)bh * Tn + jc + r) * HDn + c8);
        }
        __syncthreads();
        #pragma unroll
        for (int kh = 0; kh < 64; kh += 16) {
            unsigned a_[2][4];
            #pragma unroll
            for (int mt = 0; mt < 2; mt++) {
                unsigned off = ((unsigned)((wm * 32 + mt * 16 + (lane & 15)) * 72 + kh + 8 * (lane >> 4))) * 2;
                ldmx4(aA + off, a_[mt][0], a_[mt][1], a_[mt][2], a_[mt][3]);
            }
            #pragma unroll
            for (int nq = 0; nq < 2; nq++) {
                int n0 = wn * 32 + nq * 16;
                unsigned boff = ((unsigned)((kh + (lane & 7) + 8 * ((lane >> 3) & 1)) * 72 + n0 + 8 * (lane >> 4))) * 2;
                unsigned bh0, bh1, bh2, bh3, bl0, bl1, bl2, bl3;
                ldmx4t(aWh + boff, bh0, bh1, bh2, bh3);
                ldmx4t(aWl + boff, bl0, bl1, bl2, bl3);
                #pragma unroll
                for (int mt = 0; mt < 2; mt++) {
                    mma_f16(acc[mt][2 * nq],     a_[mt][0], a_[mt][1], a_[mt][2], a_[mt][3], bh0, bh1);
                    mma_f16(acc[mt][2 * nq],     a_[mt][0], a_[mt][1], a_[mt][2], a_[mt][3], bl0, bl1);
                    mma_f16(acc[mt][2 * nq + 1], a_[mt][0], a_[mt][1], a_[mt][2], a_[mt][3], bh2, bh3);
                    mma_f16(acc[mt][2 * nq + 1], a_[mt][0], a_[mt][1], a_[mt][2], a_[mt][3], bl2, bl3);
                }
            }
        }
    }
    #pragma unroll
    for (int mt = 0; mt < 2; mt++) {
        #pragma unroll
        for (int f = 0; f < 4; f++) {
            float* cc = acc[mt][f];
            int r = i0 + wm * 32 + mt * 16 + (lane >> 2);
            int d = wn * 32 + f * 8 + 2 * (lane & 3);
            float wt0 = g_wtot[bh * HDn + d], wt1 = g_wtot[bh * HDn + d + 1];
            float eu0 = g_eu[bh * Tn + r] * 2048.f;
            float eu1 = g_eu[bh * Tn + r + 8] * 2048.f;
            size_t base = ((size_t)(b * Tn) + r) * Cn + h * HDn + d;
            g_y[base]     = (cc[0] * WINV + wt0) * eu0;
            g_y[base + 1] = (cc[1] * WINV + wt1) * eu0;
            g_y[base + (size_t)8 * Cn]     = (cc[2] * WINV + wt0) * eu1;
            g_y[base + (size_t)8 * Cn + 1] = (cc[3] * WINV + wt1) * eu1;
        }
    }
}

// ---------------- launch ----------------
extern "C" void kernel_launch(void* const* d_in, const int* in_sizes, int n_in,
                              void* d_out, int out_size) {
    const float* x      = (const float*)d_in[0];
    const float* t      = (const float*)d_in[1];
    const float* ln1_w  = (const float*)d_in[2];
    const float* ln1_b  = (const float*)d_in[3];
    const float* attn_w = (const float*)d_in[4];
    const float* attn_b = (const float*)d_in[5];
    const float* proj_w = (const float*)d_in[6];
    const float* proj_b = (const float*)d_in[7];
    const float* ln2_w  = (const float*)d_in[8];
    const float* ln2_b  = (const float*)d_in[9];
    const float* fc_w   = (const float*)d_in[10];
    const float* fc_b   = (const float*)d_in[11];
    const float* fc2_w  = (const float*)d_in[12];
    const float* fc2_b  = (const float*)d_in[13];
    float* out = (float*)d_out;

    float *p_qkv, *p_y, *p_h, *p_eu, *p_ev, *p_eutot, *p_evtot;
    __nv_bfloat16 *p_ah, *p_al, *p_a2h, *p_a2l, *p_bh, *p_bl;
    cudaGetSymbolAddress((void**)&p_qkv, g_qkv);
    cudaGetSymbolAddress((void**)&p_y,   g_y);
    cudaGetSymbolAddress((void**)&p_h,   g_h);
    cudaGetSymbolAddress((void**)&p_eu,  g_eu);
    cudaGetSymbolAddress((void**)&p_ev,  g_ev);
    cudaGetSymbolAddress((void**)&p_eutot, g_eutot);
    cudaGetSymbolAddress((void**)&p_evtot, g_evtot);
    cudaGetSymbolAddress((void**)&p_ah,  g_ah);
    cudaGetSymbolAddress((void**)&p_al,  g_al);
    cudaGetSymbolAddress((void**)&p_a2h, g_a2h);
    cudaGetSymbolAddress((void**)&p_a2l, g_a2l);
    cudaGetSymbolAddress((void**)&p_bh,  g_bh);
    cudaGetSymbolAddress((void**)&p_bl,  g_bl);

    static int smem_set = 0;
    const int GSM = 75776;
    if (!smem_set) {
        cudaFuncSetAttribute(gemm_bf, cudaFuncAttributeMaxDynamicSharedMemorySize, GSM);
        smem_set = 1;
    }

    // ---- attention sub-block ----
    zero_misc<<<96, 256>>>();
    ln_bf<<<ROWS, 256>>>(x, t, ln1_w, ln1_b, p_ah, p_al);
    conv_b<<<(KA_LN * N3 / 4 + 255) / 256, 256>>>(attn_w, p_bh, p_bl, C1, KA_LN, N3);
    gemm_bf<<<dim3(N3 / 128, ROWS / 128), 256, GSM>>>(p_ah, p_al, p_bh, p_bl, attn_b,
                                                      p_qkv, nullptr, nullptr, ROWS, N3, KA_LN, 0, 2);
    score_tc<<<dim3(Tn / 128, Tn / 128, BHn), 256>>>();
    em1_row<<<dim3(Tn, BHn), 256>>>();
    tot_kernel<<<BHn, 256>>>(p_eu, p_eutot);

    // sinkhorn remaining 5 passes: col,row,col,row,col
    sink_col_part<<<dim3(4, 8, BHn), 256>>>();
    sink_col_fin<<<dim3(8, BHn), 256>>>();
    tot_kernel<<<BHn, 256>>>(p_ev, p_evtot);
    sink_row_f<<<dim3(Tn / 8, BHn), 256>>>();
    tot_kernel<<<BHn, 256>>>(p_eu, p_eutot);
    sink_col_part<<<dim3(4, 8, BHn), 256>>>();
    sink_col_fin<<<dim3(8, BHn), 256>>>();
    tot_kernel<<<BHn, 256>>>(p_ev, p_evtot);
    sink_row_f<<<dim3(Tn / 8, BHn), 256>>>();
    tot_kernel<<<BHn, 256>>>(p_eu, p_eutot);
    sink_col_part<<<dim3(4, 8, BHn), 256>>>();
    sink_col_fin<<<dim3(8, BHn), 256>>>();

    w_kernel<<<dim3(Tn / 128, BHn), 256>>>();
    pi_v_tc<<<dim3(Tn / 128, BHn), 256>>>();

    // proj
    conv_a<<<(ROWS * Cn / 4 + 255) / 256, 256>>>(p_y, p_ah, p_al, ROWS * Cn / 4);
    conv_b<<<(Cn * Cn / 4 + 255) / 256, 256>>>(proj_w, p_bh, p_bl, Cn, Cn, Cn);
    gemm_bf<<<dim3(Cn / 128, ROWS / 128), 256, GSM>>>(p_ah, p_al, p_bh, p_bl, proj_b,
                                                      p_h, nullptr, nullptr, ROWS, Cn, Cn, 0, 0);

    // ---- MLP sub-block ----
    ln_bf<<<ROWS, 256>>>(p_h, t, ln2_w, ln2_b, p_ah, p_al);
    conv_b<<<(KA_LN * N4 / 4 + 255) / 256, 256>>>(fc_w, p_bh, p_bl, C1, KA_LN, N4);
    gemm_bf<<<dim3(N4 / 128, ROWS / 128), 256, GSM>>>(p_ah, p_al, p_bh, p_bl, fc_b,
                                                      nullptr, p_a2h, p_a2l, ROWS, N4, KA_LN, 1, 1);
    conv_b<<<(N4 * Cn / 4 + 255) / 256, 256>>>(fc2_w, p_bh, p_bl, N4, N4, Cn);
    gemm_bf<<<dim3(Cn / 128, ROWS / 128), 256, GSM>>>(p_a2h, p_a2l, p_bh, p_bl, fc2_b,
                                                      out, nullptr, nullptr, ROWS, Cn, N4, 0, 0);
}

// round 10
// speedup vs baseline: 5.7479x; 1.0376x over previous
#include <cuda_runtime.h>
#include <cuda_fp16.h>
#include <cuda_bf16.h>
#include <math.h>

#define Tn 2048
#define Cn 384
#define Hn 6
#define HDn 64
#define Bn 2
#define BHn 12
#define ROWS 4096      // B*T
#define C1 385         // C+1
#define KA_LN 416      // C1 padded to 32
#define N3 1152        // 3C
#define N4 1536        // 4C
#define LOGT 7.62461899f   // ln(2048)
#define WSCALE 512.f
#define WINV   (1.f / 512.f)

// weight buffer offsets (elements)
#define WOFF_QKV 0
#define WSZ_QKV  (KA_LN * N3)          // 479232
#define WOFF_PRJ (WOFF_QKV + WSZ_QKV)  // 479232
#define WSZ_PRJ  (Cn * Cn)             // 147456
#define WOFF_FC  (WOFF_PRJ + WSZ_PRJ)  // 626688
#define WSZ_FC   (KA_LN * N4)          // 638976
#define WOFF_FC2 (WOFF_FC + WSZ_FC)    // 1265664
#define WSZ_FC2  (N4 * Cn)             // 589824
#define WTOTAL   (WOFF_FC2 + WSZ_FC2)  // 1855488

// ---------------- scratch ----------------
__device__ __align__(16) float g_qkv[ROWS * N3];
__device__ __align__(16) __half g_e[(size_t)BHn * Tn * Tn];    // fp16 e=exp(score) lower tri
__device__ __align__(16) __half g_c[(size_t)BHn * Tn * Tn];    // fp16 Em1 (zero-init padding relied upon)
__device__ __align__(16) __nv_bfloat16 g_qh[ROWS * Cn];
__device__ __align__(16) __nv_bfloat16 g_ql[ROWS * Cn];
__device__ __align__(16) __nv_bfloat16 g_kh[ROWS * Cn];
__device__ __align__(16) __nv_bfloat16 g_kl[ROWS * Cn];
__device__ __align__(16) __half g_wh[BHn * Tn * HDn];
__device__ __align__(16) __half g_wl[BHn * Tn * HDn];
__device__ float g_rowsum[BHn * Tn];
__device__ float g_eu[BHn * Tn];
__device__ float g_ev[BHn * Tn];
__device__ float g_tots[8 * BHn];
__device__ float g_wtot[BHn * HDn];
__device__ __align__(16) float g_cpart[8 * BHn * Tn];
__device__ __align__(16) float g_h[ROWS * Cn];
__device__ __align__(16) __nv_bfloat16 g_ah[ROWS * N4];
__device__ __align__(16) __nv_bfloat16 g_al[ROWS * N4];
__device__ __align__(16) __nv_bfloat16 g_a2h[ROWS * N4];
__device__ __align__(16) __nv_bfloat16 g_a2l[ROWS * N4];
__device__ __align__(16) __nv_bfloat16 g_bh[WTOTAL];
__device__ __align__(16) __nv_bfloat16 g_bl[WTOTAL];

// ---------------- helpers ----------------
__device__ __forceinline__ void ldmx4(unsigned addr, unsigned& r0, unsigned& r1, unsigned& r2, unsigned& r3) {
    asm volatile("ldmatrix.sync.aligned.m8n8.x4.shared.b16 {%0,%1,%2,%3},[%4];"
                 : "=r"(r0), "=r"(r1), "=r"(r2), "=r"(r3) : "r"(addr));
}
__device__ __forceinline__ void ldmx4t(unsigned addr, unsigned& r0, unsigned& r1, unsigned& r2, unsigned& r3) {
    asm volatile("ldmatrix.sync.aligned.m8n8.x4.trans.shared.b16 {%0,%1,%2,%3},[%4];"
                 : "=r"(r0), "=r"(r1), "=r"(r2), "=r"(r3) : "r"(addr));
}
__device__ __forceinline__ void mma_bf16(float* c, unsigned a0, unsigned a1, unsigned a2, unsigned a3,
                                         unsigned b0, unsigned b1) {
    asm volatile("mma.sync.aligned.m16n8k16.row.col.f32.bf16.bf16.f32 "
                 "{%0,%1,%2,%3},{%4,%5,%6,%7},{%8,%9},{%0,%1,%2,%3};"
                 : "+f"(c[0]), "+f"(c[1]), "+f"(c[2]), "+f"(c[3])
                 : "r"(a0), "r"(a1), "r"(a2), "r"(a3), "r"(b0), "r"(b1));
}
__device__ __forceinline__ void mma_f16(float* c, unsigned a0, unsigned a1, unsigned a2, unsigned a3,
                                        unsigned b0, unsigned b1) {
    asm volatile("mma.sync.aligned.m16n8k16.row.col.f32.f16.f16.f32 "
                 "{%0,%1,%2,%3},{%4,%5,%6,%7},{%8,%9},{%0,%1,%2,%3};"
                 : "+f"(c[0]), "+f"(c[1]), "+f"(c[2]), "+f"(c[3])
                 : "r"(a0), "r"(a1), "r"(a2), "r"(a3), "r"(b0), "r"(b1));
}
__device__ __forceinline__ void cpa16(unsigned dst, const void* src) {
    asm volatile("cp.async.cg.shared.global [%0],[%1],16;" :: "r"(dst), "l"(src));
}
#define CPA_COMMIT asm volatile("cp.async.commit_group;")
#define CPA_WAIT1  asm volatile("cp.async.wait_group 1;")

// expm1 on [0,1]: degree-8 Taylor
__device__ __forceinline__ float em1p(float x) {
    float t = fmaf(x, 0.125f, 1.f);
    t = fmaf(x * 0.14285714f, t, 1.f);
    t = fmaf(x * 0.16666667f, t, 1.f);
    t = fmaf(x * 0.2f,        t, 1.f);
    t = fmaf(x * 0.25f,       t, 1.f);
    t = fmaf(x * 0.33333333f, t, 1.f);
    t = fmaf(x * 0.5f,        t, 1.f);
    return x * t;
}

// ---------------- zero rowsum + wtot + tots ----------------
__global__ void zero_misc() {
    int i = blockIdx.x * 256 + threadIdx.x;
    if (i < BHn * Tn) g_rowsum[i] = 0.f;
    if (i < BHn * HDn) g_wtot[i] = 0.f;
    if (i < 8 * BHn) g_tots[i] = 0.f;
}

// ---------------- all weights fp32 -> bf16 hi/lo packed buffer ----------------
__global__ void conv_w_all(const float* __restrict__ w0, const float* __restrict__ w1,
                           const float* __restrict__ w2, const float* __restrict__ w3) {
    int idx = blockIdx.x * 256 + threadIdx.x;
    int e = idx * 4;
    if (e >= WTOTAL) return;
    const float* src;
    int K, N, local;
    if (e < WOFF_PRJ)       { src = w0; K = C1;  N = N3; local = e - WOFF_QKV; }
    else if (e < WOFF_FC)   { src = w1; K = Cn;  N = Cn; local = e - WOFF_PRJ; }
    else if (e < WOFF_FC2)  { src = w2; K = C1;  N = N4; local = e - WOFF_FC;  }
    else                    { src = w3; K = N4;  N = Cn; local = e - WOFF_FC2; }
    int row = local / N, col = local % N;
    float4 v = (row < K) ? *(const float4*)(src + (size_t)row * N + col)
                         : make_float4(0.f, 0.f, 0.f, 0.f);
    __nv_bfloat16 h0 = __float2bfloat16(v.x), h1 = __float2bfloat16(v.y);
    __nv_bfloat16 h2 = __float2bfloat16(v.z), h3 = __float2bfloat16(v.w);
    __nv_bfloat16 hbuf[4] = {h0, h1, h2, h3};
    __nv_bfloat16 lbuf[4] = {
        __float2bfloat16(v.x - __bfloat162float(h0)), __float2bfloat16(v.y - __bfloat162float(h1)),
        __float2bfloat16(v.z - __bfloat162float(h2)), __float2bfloat16(v.w - __bfloat162float(h3))};
    *(uint2*)(g_bh + e) = *(uint2*)hbuf;
    *(uint2*)(g_bl + e) = *(uint2*)lbuf;
}

// ---------------- LayerNorm -> bf16 hi/lo, stride KA_LN ----------------
__global__ void ln_bf(const float* __restrict__ x, const float* __restrict__ t,
                      const float* __restrict__ w, const float* __restrict__ bb,
                      __nv_bfloat16* __restrict__ oh, __nv_bfloat16* __restrict__ ol) {
    int row = blockIdx.x;
    int tid = threadIdx.x;
    __shared__ float sx[C1];
    __shared__ float red[256];
    float s1 = 0.f;
    for (int c = tid; c < C1; c += 256) {
        float v = (c < Cn) ? x[(size_t)row * Cn + c] : t[0];
        sx[c] = v;
        s1 += v;
    }
    red[tid] = s1; __syncthreads();
    for (int o = 128; o > 0; o >>= 1) { if (tid < o) red[tid] += red[tid + o]; __syncthreads(); }
    float mean = red[0] * (1.f / C1);
    __syncthreads();
    float s2 = 0.f;
    for (int c = tid; c < C1; c += 256) { float d = sx[c] - mean; s2 += d * d; }
    red[tid] = s2; __syncthreads();
    for (int o = 128; o > 0; o >>= 1) { if (tid < o) red[tid] += red[tid + o]; __syncthreads(); }
    float rs = rsqrtf(red[0] * (1.f / C1) + 1e-5f);
    for (int c = tid; c < C1; c += 256) {
        float v = (sx[c] - mean) * rs * w[c] + bb[c];
        __nv_bfloat16 hi = __float2bfloat16(v);
        oh[(size_t)row * KA_LN + c] = hi;
        ol[(size_t)row * KA_LN + c] = __float2bfloat16(v - __bfloat162float(hi));
    }
    if (tid < KA_LN - C1) {
        oh[(size_t)row * KA_LN + C1 + tid] = __float2bfloat16(0.f);
        ol[(size_t)row * KA_LN + C1 + tid] = __float2bfloat16(0.f);
    }
}

// ---------------- pipelined bf16 GEMM ----------------
// obf=0: fp32 out. obf=1: gelu + bf16 hi/lo out. obf=2: fp32 out + q/k bf16 split.
__global__ void __launch_bounds__(256) gemm_bf(const __nv_bfloat16* __restrict__ Ah,
                                               const __nv_bfloat16* __restrict__ Al,
                                               const __nv_bfloat16* __restrict__ Bh,
                                               const __nv_bfloat16* __restrict__ Bl,
                                               const float* __restrict__ bias,
                                               float* __restrict__ outF,
                                               __nv_bfloat16* __restrict__ oAh,
                                               __nv_bfloat16* __restrict__ oAl,
                                               int M, int N, int Ka, int act, int obf) {
    extern __shared__ __nv_bfloat16 dyn[];
    __nv_bfloat16* sA = dyn;
    __nv_bfloat16* sB = dyn + 4 * 5120;
    int tid = threadIdx.x;
    int wid = tid >> 5, lane = tid & 31;
    int wm = wid & 3, wn = wid >> 2;
    int bm = blockIdx.y * 128, bn = blockIdx.x * 128;
    float acc[2][8][4] = {};
    unsigned sAu = (unsigned)__cvta_generic_to_shared(sA);
    unsigned sBu = (unsigned)__cvta_generic_to_shared(sB);

    int nk = Ka >> 5;
    auto load_stage = [&](int kt, int st) {
        unsigned aH = sAu + (st * 2 + 0) * 5120 * 2;
        unsigned aL = sAu + (st * 2 + 1) * 5120 * 2;
        unsigned bH = sBu + (st * 2 + 0) * 4352 * 2;
        unsigned bL = sBu + (st * 2 + 1) * 4352 * 2;
        int k0 = kt * 32;
        #pragma unroll
        for (int z = 0; z < 2; z++) {
            int idx = z * 256 + tid;
            int row = idx >> 2, cq = (idx & 3) * 8;
            cpa16(aH + (row * 40 + cq) * 2, Ah + (size_t)(bm + row) * Ka + k0 + cq);
            cpa16(aL + (row * 40 + cq) * 2, Al + (size_t)(bm + row) * Ka + k0 + cq);
        }
        #pragma unroll
        for (int z = 0; z < 2; z++) {
            int idx = z * 256 + tid;
            int row = idx >> 4, cq = (idx & 15) * 8;
            cpa16(bH + (row * 136 + cq) * 2, Bh + (size_t)(k0 + row) * N + bn + cq);
            cpa16(bL + (row * 136 + cq) * 2, Bl + (size_t)(k0 + row) * N + bn + cq);
        }
    };

    load_stage(0, 0);
    CPA_COMMIT;
    for (int kt = 0; kt < nk; kt++) {
        int cur = kt & 1;
        if (kt + 1 < nk) load_stage(kt + 1, cur ^ 1);
        CPA_COMMIT;
        CPA_WAIT1;
        __syncthreads();
        unsigned aH = sAu + (cur * 2 + 0) * 5120 * 2;
        unsigned aL = sAu + (cur * 2 + 1) * 5120 * 2;
        unsigned bH = sBu + (cur * 2 + 0) * 4352 * 2;
        unsigned bL = sBu + (cur * 2 + 1) * 4352 * 2;
        #pragma unroll
        for (int kh = 0; kh < 32; kh += 16) {
            unsigned ah[2][4], al[2][4];
            #pragma unroll
            for (int mt = 0; mt < 2; mt++) {
                unsigned off = ((unsigned)((wm * 32 + mt * 16 + (lane & 15)) * 40 + kh + (lane >> 4) * 8)) * 2;
                ldmx4(aH + off, ah[mt][0], ah[mt][1], ah[mt][2], ah[mt][3]);
                ldmx4(aL + off, al[mt][0], al[mt][1], al[mt][2], al[mt][3]);
            }
            #pragma unroll
            for (int np = 0; np < 4; np++) {
                int n0 = wn * 64 + np * 16;
                unsigned boff = ((unsigned)((kh + (lane & 7) + 8 * ((lane >> 3) & 1)) * 136 + n0 + 8 * (lane >> 4))) * 2;
                unsigned bh0, bh1, bh2, bh3, bl0, bl1, bl2, bl3;
                ldmx4t(bH + boff, bh0, bh1, bh2, bh3);
                ldmx4t(bL + boff, bl0, bl1, bl2, bl3);
                #pragma unroll
                for (int mt = 0; mt < 2; mt++) {
                    mma_bf16(acc[mt][2 * np],     ah[mt][0], ah[mt][1], ah[mt][2], ah[mt][3], bh0, bh1);
                    mma_bf16(acc[mt][2 * np],     ah[mt][0], ah[mt][1], ah[mt][2], ah[mt][3], bl0, bl1);
                    mma_bf16(acc[mt][2 * np],     al[mt][0], al[mt][1], al[mt][2], al[mt][3], bh0, bh1);
                    mma_bf16(acc[mt][2 * np + 1], ah[mt][0], ah[mt][1], ah[mt][2], ah[mt][3], bh2, bh3);
                    mma_bf16(acc[mt][2 * np + 1], ah[mt][0], ah[mt][1], ah[mt][2], ah[mt][3], bl2, bl3);
                    mma_bf16(acc[mt][2 * np + 1], al[mt][0], al[mt][1], al[mt][2], al[mt][3], bh2, bh3);
                }
            }
        }
        __syncthreads();
    }
    #pragma unroll
    for (int mt = 0; mt < 2; mt++) {
        #pragma unroll
        for (int nt = 0; nt < 8; nt++) {
            float* cc = acc[mt][nt];
            int r = bm + wm * 32 + mt * 16 + (lane >> 2);
            int cn = bn + wn * 64 + nt * 8 + (lane & 3) * 2;
            float b0 = bias[cn], b1 = bias[cn + 1];
            float v0 = cc[0] + b0, v1 = cc[1] + b1;
            float v2 = cc[2] + b0, v3 = cc[3] + b1;
            if (act == 1) {
                v0 = 0.5f * v0 * (1.f + erff(v0 * 0.70710678f));
                v1 = 0.5f * v1 * (1.f + erff(v1 * 0.70710678f));
                v2 = 0.5f * v2 * (1.f + erff(v2 * 0.70710678f));
                v3 = 0.5f * v3 * (1.f + erff(v3 * 0.70710678f));
            }
            if (obf == 1) {
                __nv_bfloat16 h0 = __float2bfloat16(v0), h1 = __float2bfloat16(v1);
                __nv_bfloat16 h2 = __float2bfloat16(v2), h3 = __float2bfloat16(v3);
                oAh[(size_t)r * N + cn] = h0;
                oAh[(size_t)r * N + cn + 1] = h1;
                oAh[(size_t)(r + 8) * N + cn] = h2;
                oAh[(size_t)(r + 8) * N + cn + 1] = h3;
                oAl[(size_t)r * N + cn] = __float2bfloat16(v0 - __bfloat162float(h0));
                oAl[(size_t)r * N + cn + 1] = __float2bfloat16(v1 - __bfloat162float(h1));
                oAl[(size_t)(r + 8) * N + cn] = __float2bfloat16(v2 - __bfloat162float(h2));
                oAl[(size_t)(r + 8) * N + cn + 1] = __float2bfloat16(v3 - __bfloat162float(h3));
            } else {
                outF[(size_t)r * N + cn] = v0;
                outF[(size_t)r * N + cn + 1] = v1;
                outF[(size_t)(r + 8) * N + cn] = v2;
                outF[(size_t)(r + 8) * N + cn + 1] = v3;
                if (obf == 2 && cn < 2 * Cn) {
                    int isK = cn >= Cn;
                    int c2 = cn - isK * Cn;
                    __nv_bfloat16* H = isK ? g_kh : g_qh;
                    __nv_bfloat16* L = isK ? g_kl : g_ql;
                    __nv_bfloat16 h0 = __float2bfloat16(v0), h1 = __float2bfloat16(v1);
                    __nv_bfloat16 h2 = __float2bfloat16(v2), h3 = __float2bfloat16(v3);
                    H[(size_t)r * Cn + c2] = h0;
                    H[(size_t)r * Cn + c2 + 1] = h1;
                    H[(size_t)(r + 8) * Cn + c2] = h2;
                    H[(size_t)(r + 8) * Cn + c2 + 1] = h3;
                    L[(size_t)r * Cn + c2] = __float2bfloat16(v0 - __bfloat162float(h0));
                    L[(size_t)r * Cn + c2 + 1] = __float2bfloat16(v1 - __bfloat162float(h1));
                    L[(size_t)(r + 8) * Cn + c2] = __float2bfloat16(v2 - __bfloat162float(h2));
                    L[(size_t)(r + 8) * Cn + c2 + 1] = __float2bfloat16(v3 - __bfloat162float(h3));
                }
            }
        }
    }
}

// ---------------- TC scores + fused exp (fp16) + inline row sums ----------------
__global__ void __launch_bounds__(256) score_tc() {
    int jt = blockIdx.x, it = blockIdx.y, bh = blockIdx.z;
    if (jt > it) return;
    int b = bh / Hn, h = bh % Hn;
    __shared__ __nv_bfloat16 sQh[128][40], sQl[128][40], sKh[128][40], sKl[128][40];
    int tid = threadIdx.x, wid = tid >> 5, lane = tid & 31;
    int wm = wid & 3, wn = wid >> 2;
    float acc[2][8][4] = {};
    unsigned aQh = (unsigned)__cvta_generic_to_shared(&sQh[0][0]);
    unsigned aQl = (unsigned)__cvta_generic_to_shared(&sQl[0][0]);
    unsigned aKh = (unsigned)__cvta_generic_to_shared(&sKh[0][0]);
    unsigned aKl = (unsigned)__cvta_generic_to_shared(&sKl[0][0]);
    size_t qbase = ((size_t)(b * Tn + it * 128)) * Cn + h * HDn;
    size_t kbase = ((size_t)(b * Tn + jt * 128)) * Cn + h * HDn;

    for (int ks = 0; ks < 2; ks++) {
        if (ks) __syncthreads();
        #pragma unroll
        for (int z = 0; z < 2; z++) {
            int idx = z * 256 + tid;
            int r = idx >> 2, c8 = (idx & 3) * 8;
            *(uint4*)&sQh[r][c8] = *(const uint4*)(g_qh + qbase + (size_t)r * Cn + ks * 32 + c8);
            *(uint4*)&sQl[r][c8] = *(const uint4*)(g_ql + qbase + (size_t)r * Cn + ks * 32 + c8);
            *(uint4*)&sKh[r][c8] = *(const uint4*)(g_kh + kbase + (size_t)r * Cn + ks * 32 + c8);
            *(uint4*)&sKl[r][c8] = *(const uint4*)(g_kl + kbase + (size_t)r * Cn + ks * 32 + c8);
        }
        __syncthreads();
        #pragma unroll
        for (int kh = 0; kh < 32; kh += 16) {
            unsigned qh_[2][4], ql_[2][4];
            #pragma unroll
            for (int mt = 0; mt < 2; mt++) {
                unsigned off = ((unsigned)((wm * 32 + mt * 16 + (lane & 15)) * 40 + kh + 8 * (lane >> 4))) * 2;
                ldmx4(aQh + off, qh_[mt][0], qh_[mt][1], qh_[mt][2], qh_[mt][3]);
                ldmx4(aQl + off, ql_[mt][0], ql_[mt][1], ql_[mt][2], ql_[mt][3]);
            }
            #pragma unroll
            for (int nq = 0; nq < 4; nq++) {
                int n0 = wn * 64 + nq * 16;
                unsigned boff = ((unsigned)((n0 + (lane & 15)) * 40 + kh + 8 * (lane >> 4))) * 2;
                unsigned kh0, kh1, kh2, kh3, kl0, kl1, kl2, kl3;
                ldmx4(aKh + boff, kh0, kh1, kh2, kh3);
                ldmx4(aKl + boff, kl0, kl1, kl2, kl3);
                #pragma unroll
                for (int mt = 0; mt < 2; mt++) {
                    mma_bf16(acc[mt][2 * nq],     qh_[mt][0], qh_[mt][1], qh_[mt][2], qh_[mt][3], kh0, kh2);
                    mma_bf16(acc[mt][2 * nq],     qh_[mt][0], qh_[mt][1], qh_[mt][2], qh_[mt][3], kl0, kl2);
                    mma_bf16(acc[mt][2 * nq],     ql_[mt][0], ql_[mt][1], ql_[mt][2], ql_[mt][3], kh0, kh2);
                    mma_bf16(acc[mt][2 * nq + 1], qh_[mt][0], qh_[mt][1], qh_[mt][2], qh_[mt][3], kh1, kh3);
                    mma_bf16(acc[mt][2 * nq + 1], qh_[mt][0], qh_[mt][1], qh_[mt][2], qh_[mt][3], kl1, kl3);
                    mma_bf16(acc[mt][2 * nq + 1], ql_[mt][0], ql_[mt][1], ql_[mt][2], ql_[mt][3], kh1, kh3);
                }
            }
        }
    }
    __half* erow = g_e + (size_t)bh * Tn * Tn;
    float rsum[2][2] = {};
    int diag = (it == jt);
    #pragma unroll
    for (int mt = 0; mt < 2; mt++) {
        #pragma unroll
        for (int f = 0; f < 8; f++) {
            float* cc = acc[mt][f];
            int gi = it * 128 + wm * 32 + mt * 16 + (lane >> 2);
            int gj = jt * 128 + wn * 64 + (f >> 1) * 16 + (f & 1) * 8 + 2 * (lane & 3);
            float e0 = __expf(fminf(cc[0] * 0.125f, 11.f));
            float e1 = __expf(fminf(cc[1] * 0.125f, 11.f));
            float e2 = __expf(fminf(cc[2] * 0.125f, 11.f));
            float e3 = __expf(fminf(cc[3] * 0.125f, 11.f));
            if (diag) {
                if (gj > gi) e0 = 0.f;
                if (gj + 1 > gi) e1 = 0.f;
                if (gj > gi + 8) e2 = 0.f;
                if (gj + 1 > gi + 8) e3 = 0.f;
            }
            rsum[mt][0] += e0 + e1;
            rsum[mt][1] += e2 + e3;
            *(__half2*)(erow + (size_t)gi * Tn + gj) = __floats2half2_rn(e0, e1);
            *(__half2*)(erow + (size_t)(gi + 8) * Tn + gj) = __floats2half2_rn(e2, e3);
        }
    }
    #pragma unroll
    for (int mt = 0; mt < 2; mt++) {
        #pragma unroll
        for (int hh = 0; hh < 2; hh++) {
            float v = rsum[mt][hh];
            v += __shfl_xor_sync(0xffffffffu, v, 1);
            v += __shfl_xor_sync(0xffffffffu, v, 2);
            if ((lane & 3) == 0) {
                int gi = it * 128 + wm * 32 + mt * 16 + (lane >> 2) + hh * 8;
                atomicAdd(&g_rowsum[bh * Tn + gi], v);
            }
        }
    }
}

// ---------------- per row: Em1 = expm1(e/rowsum); u1, eu; eutot -> slot 0 ----------------
__global__ void em1_row() {
    int i = blockIdx.x, bh = blockIdx.y;
    int tid = threadIdx.x;
    int lane = tid & 31, wid = tid >> 5;
    float inv = 1.f / g_rowsum[bh * Tn + i];
    const uint4* src = (const uint4*)(g_e + ((size_t)bh * Tn + i) * Tn);
    uint4* dst = (uint4*)(g_c + ((size_t)bh * Tn + i) * Tn);
    int nv = ((i >> 7) + 1) << 4;
    float se = 0.f;
    if (tid < nv) {
        uint4 pk = src[tid];
        const __half2* hp = (const __half2*)&pk;
        uint4 outp;
        __half2* op = (__half2*)&outp;
        #pragma unroll
        for (int z = 0; z < 4; z++) {
            float2 f = __half22float2(hp[z]);
            float a = em1p(f.x * inv);
            float bb = em1p(f.y * inv);
            se += a + bb;
            op[z] = __floats2half2_rn(a, bb);
        }
        dst[tid] = outp;
    }
    se += __shfl_xor_sync(0xffffffffu, se, 16);
    se += __shfl_xor_sync(0xffffffffu, se, 8);
    se += __shfl_xor_sync(0xffffffffu, se, 4);
    se += __shfl_xor_sync(0xffffffffu, se, 2);
    se += __shfl_xor_sync(0xffffffffu, se, 1);
    __shared__ float red[8];
    if (lane == 0) red[wid] = se;
    __syncthreads();
    if (tid == 0) {
        float s = red[0] + red[1] + red[2] + red[3] + red[4] + red[5] + red[6] + red[7];
        float eu = __expf(-LOGT - __logf(s + (float)Tn));
        g_eu[bh * Tn + i] = eu;
        atomicAdd(&g_tots[bh], eu);   // slot 0
    }
}

// ---------------- Sinkhorn row pass: evtot from slot_in, eutot -> slot_out ----------------
__global__ void sink_row_f(int slot_in, int slot_out) {
    int r0 = blockIdx.x * 8, bh = blockIdx.y;
    int tid = threadIdx.x;
    __shared__ float sev[Tn];
    __shared__ float red[256];
    int jmax = r0 + 8;
    for (int j = tid; j < jmax; j += 256) sev[j] = g_ev[bh * Tn + j];
    float evtot = g_tots[slot_in * BHn + bh];
    __syncthreads();
    float euacc = 0.f;
    for (int r = 0; r < 8; r++) {
        int i = r0 + r;
        const uint4* cv = (const uint4*)(g_c + ((size_t)bh * Tn + i) * Tn);
        int nv = (i + 8) >> 3;
        float s = 0.f;
        for (int vi = tid; vi < nv; vi += 256) {
            uint4 pk = cv[vi];
            const __half2* hp = (const __half2*)&pk;
            int jb = vi * 8;
            #pragma unroll
            for (int z = 0; z < 4; z++) {
                float2 f = __half22float2(hp[z]);
                s += f.x * sev[jb + 2 * z] + f.y * sev[jb + 2 * z + 1];
            }
        }
        red[tid] = s; __syncthreads();
        for (int o = 128; o > 0; o >>= 1) { if (tid < o) red[tid] += red[tid + o]; __syncthreads(); }
        if (tid == 0) {
            float eu = __expf(-LOGT - __logf(red[0] + evtot));
            g_eu[bh * Tn + i] = eu;
            euacc += eu;
        }
        __syncthreads();
    }
    if (tid == 0) atomicAdd(&g_tots[slot_out * BHn + bh], euacc);
}

// ---------------- Sinkhorn col pass: partial over i-chunks ----------------
__global__ void sink_col_part() {
    int cb = blockIdx.x;
    int ic = blockIdx.y;
    int bh = blockIdx.z;
    int tid = threadIdx.x;
    int j0 = cb * 512 + tid * 2;
    int is = ic * 256;
    float* part = g_cpart + (size_t)(ic * BHn + bh) * Tn;
    if (cb * 512 >= is + 256) {
        part[j0] = 0.f;
        part[j0 + 1] = 0.f;
        return;
    }
    __shared__ float seu[256];
    seu[tid] = g_eu[bh * Tn + is + tid];
    __syncthreads();
    const __half* base = g_c + (size_t)bh * Tn * Tn + j0;
    float s0 = 0.f, s1 = 0.f;
    #pragma unroll 4
    for (int r = 0; r < 256; r++) {
        __half2 hh = *(const __half2*)(base + (size_t)(is + r) * Tn);
        float2 f = __half22float2(hh);
        float ui = seu[r];
        s0 += f.x * ui;
        s1 += f.y * ui;
    }
    part[j0] = s0;
    part[j0 + 1] = s1;
}

// ---------------- col finalize: eutot from slot_in, ev; evtot -> slot_out ----------------
__global__ void sink_col_fin(int slot_in, int slot_out) {
    int bh = blockIdx.y;
    int tid = threadIdx.x;
    int j = blockIdx.x * 256 + tid;
    float s = 0.f;
    #pragma unroll
    for (int ic = 0; ic < 8; ic++)
        s += g_cpart[(size_t)(ic * BHn + bh) * Tn + j];
    float ev = __expf(-LOGT - __logf(s + g_tots[slot_in * BHn + bh]));
    g_ev[bh * Tn + j] = ev;
    __shared__ float red[256];
    red[tid] = ev; __syncthreads();
    for (int o = 128; o > 0; o >>= 1) { if (tid < o) red[tid] += red[tid + o]; __syncthreads(); }
    if (tid == 0) atomicAdd(&g_tots[slot_out * BHn + bh], red[0]);
}

// ---------------- W = ev*V*512 -> fp16 hi/lo; Wtot ----------------
__global__ void w_kernel() {
    int jt = blockIdx.x, bh = blockIdx.y;
    int b = bh / Hn, h = bh % Hn;
    int tid = threadIdx.x;
    int d = tid & 63, r0 = tid >> 6;
    float part = 0.f;
    for (int r = r0; r < 128; r += 4) {
        int j = jt * 128 + r;
        float ev = g_ev[bh * Tn + j];
        float v = g_qkv[((size_t)(b * Tn + j)) * N3 + 2 * Cn + h * HDn + d];
        float w = ev * v;
        part += w;
        float ws = fminf(fmaxf(w * WSCALE, -32768.f), 32768.f);
        __half hi = __float2half(ws);
        g_wh[((size_t)bh * Tn + j) * HDn + d] = hi;
        g_wl[((size_t)bh * Tn + j) * HDn + d] = __float2half(ws - __half2float(hi));
    }
    __shared__ float red[256];
    red[tid] = part; __syncthreads();
    if (tid < 128) red[tid] += red[tid + 128];
    __syncthreads();
    if (tid < 64) atomicAdd(&g_wtot[bh * HDn + tid], red[tid] + red[tid + 64]);
}

// ---------------- pi@V via fp16 TC; y written as bf16 hi/lo (proj A operand) ----------------
__global__ void __launch_bounds__(256) pi_v_tc() {
    int bh = blockIdx.y;
    int b = bh / Hn, h = bh % Hn;
    int it = gridDim.x - 1 - blockIdx.x;
    int i0 = it * 128;
    __shared__ __half sA[128][72];
    __shared__ __half sWh[64][72], sWl[64][72];
    int tid = threadIdx.x, wid = tid >> 5, lane = tid & 31;
    int wm = wid & 3, wn = wid >> 2;
    float acc[2][4][4] = {};
    unsigned aA = (unsigned)__cvta_generic_to_shared(&sA[0][0]);
    unsigned aWh = (unsigned)__cvta_generic_to_shared(&sWh[0][0]);
    unsigned aWl = (unsigned)__cvta_generic_to_shared(&sWl[0][0]);

    for (int jc = 0; jc < i0 + 128; jc += 64) {
        if (jc) __syncthreads();
        #pragma unroll
        for (int z = 0; z < 4; z++) {
            int idx = z * 256 + tid;
            int r = idx >> 3, c8 = (idx & 7) * 8;
            *(uint4*)&sA[r][c8] = *(const uint4*)(g_c + ((size_t)bh * Tn + i0 + r) * Tn + jc + c8);
        }
        #pragma unroll
        for (int z = 0; z < 2; z++) {
            int idx = z * 256 + tid;
            int r = idx >> 3, c8 = (idx & 7) * 8;
            *(uint4*)&sWh[r][c8] = *(const uint4*)(g_wh + ((size_t)bh * Tn + jc + r) * HDn + c8);
            *(uint4*)&sWl[r][c8] = *(const uint4*)(g_wl + ((size_t)bh * Tn + jc + r) * HDn + c8);
        }
        __syncthreads();
        #pragma unroll
        for (int kh = 0; kh < 64; kh += 16) {
            unsigned a_[2][4];
            #pragma unroll
            for (int mt = 0; mt < 2; mt++) {
                unsigned off = ((unsigned)((wm * 32 + mt * 16 + (lane & 15)) * 72 + kh + 8 * (lane >> 4))) * 2;
                ldmx4(aA + off, a_[mt][0], a_[mt][1], a_[mt][2], a_[mt][3]);
            }
            #pragma unroll
            for (int nq = 0; nq < 2; nq++) {
                int n0 = wn * 32 + nq * 16;
                unsigned boff = ((unsigned)((kh + (lane & 7) + 8 * ((lane >> 3) & 1)) * 72 + n0 + 8 * (lane >> 4))) * 2;
                unsigned bh0, bh1, bh2, bh3, bl0, bl1, bl2, bl3;
                ldmx4t(aWh + boff, bh0, bh1, bh2, bh3);
                ldmx4t(aWl + boff, bl0, bl1, bl2, bl3);
                #pragma unroll
                for (int mt = 0; mt < 2; mt++) {
                    mma_f16(acc[mt][2 * nq],     a_[mt][0], a_[mt][1], a_[mt][2], a_[mt][3], bh0, bh1);
                    mma_f16(acc[mt][2 * nq],     a_[mt][0], a_[mt][1], a_[mt][2], a_[mt][3], bl0, bl1);
                    mma_f16(acc[mt][2 * nq + 1], a_[mt][0], a_[mt][1], a_[mt][2], a_[mt][3], bh2, bh3);
                    mma_f16(acc[mt][2 * nq + 1], a_[mt][0], a_[mt][1], a_[mt][2], a_[mt][3], bl2, bl3);
                }
            }
        }
    }
    #pragma unroll
    for (int mt = 0; mt < 2; mt++) {
        #pragma unroll
        for (int f = 0; f < 4; f++) {
            float* cc = acc[mt][f];
            int r = i0 + wm * 32 + mt * 16 + (lane >> 2);
            int d = wn * 32 + f * 8 + 2 * (lane & 3);
            float wt0 = g_wtot[bh * HDn + d], wt1 = g_wtot[bh * HDn + d + 1];
            float eu0 = g_eu[bh * Tn + r] * 2048.f;
            float eu1 = g_eu[bh * Tn + r + 8] * 2048.f;
            float y0 = (cc[0] * WINV + wt0) * eu0;
            float y1 = (cc[1] * WINV + wt1) * eu0;
            float y2 = (cc[2] * WINV + wt0) * eu1;
            float y3 = (cc[3] * WINV + wt1) * eu1;
            size_t base = ((size_t)(b * Tn) + r) * Cn + h * HDn + d;
            __nv_bfloat16 h0 = __float2bfloat16(y0), h1 = __float2bfloat16(y1);
            __nv_bfloat16 h2 = __float2bfloat16(y2), h3 = __float2bfloat16(y3);
            g_ah[base] = h0;
            g_ah[base + 1] = h1;
            g_ah[base + (size_t)8 * Cn] = h2;
            g_ah[base + (size_t)8 * Cn + 1] = h3;
            g_al[base] = __float2bfloat16(y0 - __bfloat162float(h0));
            g_al[base + 1] = __float2bfloat16(y1 - __bfloat162float(h1));
            g_al[base + (size_t)8 * Cn] = __float2bfloat16(y2 - __bfloat162float(h2));
            g_al[base + (size_t)8 * Cn + 1] = __float2bfloat16(y3 - __bfloat162float(h3));
        }
    }
}

// ---------------- launch ----------------
extern "C" void kernel_launch(void* const* d_in, const int* in_sizes, int n_in,
                              void* d_out, int out_size) {
    const float* x      = (const float*)d_in[0];
    const float* t      = (const float*)d_in[1];
    const float* ln1_w  = (const float*)d_in[2];
    const float* ln1_b  = (const float*)d_in[3];
    const float* attn_w = (const float*)d_in[4];
    const float* attn_b = (const float*)d_in[5];
    const float* proj_w = (const float*)d_in[6];
    const float* proj_b = (const float*)d_in[7];
    const float* ln2_w  = (const float*)d_in[8];
    const float* ln2_b  = (const float*)d_in[9];
    const float* fc_w   = (const float*)d_in[10];
    const float* fc_b   = (const float*)d_in[11];
    const float* fc2_w  = (const float*)d_in[12];
    const float* fc2_b  = (const float*)d_in[13];
    float* out = (float*)d_out;

    float *p_qkv, *p_h;
    __nv_bfloat16 *p_ah, *p_al, *p_a2h, *p_a2l, *p_bh, *p_bl;
    cudaGetSymbolAddress((void**)&p_qkv, g_qkv);
    cudaGetSymbolAddress((void**)&p_h,   g_h);
    cudaGetSymbolAddress((void**)&p_ah,  g_ah);
    cudaGetSymbolAddress((void**)&p_al,  g_al);
    cudaGetSymbolAddress((void**)&p_a2h, g_a2h);
    cudaGetSymbolAddress((void**)&p_a2l, g_a2l);
    cudaGetSymbolAddress((void**)&p_bh,  g_bh);
    cudaGetSymbolAddress((void**)&p_bl,  g_bl);

    static int smem_set = 0;
    const int GSM = 75776;
    if (!smem_set) {
        cudaFuncSetAttribute(gemm_bf, cudaFuncAttributeMaxDynamicSharedMemorySize, GSM);
        smem_set = 1;
    }

    // ---- setup ----
    zero_misc<<<96, 256>>>();
    conv_w_all<<<(WTOTAL / 4 + 255) / 256, 256>>>(attn_w, proj_w, fc_w, fc2_w);

    // ---- attention sub-block ----
    ln_bf<<<ROWS, 256>>>(x, t, ln1_w, ln1_b, p_ah, p_al);
    gemm_bf<<<dim3(N3 / 128, ROWS / 128), 256, GSM>>>(p_ah, p_al, p_bh + WOFF_QKV, p_bl + WOFF_QKV, attn_b,
                                                      p_qkv, nullptr, nullptr, ROWS, N3, KA_LN, 0, 2);
    score_tc<<<dim3(Tn / 128, Tn / 128, BHn), 256>>>();
    em1_row<<<dim3(Tn, BHn), 256>>>();   // -> eu, eutot slot0

    // sinkhorn remaining 5 passes: col,row,col,row,col
    sink_col_part<<<dim3(4, 8, BHn), 256>>>();
    sink_col_fin<<<dim3(8, BHn), 256>>>(0, 1);
    sink_row_f<<<dim3(Tn / 8, BHn), 256>>>(1, 2);
    sink_col_part<<<dim3(4, 8, BHn), 256>>>();
    sink_col_fin<<<dim3(8, BHn), 256>>>(2, 3);
    sink_row_f<<<dim3(Tn / 8, BHn), 256>>>(3, 4);
    sink_col_part<<<dim3(4, 8, BHn), 256>>>();
    sink_col_fin<<<dim3(8, BHn), 256>>>(4, 5);

    w_kernel<<<dim3(Tn / 128, BHn), 256>>>();
    pi_v_tc<<<dim3(Tn / 128, BHn), 256>>>();   // -> g_ah/g_al (y split), stride Cn

    // proj
    gemm_bf<<<dim3(Cn / 128, ROWS / 128), 256, GSM>>>(p_ah, p_al, p_bh + WOFF_PRJ, p_bl + WOFF_PRJ, proj_b,
                                                      p_h, nullptr, nullptr, ROWS, Cn, Cn, 0, 0);

    // ---- MLP sub-block ----
    ln_bf<<<ROWS, 256>>>(p_h, t, ln2_w, ln2_b, p_ah, p_al);
    gemm_bf<<<dim3(N4 / 128, ROWS / 128), 256, GSM>>>(p_ah, p_al, p_bh + WOFF_FC, p_bl + WOFF_FC, fc_b,
                                                      nullptr, p_a2h, p_a2l, ROWS, N4, KA_LN, 1, 1);
    gemm_bf<<<dim3(Cn / 128, ROWS / 128), 256, GSM>>>(p_a2h, p_a2l, p_bh + WOFF_FC2, p_bl + WOFF_FC2, fc2_b,
                                                      out, nullptr, nullptr, ROWS, Cn, N4, 0, 0);
}

// round 11
// speedup vs baseline: 6.1245x; 1.0655x over previous
#include <cuda_runtime.h>
#include <cuda_fp16.h>
#include <cuda_bf16.h>
#include <math.h>

#define Tn 2048
#define Cn 384
#define Hn 6
#define HDn 64
#define Bn 2
#define BHn 12
#define ROWS 4096
#define C1 385
#define KA_LN 416
#define N3 1152
#define N4 1536
#define LOGT 7.62461899f
#define WSCALE 512.f
#define WINV   (1.f / 512.f)

#define WOFF_QKV 0
#define WSZ_QKV  (KA_LN * N3)
#define WOFF_PRJ (WOFF_QKV + WSZ_QKV)
#define WSZ_PRJ  (Cn * Cn)
#define WOFF_FC  (WOFF_PRJ + WSZ_PRJ)
#define WSZ_FC   (KA_LN * N4)
#define WOFF_FC2 (WOFF_FC + WSZ_FC)
#define WSZ_FC2  (N4 * Cn)
#define WTOTAL   (WOFF_FC2 + WSZ_FC2)

// ---------------- scratch ----------------
__device__ __align__(16) float g_qkv[ROWS * N3];
__device__ __align__(16) __half g_e[(size_t)BHn * Tn * Tn];
__device__ __align__(16) __half g_c[(size_t)BHn * Tn * Tn];
__device__ __align__(16) __nv_bfloat16 g_qh[ROWS * Cn];
__device__ __align__(16) __nv_bfloat16 g_ql[ROWS * Cn];
__device__ __align__(16) __nv_bfloat16 g_kh[ROWS * Cn];
__device__ __align__(16) __nv_bfloat16 g_kl[ROWS * Cn];
__device__ __align__(16) __half g_wh[BHn * Tn * HDn];
__device__ __align__(16) __half g_wl[BHn * Tn * HDn];
__device__ float g_rowsum[BHn * Tn];
__device__ float g_eu[BHn * Tn];
__device__ float g_ev[BHn * Tn];
__device__ float g_tots[8 * BHn];
__device__ float g_wtot[BHn * HDn];
__device__ __align__(16) float g_cpart[8 * BHn * Tn];
__device__ __align__(16) float g_h[ROWS * Cn];
__device__ __align__(16) __nv_bfloat16 g_ah[ROWS * N4];
__device__ __align__(16) __nv_bfloat16 g_al[ROWS * N4];
__device__ __align__(16) __nv_bfloat16 g_a2h[ROWS * N4];
__device__ __align__(16) __nv_bfloat16 g_a2l[ROWS * N4];
__device__ __align__(16) __nv_bfloat16 g_bh[WTOTAL];
__device__ __align__(16) __nv_bfloat16 g_bl[WTOTAL];

// ---------------- helpers ----------------
__device__ __forceinline__ void ldmx4(unsigned addr, unsigned& r0, unsigned& r1, unsigned& r2, unsigned& r3) {
    asm volatile("ldmatrix.sync.aligned.m8n8.x4.shared.b16 {%0,%1,%2,%3},[%4];"
                 : "=r"(r0), "=r"(r1), "=r"(r2), "=r"(r3) : "r"(addr));
}
__device__ __forceinline__ void ldmx4t(unsigned addr, unsigned& r0, unsigned& r1, unsigned& r2, unsigned& r3) {
    asm volatile("ldmatrix.sync.aligned.m8n8.x4.trans.shared.b16 {%0,%1,%2,%3},[%4];"
                 : "=r"(r0), "=r"(r1), "=r"(r2), "=r"(r3) : "r"(addr));
}
__device__ __forceinline__ void mma_bf16(float* c, unsigned a0, unsigned a1, unsigned a2, unsigned a3,
                                         unsigned b0, unsigned b1) {
    asm volatile("mma.sync.aligned.m16n8k16.row.col.f32.bf16.bf16.f32 "
                 "{%0,%1,%2,%3},{%4,%5,%6,%7},{%8,%9},{%0,%1,%2,%3};"
                 : "+f"(c[0]), "+f"(c[1]), "+f"(c[2]), "+f"(c[3])
                 : "r"(a0), "r"(a1), "r"(a2), "r"(a3), "r"(b0), "r"(b1));
}
__device__ __forceinline__ void mma_f16(float* c, unsigned a0, unsigned a1, unsigned a2, unsigned a3,
                                        unsigned b0, unsigned b1) {
    asm volatile("mma.sync.aligned.m16n8k16.row.col.f32.f16.f16.f32 "
                 "{%0,%1,%2,%3},{%4,%5,%6,%7},{%8,%9},{%0,%1,%2,%3};"
                 : "+f"(c[0]), "+f"(c[1]), "+f"(c[2]), "+f"(c[3])
                 : "r"(a0), "r"(a1), "r"(a2), "r"(a3), "r"(b0), "r"(b1));
}
__device__ __forceinline__ void cpa16(unsigned dst, const void* src) {
    asm volatile("cp.async.cg.shared.global [%0],[%1],16;" :: "r"(dst), "l"(src));
}
#define CPA_COMMIT asm volatile("cp.async.commit_group;")
#define CPA_WAIT1  asm volatile("cp.async.wait_group 1;")

__device__ __forceinline__ float em1p(float x) {
    float t = fmaf(x, 0.125f, 1.f);
    t = fmaf(x * 0.14285714f, t, 1.f);
    t = fmaf(x * 0.16666667f, t, 1.f);
    t = fmaf(x * 0.2f,        t, 1.f);
    t = fmaf(x * 0.25f,       t, 1.f);
    t = fmaf(x * 0.33333333f, t, 1.f);
    t = fmaf(x * 0.5f,        t, 1.f);
    return x * t;
}

// ---------------- zero ----------------
__global__ void zero_misc() {
    int i = blockIdx.x * 256 + threadIdx.x;
    if (i < BHn * Tn) g_rowsum[i] = 0.f;
    if (i < BHn * HDn) g_wtot[i] = 0.f;
    if (i < 8 * BHn) g_tots[i] = 0.f;
}

// ---------------- weights -> bf16 hi/lo ----------------
__global__ void conv_w_all(const float* __restrict__ w0, const float* __restrict__ w1,
                           const float* __restrict__ w2, const float* __restrict__ w3) {
    int idx = blockIdx.x * 256 + threadIdx.x;
    int e = idx * 4;
    if (e >= WTOTAL) return;
    const float* src;
    int K, N, local;
    if (e < WOFF_PRJ)       { src = w0; K = C1;  N = N3; local = e - WOFF_QKV; }
    else if (e < WOFF_FC)   { src = w1; K = Cn;  N = Cn; local = e - WOFF_PRJ; }
    else if (e < WOFF_FC2)  { src = w2; K = C1;  N = N4; local = e - WOFF_FC;  }
    else                    { src = w3; K = N4;  N = Cn; local = e - WOFF_FC2; }
    int row = local / N, col = local % N;
    float4 v = (row < K) ? *(const float4*)(src + (size_t)row * N + col)
                         : make_float4(0.f, 0.f, 0.f, 0.f);
    __nv_bfloat16 h0 = __float2bfloat16(v.x), h1 = __float2bfloat16(v.y);
    __nv_bfloat16 h2 = __float2bfloat16(v.z), h3 = __float2bfloat16(v.w);
    __nv_bfloat16 hbuf[4] = {h0, h1, h2, h3};
    __nv_bfloat16 lbuf[4] = {
        __float2bfloat16(v.x - __bfloat162float(h0)), __float2bfloat16(v.y - __bfloat162float(h1)),
        __float2bfloat16(v.z - __bfloat162float(h2)), __float2bfloat16(v.w - __bfloat162float(h3))};
    *(uint2*)(g_bh + e) = *(uint2*)hbuf;
    *(uint2*)(g_bl + e) = *(uint2*)lbuf;
}

// ---------------- LayerNorm -> bf16 hi/lo ----------------
__global__ void ln_bf(const float* __restrict__ x, const float* __restrict__ t,
                      const float* __restrict__ w, const float* __restrict__ bb,
                      __nv_bfloat16* __restrict__ oh, __nv_bfloat16* __restrict__ ol) {
    int row = blockIdx.x;
    int tid = threadIdx.x;
    __shared__ float sx[C1];
    __shared__ float red[256];
    float s1 = 0.f;
    for (int c = tid; c < C1; c += 256) {
        float v = (c < Cn) ? x[(size_t)row * Cn + c] : t[0];
        sx[c] = v;
        s1 += v;
    }
    red[tid] = s1; __syncthreads();
    for (int o = 128; o > 0; o >>= 1) { if (tid < o) red[tid] += red[tid + o]; __syncthreads(); }
    float mean = red[0] * (1.f / C1);
    __syncthreads();
    float s2 = 0.f;
    for (int c = tid; c < C1; c += 256) { float d = sx[c] - mean; s2 += d * d; }
    red[tid] = s2; __syncthreads();
    for (int o = 128; o > 0; o >>= 1) { if (tid < o) red[tid] += red[tid + o]; __syncthreads(); }
    float rs = rsqrtf(red[0] * (1.f / C1) + 1e-5f);
    for (int c = tid; c < C1; c += 256) {
        float v = (sx[c] - mean) * rs * w[c] + bb[c];
        __nv_bfloat16 hi = __float2bfloat16(v);
        oh[(size_t)row * KA_LN + c] = hi;
        ol[(size_t)row * KA_LN + c] = __float2bfloat16(v - __bfloat162float(hi));
    }
    if (tid < KA_LN - C1) {
        oh[(size_t)row * KA_LN + C1 + tid] = __float2bfloat16(0.f);
        ol[(size_t)row * KA_LN + C1 + tid] = __float2bfloat16(0.f);
    }
}

// ---------------- pipelined bf16 GEMM, 128x128 tile ----------------
__global__ void __launch_bounds__(256) gemm_bf(const __nv_bfloat16* __restrict__ Ah,
                                               const __nv_bfloat16* __restrict__ Al,
                                               const __nv_bfloat16* __restrict__ Bh,
                                               const __nv_bfloat16* __restrict__ Bl,
                                               const float* __restrict__ bias,
                                               float* __restrict__ outF,
                                               __nv_bfloat16* __restrict__ oAh,
                                               __nv_bfloat16* __restrict__ oAl,
                                               int M, int N, int Ka, int act, int obf) {
    extern __shared__ __nv_bfloat16 dyn[];
    __nv_bfloat16* sA = dyn;
    __nv_bfloat16* sB = dyn + 4 * 5120;
    int tid = threadIdx.x;
    int wid = tid >> 5, lane = tid & 31;
    int wm = wid & 3, wn = wid >> 2;
    int bm = blockIdx.y * 128, bn = blockIdx.x * 128;
    float acc[2][8][4] = {};
    unsigned sAu = (unsigned)__cvta_generic_to_shared(sA);
    unsigned sBu = (unsigned)__cvta_generic_to_shared(sB);

    int nk = Ka >> 5;
    auto load_stage = [&](int kt, int st) {
        unsigned aH = sAu + (st * 2 + 0) * 5120 * 2;
        unsigned aL = sAu + (st * 2 + 1) * 5120 * 2;
        unsigned bH = sBu + (st * 2 + 0) * 4352 * 2;
        unsigned bL = sBu + (st * 2 + 1) * 4352 * 2;
        int k0 = kt * 32;
        #pragma unroll
        for (int z = 0; z < 2; z++) {
            int idx = z * 256 + tid;
            int row = idx >> 2, cq = (idx & 3) * 8;
            cpa16(aH + (row * 40 + cq) * 2, Ah + (size_t)(bm + row) * Ka + k0 + cq);
            cpa16(aL + (row * 40 + cq) * 2, Al + (size_t)(bm + row) * Ka + k0 + cq);
        }
        #pragma unroll
        for (int z = 0; z < 2; z++) {
            int idx = z * 256 + tid;
            int row = idx >> 4, cq = (idx & 15) * 8;
            cpa16(bH + (row * 136 + cq) * 2, Bh + (size_t)(k0 + row) * N + bn + cq);
            cpa16(bL + (row * 136 + cq) * 2, Bl + (size_t)(k0 + row) * N + bn + cq);
        }
    };

    load_stage(0, 0);
    CPA_COMMIT;
    for (int kt = 0; kt < nk; kt++) {
        int cur = kt & 1;
        if (kt + 1 < nk) load_stage(kt + 1, cur ^ 1);
        CPA_COMMIT;
        CPA_WAIT1;
        __syncthreads();
        unsigned aH = sAu + (cur * 2 + 0) * 5120 * 2;
        unsigned aL = sAu + (cur * 2 + 1) * 5120 * 2;
        unsigned bH = sBu + (cur * 2 + 0) * 4352 * 2;
        unsigned bL = sBu + (cur * 2 + 1) * 4352 * 2;
        #pragma unroll
        for (int kh = 0; kh < 32; kh += 16) {
            unsigned ah[2][4], al[2][4];
            #pragma unroll
            for (int mt = 0; mt < 2; mt++) {
                unsigned off = ((unsigned)((wm * 32 + mt * 16 + (lane & 15)) * 40 + kh + (lane >> 4) * 8)) * 2;
                ldmx4(aH + off, ah[mt][0], ah[mt][1], ah[mt][2], ah[mt][3]);
                ldmx4(aL + off, al[mt][0], al[mt][1], al[mt][2], al[mt][3]);
            }
            #pragma unroll
            for (int np = 0; np < 4; np++) {
                int n0 = wn * 64 + np * 16;
                unsigned boff = ((unsigned)((kh + (lane & 7) + 8 * ((lane >> 3) & 1)) * 136 + n0 + 8 * (lane >> 4))) * 2;
                unsigned bh0, bh1, bh2, bh3, bl0, bl1, bl2, bl3;
                ldmx4t(bH + boff, bh0, bh1, bh2, bh3);
                ldmx4t(bL + boff, bl0, bl1, bl2, bl3);
                #pragma unroll
                for (int mt = 0; mt < 2; mt++) {
                    mma_bf16(acc[mt][2 * np],     ah[mt][0], ah[mt][1], ah[mt][2], ah[mt][3], bh0, bh1);
                    mma_bf16(acc[mt][2 * np],     ah[mt][0], ah[mt][1], ah[mt][2], ah[mt][3], bl0, bl1);
                    mma_bf16(acc[mt][2 * np],     al[mt][0], al[mt][1], al[mt][2], al[mt][3], bh0, bh1);
                    mma_bf16(acc[mt][2 * np + 1], ah[mt][0], ah[mt][1], ah[mt][2], ah[mt][3], bh2, bh3);
                    mma_bf16(acc[mt][2 * np + 1], ah[mt][0], ah[mt][1], ah[mt][2], ah[mt][3], bl2, bl3);
                    mma_bf16(acc[mt][2 * np + 1], al[mt][0], al[mt][1], al[mt][2], al[mt][3], bh2, bh3);
                }
            }
        }
        __syncthreads();
    }
    #pragma unroll
    for (int mt = 0; mt < 2; mt++) {
        #pragma unroll
        for (int nt = 0; nt < 8; nt++) {
            float* cc = acc[mt][nt];
            int r = bm + wm * 32 + mt * 16 + (lane >> 2);
            int cn = bn + wn * 64 + nt * 8 + (lane & 3) * 2;
            float b0 = bias[cn], b1 = bias[cn + 1];
            float v0 = cc[0] + b0, v1 = cc[1] + b1;
            float v2 = cc[2] + b0, v3 = cc[3] + b1;
            if (act == 1) {
                v0 = 0.5f * v0 * (1.f + erff(v0 * 0.70710678f));
                v1 = 0.5f * v1 * (1.f + erff(v1 * 0.70710678f));
                v2 = 0.5f * v2 * (1.f + erff(v2 * 0.70710678f));
                v3 = 0.5f * v3 * (1.f + erff(v3 * 0.70710678f));
            }
            if (obf == 1) {
                __nv_bfloat16 h0 = __float2bfloat16(v0), h1 = __float2bfloat16(v1);
                __nv_bfloat16 h2 = __float2bfloat16(v2), h3 = __float2bfloat16(v3);
                oAh[(size_t)r * N + cn] = h0;
                oAh[(size_t)r * N + cn + 1] = h1;
                oAh[(size_t)(r + 8) * N + cn] = h2;
                oAh[(size_t)(r + 8) * N + cn + 1] = h3;
                oAl[(size_t)r * N + cn] = __float2bfloat16(v0 - __bfloat162float(h0));
                oAl[(size_t)r * N + cn + 1] = __float2bfloat16(v1 - __bfloat162float(h1));
                oAl[(size_t)(r + 8) * N + cn] = __float2bfloat16(v2 - __bfloat162float(h2));
                oAl[(size_t)(r + 8) * N + cn + 1] = __float2bfloat16(v3 - __bfloat162float(h3));
            } else {
                outF[(size_t)r * N + cn] = v0;
                outF[(size_t)r * N + cn + 1] = v1;
                outF[(size_t)(r + 8) * N + cn] = v2;
                outF[(size_t)(r + 8) * N + cn + 1] = v3;
                if (obf == 2 && cn < 2 * Cn) {
                    int isK = cn >= Cn;
                    int c2 = cn - isK * Cn;
                    __nv_bfloat16* H = isK ? g_kh : g_qh;
                    __nv_bfloat16* L = isK ? g_kl : g_ql;
                    __nv_bfloat16 h0 = __float2bfloat16(v0), h1 = __float2bfloat16(v1);
                    __nv_bfloat16 h2 = __float2bfloat16(v2), h3 = __float2bfloat16(v3);
                    H[(size_t)r * Cn + c2] = h0;
                    H[(size_t)r * Cn + c2 + 1] = h1;
                    H[(size_t)(r + 8) * Cn + c2] = h2;
                    H[(size_t)(r + 8) * Cn + c2 + 1] = h3;
                    L[(size_t)r * Cn + c2] = __float2bfloat16(v0 - __bfloat162float(h0));
                    L[(size_t)r * Cn + c2 + 1] = __float2bfloat16(v1 - __bfloat162float(h1));
                    L[(size_t)(r + 8) * Cn + c2] = __float2bfloat16(v2 - __bfloat162float(h2));
                    L[(size_t)(r + 8) * Cn + c2 + 1] = __float2bfloat16(v3 - __bfloat162float(h3));
                }
            }
        }
    }
}

// ---------------- pipelined bf16 GEMM, 64x128 tile (for small-N GEMMs) ----------------
__global__ void __launch_bounds__(256) gemm_bf64(const __nv_bfloat16* __restrict__ Ah,
                                                 const __nv_bfloat16* __restrict__ Al,
                                                 const __nv_bfloat16* __restrict__ Bh,
                                                 const __nv_bfloat16* __restrict__ Bl,
                                                 const float* __restrict__ bias,
                                                 float* __restrict__ outF,
                                                 int M, int N, int Ka) {
    extern __shared__ __nv_bfloat16 dyn[];
    __nv_bfloat16* sA = dyn;               // 2 stages x 2 hl x 2560
    __nv_bfloat16* sB = dyn + 4 * 2560;    // 2 stages x 2 hl x 4352
    int tid = threadIdx.x;
    int wid = tid >> 5, lane = tid & 31;
    int wm = wid & 1, wn = wid >> 1;       // 2 m-warps x 4 n-warps
    int bm = blockIdx.y * 64, bn = blockIdx.x * 128;
    float acc[2][4][4] = {};
    unsigned sAu = (unsigned)__cvta_generic_to_shared(sA);
    unsigned sBu = (unsigned)__cvta_generic_to_shared(sB);

    int nk = Ka >> 5;
    auto load_stage = [&](int kt, int st) {
        unsigned aH = sAu + (st * 2 + 0) * 2560 * 2;
        unsigned aL = sAu + (st * 2 + 1) * 2560 * 2;
        unsigned bH = sBu + (st * 2 + 0) * 4352 * 2;
        unsigned bL = sBu + (st * 2 + 1) * 4352 * 2;
        int k0 = kt * 32;
        {
            int row = tid >> 2, cq = (tid & 3) * 8;
            cpa16(aH + (row * 40 + cq) * 2, Ah + (size_t)(bm + row) * Ka + k0 + cq);
            cpa16(aL + (row * 40 + cq) * 2, Al + (size_t)(bm + row) * Ka + k0 + cq);
        }
        #pragma unroll
        for (int z = 0; z < 2; z++) {
            int idx = z * 256 + tid;
            int row = idx >> 4, cq = (idx & 15) * 8;
            cpa16(bH + (row * 136 + cq) * 2, Bh + (size_t)(k0 + row) * N + bn + cq);
            cpa16(bL + (row * 136 + cq) * 2, Bl + (size_t)(k0 + row) * N + bn + cq);
        }
    };

    load_stage(0, 0);
    CPA_COMMIT;
    for (int kt = 0; kt < nk; kt++) {
        int cur = kt & 1;
        if (kt + 1 < nk) load_stage(kt + 1, cur ^ 1);
        CPA_COMMIT;
        CPA_WAIT1;
        __syncthreads();
        unsigned aH = sAu + (cur * 2 + 0) * 2560 * 2;
        unsigned aL = sAu + (cur * 2 + 1) * 2560 * 2;
        unsigned bH = sBu + (cur * 2 + 0) * 4352 * 2;
        unsigned bL = sBu + (cur * 2 + 1) * 4352 * 2;
        #pragma unroll
        for (int kh = 0; kh < 32; kh += 16) {
            unsigned ah[2][4], al[2][4];
            #pragma unroll
            for (int mt = 0; mt < 2; mt++) {
                unsigned off = ((unsigned)((wm * 32 + mt * 16 + (lane & 15)) * 40 + kh + (lane >> 4) * 8)) * 2;
                ldmx4(aH + off, ah[mt][0], ah[mt][1], ah[mt][2], ah[mt][3]);
                ldmx4(aL + off, al[mt][0], al[mt][1], al[mt][2], al[mt][3]);
            }
            #pragma unroll
            for (int np = 0; np < 2; np++) {
                int n0 = wn * 32 + np * 16;
                unsigned boff = ((unsigned)((kh + (lane & 7) + 8 * ((lane >> 3) & 1)) * 136 + n0 + 8 * (lane >> 4))) * 2;
                unsigned bh0, bh1, bh2, bh3, bl0, bl1, bl2, bl3;
                ldmx4t(bH + boff, bh0, bh1, bh2, bh3);
                ldmx4t(bL + boff, bl0, bl1, bl2, bl3);
                #pragma unroll
                for (int mt = 0; mt < 2; mt++) {
                    mma_bf16(acc[mt][2 * np],     ah[mt][0], ah[mt][1], ah[mt][2], ah[mt][3], bh0, bh1);
                    mma_bf16(acc[mt][2 * np],     ah[mt][0], ah[mt][1], ah[mt][2], ah[mt][3], bl0, bl1);
                    mma_bf16(acc[mt][2 * np],     al[mt][0], al[mt][1], al[mt][2], al[mt][3], bh0, bh1);
                    mma_bf16(acc[mt][2 * np + 1], ah[mt][0], ah[mt][1], ah[mt][2], ah[mt][3], bh2, bh3);
                    mma_bf16(acc[mt][2 * np + 1], ah[mt][0], ah[mt][1], ah[mt][2], ah[mt][3], bl2, bl3);
                    mma_bf16(acc[mt][2 * np + 1], al[mt][0], al[mt][1], al[mt][2], al[mt][3], bh2, bh3);
                }
            }
        }
        __syncthreads();
    }
    #pragma unroll
    for (int mt = 0; mt < 2; mt++) {
        #pragma unroll
        for (int nt = 0; nt < 4; nt++) {
            float* cc = acc[mt][nt];
            int r = bm + wm * 32 + mt * 16 + (lane >> 2);
            int cn = bn + wn * 32 + (nt >> 1) * 16 + (nt & 1) * 8 + (lane & 3) * 2;
            float b0 = bias[cn], b1 = bias[cn + 1];
            outF[(size_t)r * N + cn] = cc[0] + b0;
            outF[(size_t)r * N + cn + 1] = cc[1] + b1;
            outF[(size_t)(r + 8) * N + cn] = cc[2] + b0;
            outF[(size_t)(r + 8) * N + cn + 1] = cc[3] + b1;
        }
    }
}

// ---------------- TC scores + fused exp + inline row sums (triangular grid) ----------------
__global__ void __launch_bounds__(256) score_tc() {
    int li = blockIdx.x, bh = blockIdx.y;
    int it = (int)((sqrtf(8.f * li + 1.f) - 1.f) * 0.5f);
    while ((it + 1) * (it + 2) / 2 <= li) it++;
    while (it * (it + 1) / 2 > li) it--;
    int jt = li - it * (it + 1) / 2;
    int b = bh / Hn, h = bh % Hn;
    __shared__ __nv_bfloat16 sQh[128][40], sQl[128][40], sKh[128][40], sKl[128][40];
    int tid = threadIdx.x, wid = tid >> 5, lane = tid & 31;
    int wm = wid & 3, wn = wid >> 2;
    float acc[2][8][4] = {};
    unsigned aQh = (unsigned)__cvta_generic_to_shared(&sQh[0][0]);
    unsigned aQl = (unsigned)__cvta_generic_to_shared(&sQl[0][0]);
    unsigned aKh = (unsigned)__cvta_generic_to_shared(&sKh[0][0]);
    unsigned aKl = (unsigned)__cvta_generic_to_shared(&sKl[0][0]);
    size_t qbase = ((size_t)(b * Tn + it * 128)) * Cn + h * HDn;
    size_t kbase = ((size_t)(b * Tn + jt * 128)) * Cn + h * HDn;

    for (int ks = 0; ks < 2; ks++) {
        if (ks) __syncthreads();
        #pragma unroll
        for (int z = 0; z < 2; z++) {
            int idx = z * 256 + tid;
            int r = idx >> 2, c8 = (idx & 3) * 8;
            *(uint4*)&sQh[r][c8] = *(const uint4*)(g_qh + qbase + (size_t)r * Cn + ks * 32 + c8);
            *(uint4*)&sQl[r][c8] = *(const uint4*)(g_ql + qbase + (size_t)r * Cn + ks * 32 + c8);
            *(uint4*)&sKh[r][c8] = *(const uint4*)(g_kh + kbase + (size_t)r * Cn + ks * 32 + c8);
            *(uint4*)&sKl[r][c8] = *(const uint4*)(g_kl + kbase + (size_t)r * Cn + ks * 32 + c8);
        }
        __syncthreads();
        #pragma unroll
        for (int kh = 0; kh < 32; kh += 16) {
            unsigned qh_[2][4], ql_[2][4];
            #pragma unroll
            for (int mt = 0; mt < 2; mt++) {
                unsigned off = ((unsigned)((wm * 32 + mt * 16 + (lane & 15)) * 40 + kh + 8 * (lane >> 4))) * 2;
                ldmx4(aQh + off, qh_[mt][0], qh_[mt][1], qh_[mt][2], qh_[mt][3]);
                ldmx4(aQl + off, ql_[mt][0], ql_[mt][1], ql_[mt][2], ql_[mt][3]);
            }
            #pragma unroll
            for (int nq = 0; nq < 4; nq++) {
                int n0 = wn * 64 + nq * 16;
                unsigned boff = ((unsigned)((n0 + (lane & 15)) * 40 + kh + 8 * (lane >> 4))) * 2;
                unsigned kh0, kh1, kh2, kh3, kl0, kl1, kl2, kl3;
                ldmx4(aKh + boff, kh0, kh1, kh2, kh3);
                ldmx4(aKl + boff, kl0, kl1, kl2, kl3);
                #pragma unroll
                for (int mt = 0; mt < 2; mt++) {
                    mma_bf16(acc[mt][2 * nq],     qh_[mt][0], qh_[mt][1], qh_[mt][2], qh_[mt][3], kh0, kh2);
                    mma_bf16(acc[mt][2 * nq],     qh_[mt][0], qh_[mt][1], qh_[mt][2], qh_[mt][3], kl0, kl2);
                    mma_bf16(acc[mt][2 * nq],     ql_[mt][0], ql_[mt][1], ql_[mt][2], ql_[mt][3], kh0, kh2);
                    mma_bf16(acc[mt][2 * nq + 1], qh_[mt][0], qh_[mt][1], qh_[mt][2], qh_[mt][3], kh1, kh3);
                    mma_bf16(acc[mt][2 * nq + 1], qh_[mt][0], qh_[mt][1], qh_[mt][2], qh_[mt][3], kl1, kl3);
                    mma_bf16(acc[mt][2 * nq + 1], ql_[mt][0], ql_[mt][1], ql_[mt][2], ql_[mt][3], kh1, kh3);
                }
            }
        }
    }
    __half* erow = g_e + (size_t)bh * Tn * Tn;
    float rsum[2][2] = {};
    int diag = (it == jt);
    #pragma unroll
    for (int mt = 0; mt < 2; mt++) {
        #pragma unroll
        for (int f = 0; f < 8; f++) {
            float* cc = acc[mt][f];
            int gi = it * 128 + wm * 32 + mt * 16 + (lane >> 2);
            int gj = jt * 128 + wn * 64 + (f >> 1) * 16 + (f & 1) * 8 + 2 * (lane & 3);
            float e0 = __expf(fminf(cc[0] * 0.125f, 11.f));
            float e1 = __expf(fminf(cc[1] * 0.125f, 11.f));
            float e2 = __expf(fminf(cc[2] * 0.125f, 11.f));
            float e3 = __expf(fminf(cc[3] * 0.125f, 11.f));
            if (diag) {
                if (gj > gi) e0 = 0.f;
                if (gj + 1 > gi) e1 = 0.f;
                if (gj > gi + 8) e2 = 0.f;
                if (gj + 1 > gi + 8) e3 = 0.f;
            }
            rsum[mt][0] += e0 + e1;
            rsum[mt][1] += e2 + e3;
            *(__half2*)(erow + (size_t)gi * Tn + gj) = __floats2half2_rn(e0, e1);
            *(__half2*)(erow + (size_t)(gi + 8) * Tn + gj) = __floats2half2_rn(e2, e3);
        }
    }
    #pragma unroll
    for (int mt = 0; mt < 2; mt++) {
        #pragma unroll
        for (int hh = 0; hh < 2; hh++) {
            float v = rsum[mt][hh];
            v += __shfl_xor_sync(0xffffffffu, v, 1);
            v += __shfl_xor_sync(0xffffffffu, v, 2);
            if ((lane & 3) == 0) {
                int gi = it * 128 + wm * 32 + mt * 16 + (lane >> 2) + hh * 8;
                atomicAdd(&g_rowsum[bh * Tn + gi], v);
            }
        }
    }
}

// ---------------- per row: Em1 = expm1(e/rowsum); eu; eutot -> slot0 ----------------
__global__ void em1_row() {
    int i = blockIdx.x, bh = blockIdx.y;
    int tid = threadIdx.x;
    int lane = tid & 31, wid = tid >> 5;
    float inv = 1.f / g_rowsum[bh * Tn + i];
    const uint4* src = (const uint4*)(g_e + ((size_t)bh * Tn + i) * Tn);
    uint4* dst = (uint4*)(g_c + ((size_t)bh * Tn + i) * Tn);
    int nv = ((i >> 7) + 1) << 4;
    float se = 0.f;
    if (tid < nv) {
        uint4 pk = src[tid];
        const __half2* hp = (const __half2*)&pk;
        uint4 outp;
        __half2* op = (__half2*)&outp;
        #pragma unroll
        for (int z = 0; z < 4; z++) {
            float2 f = __half22float2(hp[z]);
            float a = em1p(f.x * inv);
            float bb = em1p(f.y * inv);
            se += a + bb;
            op[z] = __floats2half2_rn(a, bb);
        }
        dst[tid] = outp;
    }
    se += __shfl_xor_sync(0xffffffffu, se, 16);
    se += __shfl_xor_sync(0xffffffffu, se, 8);
    se += __shfl_xor_sync(0xffffffffu, se, 4);
    se += __shfl_xor_sync(0xffffffffu, se, 2);
    se += __shfl_xor_sync(0xffffffffu, se, 1);
    __shared__ float red[8];
    if (lane == 0) red[wid] = se;
    __syncthreads();
    if (tid == 0) {
        float s = red[0] + red[1] + red[2] + red[3] + red[4] + red[5] + red[6] + red[7];
        float eu = __expf(-LOGT - __logf(s + (float)Tn));
        g_eu[bh * Tn + i] = eu;
        atomicAdd(&g_tots[bh], eu);
    }
}

// ---------------- Sinkhorn row pass: warp-per-row ----------------
__global__ void sink_row_f(int slot_in, int slot_out) {
    int r0 = blockIdx.x * 8, bh = blockIdx.y;
    int tid = threadIdx.x, lane = tid & 31, w = tid >> 5;
    __shared__ float sev[Tn];
    __shared__ float sred[8];
    int jmax = r0 + 8;
    for (int j = tid; j < jmax; j += 256) sev[j] = g_ev[bh * Tn + j];
    float evtot = g_tots[slot_in * BHn + bh];
    __syncthreads();
    int i = r0 + w;
    const uint4* cv = (const uint4*)(g_c + ((size_t)bh * Tn + i) * Tn);
    int nv = (i + 8) >> 3;
    float s = 0.f;
    for (int vi = lane; vi < nv; vi += 32) {
        uint4 pk = cv[vi];
        const __half2* hp = (const __half2*)&pk;
        int jb = vi * 8;
        #pragma unroll
        for (int z = 0; z < 4; z++) {
            float2 f = __half22float2(hp[z]);
            s += f.x * sev[jb + 2 * z] + f.y * sev[jb + 2 * z + 1];
        }
    }
    s += __shfl_xor_sync(0xffffffffu, s, 16);
    s += __shfl_xor_sync(0xffffffffu, s, 8);
    s += __shfl_xor_sync(0xffffffffu, s, 4);
    s += __shfl_xor_sync(0xffffffffu, s, 2);
    s += __shfl_xor_sync(0xffffffffu, s, 1);
    if (lane == 0) {
        float eu = __expf(-LOGT - __logf(s + evtot));
        g_eu[bh * Tn + i] = eu;
        sred[w] = eu;
    }
    __syncthreads();
    if (tid == 0)
        atomicAdd(&g_tots[slot_out * BHn + bh],
                  sred[0] + sred[1] + sred[2] + sred[3] + sred[4] + sred[5] + sred[6] + sred[7]);
}

// ---------------- Sinkhorn col pass: partial over i-chunks ----------------
__global__ void sink_col_part() {
    int cb = blockIdx.x;
    int ic = blockIdx.y;
    int bh = blockIdx.z;
    int tid = threadIdx.x;
    int j0 = cb * 512 + tid * 2;
    int is = ic * 256;
    float* part = g_cpart + (size_t)(ic * BHn + bh) * Tn;
    if (cb * 512 >= is + 256) {
        part[j0] = 0.f;
        part[j0 + 1] = 0.f;
        return;
    }
    __shared__ float seu[256];
    seu[tid] = g_eu[bh * Tn + is + tid];
    __syncthreads();
    const __half* base = g_c + (size_t)bh * Tn * Tn + j0;
    float s0 = 0.f, s1 = 0.f;
    #pragma unroll 4
    for (int r = 0; r < 256; r++) {
        __half2 hh = *(const __half2*)(base + (size_t)(is + r) * Tn);
        float2 f = __half22float2(hh);
        float ui = seu[r];
        s0 += f.x * ui;
        s1 += f.y * ui;
    }
    part[j0] = s0;
    part[j0 + 1] = s1;
}

// ---------------- mid col finalize: writes ev + evtot slot ----------------
__global__ void sink_col_fin(int slot_in, int slot_out) {
    int bh = blockIdx.y;
    int tid = threadIdx.x;
    int j = blockIdx.x * 256 + tid;
    float s = 0.f;
    #pragma unroll
    for (int ic = 0; ic < 8; ic++)
        s += g_cpart[(size_t)(ic * BHn + bh) * Tn + j];
    float ev = __expf(-LOGT - __logf(s + g_tots[slot_in * BHn + bh]));
    g_ev[bh * Tn + j] = ev;
    __shared__ float red[256];
    red[tid] = ev; __syncthreads();
    for (int o = 128; o > 0; o >>= 1) { if (tid < o) red[tid] += red[tid + o]; __syncthreads(); }
    if (tid == 0) atomicAdd(&g_tots[slot_out * BHn + bh], red[0]);
}

// ---------------- final col pass fused with W build ----------------
__global__ void sink_col_finw(int slot_in) {
    int bh = blockIdx.y;
    int tid = threadIdx.x;
    int jb = blockIdx.x * 256;
    int j = jb + tid;
    int b = bh / Hn, h = bh % Hn;
    float s = 0.f;
    #pragma unroll
    for (int ic = 0; ic < 8; ic++)
        s += g_cpart[(size_t)(ic * BHn + bh) * Tn + j];
    float ev = __expf(-LOGT - __logf(s + g_tots[slot_in * BHn + bh]));
    __shared__ float sev[256];
    sev[tid] = ev;
    __syncthreads();
    int d = tid & 63, rr = tid >> 6;
    const float* Vbase = g_qkv + (size_t)b * Tn * N3 + 2 * Cn + h * HDn + d;
    float part = 0.f;
    for (int r = rr; r < 256; r += 4) {
        int jj = jb + r;
        float w = sev[r] * Vbase[(size_t)jj * N3];
        part += w;
        float ws = fminf(fmaxf(w * WSCALE, -32768.f), 32768.f);
        __half hi = __float2half(ws);
        g_wh[((size_t)bh * Tn + jj) * HDn + d] = hi;
        g_wl[((size_t)bh * Tn + jj) * HDn + d] = __float2half(ws - __half2float(hi));
    }
    __shared__ float red[256];
    red[tid] = part;
    __syncthreads();
    if (tid < 128) red[tid] += red[tid + 128];
    __syncthreads();
    if (tid < 64) atomicAdd(&g_wtot[bh * HDn + tid], red[tid] + red[tid + 64]);
}

// ---------------- pi@V via fp16 TC; y written as bf16 hi/lo ----------------
__global__ void __launch_bounds__(256) pi_v_tc() {
    int bh = blockIdx.y;
    int b = bh / Hn, h = bh % Hn;
    int it = gridDim.x - 1 - blockIdx.x;
    int i0 = it * 128;
    __shared__ __half sA[128][72];
    __shared__ __half sWh[64][72], sWl[64][72];
    int tid = threadIdx.x, wid = tid >> 5, lane = tid & 31;
    int wm = wid & 3, wn = wid >> 2;
    float acc[2][4][4] = {};
    unsigned aA = (unsigned)__cvta_generic_to_shared(&sA[0][0]);
    unsigned aWh = (unsigned)__cvta_generic_to_shared(&sWh[0][0]);
    unsigned aWl = (unsigned)__cvta_generic_to_shared(&sWl[0][0]);

    for (int jc = 0; jc < i0 + 128; jc += 64) {
        if (jc) __syncthreads();
        #pragma unroll
        for (int z = 0; z < 4; z++) {
            int idx = z * 256 + tid;
            int r = idx >> 3, c8 = (idx & 7) * 8;
            *(uint4*)&sA[r][c8] = *(const uint4*)(g_c + ((size_t)bh * Tn + i0 + r) * Tn + jc + c8);
        }
        #pragma unroll
        for (int z = 0; z < 2; z++) {
            int idx = z * 256 + tid;
            int r = idx >> 3, c8 = (idx & 7) * 8;
            *(uint4*)&sWh[r][c8] = *(const uint4*)(g_wh + ((size_t)bh * Tn + jc + r) * HDn + c8);
            *(uint4*)&sWl[r][c8] = *(const uint4*)(g_wl + ((size_t)bh * Tn + jc + r) * HDn + c8);
        }
        __syncthreads();
        #pragma unroll
        for (int kh = 0; kh < 64; kh += 16) {
            unsigned a_[2][4];
            #pragma unroll
            for (int mt = 0; mt < 2; mt++) {
                unsigned off = ((unsigned)((wm * 32 + mt * 16 + (lane & 15)) * 72 + kh + 8 * (lane >> 4))) * 2;
                ldmx4(aA + off, a_[mt][0], a_[mt][1], a_[mt][2], a_[mt][3]);
            }
            #pragma unroll
            for (int nq = 0; nq < 2; nq++) {
                int n0 = wn * 32 + nq * 16;
                unsigned boff = ((unsigned)((kh + (lane & 7) + 8 * ((lane >> 3) & 1)) * 72 + n0 + 8 * (lane >> 4))) * 2;
                unsigned bh0, bh1, bh2, bh3, bl0, bl1, bl2, bl3;
                ldmx4t(aWh + boff, bh0, bh1, bh2, bh3);
                ldmx4t(aWl + boff, bl0, bl1, bl2, bl3);
                #pragma unroll
                for (int mt = 0; mt < 2; mt++) {
                    mma_f16(acc[mt][2 * nq],     a_[mt][0], a_[mt][1], a_[mt][2], a_[mt][3], bh0, bh1);
                    mma_f16(acc[mt][2 * nq],     a_[mt][0], a_[mt][1], a_[mt][2], a_[mt][3], bl0, bl1);
                    mma_f16(acc[mt][2 * nq + 1], a_[mt][0], a_[mt][1], a_[mt][2], a_[mt][3], bh2, bh3);
                    mma_f16(acc[mt][2 * nq + 1], a_[mt][0], a_[mt][1], a_[mt][2], a_[mt][3], bl2, bl3);
                }
            }
        }
    }
    #pragma unroll
    for (int mt = 0; mt < 2; mt++) {
        #pragma unroll
        for (int f = 0; f < 4; f++) {
            float* cc = acc[mt][f];
            int r = i0 + wm * 32 + mt * 16 + (lane >> 2);
            int d = wn * 32 + f * 8 + 2 * (lane & 3);
            float wt0 = g_wtot[bh * HDn + d], wt1 = g_wtot[bh * HDn + d + 1];
            float eu0 = g_eu[bh * Tn + r] * 2048.f;
            float eu1 = g_eu[bh * Tn + r + 8] * 2048.f;
            float y0 = (cc[0] * WINV + wt0) * eu0;
            float y1 = (cc[1] * WINV + wt1) * eu0;
            float y2 = (cc[2] * WINV + wt0) * eu1;
            float y3 = (cc[3] * WINV + wt1) * eu1;
            size_t base = ((size_t)(b * Tn) + r) * Cn + h * HDn + d;
            __nv_bfloat16 h0 = __float2bfloat16(y0), h1 = __float2bfloat16(y1);
            __nv_bfloat16 h2 = __float2bfloat16(y2), h3 = __float2bfloat16(y3);
            g_ah[base] = h0;
            g_ah[base + 1] = h1;
            g_ah[base + (size_t)8 * Cn] = h2;
            g_ah[base + (size_t)8 * Cn + 1] = h3;
            g_al[base] = __float2bfloat16(y0 - __bfloat162float(h0));
            g_al[base + 1] = __float2bfloat16(y1 - __bfloat162float(h1));
            g_al[base + (size_t)8 * Cn] = __float2bfloat16(y2 - __bfloat162float(h2));
            g_al[base + (size_t)8 * Cn + 1] = __float2bfloat16(y3 - __bfloat162float(h3));
        }
    }
}

// ---------------- launch ----------------
extern "C" void kernel_launch(void* const* d_in, const int* in_sizes, int n_in,
                              void* d_out, int out_size) {
    const float* x      = (const float*)d_in[0];
    const float* t      = (const float*)d_in[1];
    const float* ln1_w  = (const float*)d_in[2];
    const float* ln1_b  = (const float*)d_in[3];
    const float* attn_w = (const float*)d_in[4];
    const float* attn_b = (const float*)d_in[5];
    const float* proj_w = (const float*)d_in[6];
    const float* proj_b = (const float*)d_in[7];
    const float* ln2_w  = (const float*)d_in[8];
    const float* ln2_b  = (const float*)d_in[9];
    const float* fc_w   = (const float*)d_in[10];
    const float* fc_b   = (const float*)d_in[11];
    const float* fc2_w  = (const float*)d_in[12];
    const float* fc2_b  = (const float*)d_in[13];
    float* out = (float*)d_out;

    float *p_qkv, *p_h;
    __nv_bfloat16 *p_ah, *p_al, *p_a2h, *p_a2l, *p_bh, *p_bl;
    cudaGetSymbolAddress((void**)&p_qkv, g_qkv);
    cudaGetSymbolAddress((void**)&p_h,   g_h);
    cudaGetSymbolAddress((void**)&p_ah,  g_ah);
    cudaGetSymbolAddress((void**)&p_al,  g_al);
    cudaGetSymbolAddress((void**)&p_a2h, g_a2h);
    cudaGetSymbolAddress((void**)&p_a2l, g_a2l);
    cudaGetSymbolAddress((void**)&p_bh,  g_bh);
    cudaGetSymbolAddress((void**)&p_bl,  g_bl);

    static int smem_set = 0;
    const int GSM = 75776;
    const int GSM64 = 55296;
    if (!smem_set) {
        cudaFuncSetAttribute(gemm_bf, cudaFuncAttributeMaxDynamicSharedMemorySize, GSM);
        cudaFuncSetAttribute(gemm_bf64, cudaFuncAttributeMaxDynamicSharedMemorySize, GSM64);
        smem_set = 1;
    }

    // ---- setup ----
    zero_misc<<<96, 256>>>();
    conv_w_all<<<(WTOTAL / 4 + 255) / 256, 256>>>(attn_w, proj_w, fc_w, fc2_w);

    // ---- attention sub-block ----
    ln_bf<<<ROWS, 256>>>(x, t, ln1_w, ln1_b, p_ah, p_al);
    gemm_bf<<<dim3(N3 / 128, ROWS / 128), 256, GSM>>>(p_ah, p_al, p_bh + WOFF_QKV, p_bl + WOFF_QKV, attn_b,
                                                      p_qkv, nullptr, nullptr, ROWS, N3, KA_LN, 0, 2);
    score_tc<<<dim3(136, BHn), 256>>>();
    em1_row<<<dim3(Tn, BHn), 256>>>();

    // sinkhorn remaining 5 passes
    sink_col_part<<<dim3(4, 8, BHn), 256>>>();
    sink_col_fin<<<dim3(8, BHn), 256>>>(0, 1);
    sink_row_f<<<dim3(Tn / 8, BHn), 256>>>(1, 2);
    sink_col_part<<<dim3(4, 8, BHn), 256>>>();
    sink_col_fin<<<dim3(8, BHn), 256>>>(2, 3);
    sink_row_f<<<dim3(Tn / 8, BHn), 256>>>(3, 4);
    sink_col_part<<<dim3(4, 8, BHn), 256>>>();
    sink_col_finw<<<dim3(8, BHn), 256>>>(4);

    pi_v_tc<<<dim3(Tn / 128, BHn), 256>>>();

    // proj (64-row tiles)
    gemm_bf64<<<dim3(Cn / 128, ROWS / 64), 256, GSM64>>>(p_ah, p_al, p_bh + WOFF_PRJ, p_bl + WOFF_PRJ, proj_b,
                                                         p_h, ROWS, Cn, Cn);

    // ---- MLP sub-block ----
    ln_bf<<<ROWS, 256>>>(p_h, t, ln2_w, ln2_b, p_ah, p_al);
    gemm_bf<<<dim3(N4 / 128, ROWS / 128), 256, GSM>>>(p_ah, p_al, p_bh + WOFF_FC, p_bl + WOFF_FC, fc_b,
                                                      nullptr, p_a2h, p_a2l, ROWS, N4, KA_LN, 1, 1);
    gemm_bf64<<<dim3(Cn / 128, ROWS / 64), 256, GSM64>>>(p_a2h, p_a2l, p_bh + WOFF_FC2, p_bl + WOFF_FC2, fc2_b,
                                                         out, ROWS, Cn, N4);
}

// round 12
// speedup vs baseline: 6.1447x; 1.0033x over previous
#include <cuda_runtime.h>
#include <cuda_fp16.h>
#include <cuda_bf16.h>
#include <math.h>

#define Tn 2048
#define Cn 384
#define Hn 6
#define HDn 64
#define Bn 2
#define BHn 12
#define ROWS 4096
#define C1 385
#define KA_LN 416
#define N3 1152
#define N4 1536
#define LOGT 7.62461899f
#define WSCALE 512.f
#define WINV   (1.f / 512.f)

#define WOFF_QKV 0
#define WSZ_QKV  (KA_LN * N3)
#define WOFF_PRJ (WOFF_QKV + WSZ_QKV)
#define WSZ_PRJ  (Cn * Cn)
#define WOFF_FC  (WOFF_PRJ + WSZ_PRJ)
#define WSZ_FC   (KA_LN * N4)
#define WOFF_FC2 (WOFF_FC + WSZ_FC)
#define WSZ_FC2  (N4 * Cn)
#define WTOTAL   (WOFF_FC2 + WSZ_FC2)

// ---------------- scratch ----------------
__device__ __align__(16) float g_qkv[ROWS * N3];
__device__ __align__(16) __half g_e[(size_t)BHn * Tn * Tn];
__device__ __align__(16) __half g_c[(size_t)BHn * Tn * Tn];
__device__ __align__(16) __nv_bfloat16 g_qh[ROWS * Cn];
__device__ __align__(16) __nv_bfloat16 g_ql[ROWS * Cn];
__device__ __align__(16) __nv_bfloat16 g_kh[ROWS * Cn];
__device__ __align__(16) __nv_bfloat16 g_kl[ROWS * Cn];
__device__ __align__(16) __half g_wh[BHn * Tn * HDn];
__device__ __align__(16) __half g_wl[BHn * Tn * HDn];
__device__ float g_rowsum[BHn * Tn];
__device__ float g_eu[BHn * Tn];
__device__ float g_ev[BHn * Tn];
__device__ float g_tots[8 * BHn];
__device__ float g_wtot[BHn * HDn];
__device__ __align__(16) float g_cpart[8 * BHn * Tn];
__device__ __align__(16) float g_h[ROWS * Cn];
__device__ __align__(16) __nv_bfloat16 g_ah[ROWS * N4];
__device__ __align__(16) __nv_bfloat16 g_al[ROWS * N4];
__device__ __align__(16) __nv_bfloat16 g_a2h[ROWS * N4];
__device__ __align__(16) __nv_bfloat16 g_a2l[ROWS * N4];
__device__ __align__(16) __nv_bfloat16 g_bh[WTOTAL];
__device__ __align__(16) __nv_bfloat16 g_bl[WTOTAL];

// ---------------- helpers ----------------
__device__ __forceinline__ void ldmx4(unsigned addr, unsigned& r0, unsigned& r1, unsigned& r2, unsigned& r3) {
    asm volatile("ldmatrix.sync.aligned.m8n8.x4.shared.b16 {%0,%1,%2,%3},[%4];"
                 : "=r"(r0), "=r"(r1), "=r"(r2), "=r"(r3) : "r"(addr));
}
__device__ __forceinline__ void ldmx4t(unsigned addr, unsigned& r0, unsigned& r1, unsigned& r2, unsigned& r3) {
    asm volatile("ldmatrix.sync.aligned.m8n8.x4.trans.shared.b16 {%0,%1,%2,%3},[%4];"
                 : "=r"(r0), "=r"(r1), "=r"(r2), "=r"(r3) : "r"(addr));
}
__device__ __forceinline__ void mma_bf16(float* c, unsigned a0, unsigned a1, unsigned a2, unsigned a3,
                                         unsigned b0, unsigned b1) {
    asm volatile("mma.sync.aligned.m16n8k16.row.col.f32.bf16.bf16.f32 "
                 "{%0,%1,%2,%3},{%4,%5,%6,%7},{%8,%9},{%0,%1,%2,%3};"
                 : "+f"(c[0]), "+f"(c[1]), "+f"(c[2]), "+f"(c[3])
                 : "r"(a0), "r"(a1), "r"(a2), "r"(a3), "r"(b0), "r"(b1));
}
__device__ __forceinline__ void mma_f16(float* c, unsigned a0, unsigned a1, unsigned a2, unsigned a3,
                                        unsigned b0, unsigned b1) {
    asm volatile("mma.sync.aligned.m16n8k16.row.col.f32.f16.f16.f32 "
                 "{%0,%1,%2,%3},{%4,%5,%6,%7},{%8,%9},{%0,%1,%2,%3};"
                 : "+f"(c[0]), "+f"(c[1]), "+f"(c[2]), "+f"(c[3])
                 : "r"(a0), "r"(a1), "r"(a2), "r"(a3), "r"(b0), "r"(b1));
}
__device__ __forceinline__ void cpa16(unsigned dst, const void* src) {
    asm volatile("cp.async.cg.shared.global [%0],[%1],16;" :: "r"(dst), "l"(src));
}
#define CPA_COMMIT asm volatile("cp.async.commit_group;")
#define CPA_WAIT1  asm volatile("cp.async.wait_group 1;")

__device__ __forceinline__ float em1p(float x) {
    float t = fmaf(x, 0.125f, 1.f);
    t = fmaf(x * 0.14285714f, t, 1.f);
    t = fmaf(x * 0.16666667f, t, 1.f);
    t = fmaf(x * 0.2f,        t, 1.f);
    t = fmaf(x * 0.25f,       t, 1.f);
    t = fmaf(x * 0.33333333f, t, 1.f);
    t = fmaf(x * 0.5f,        t, 1.f);
    return x * t;
}

// ---------------- zero ----------------
__global__ void zero_misc() {
    int i = blockIdx.x * 256 + threadIdx.x;
    if (i < BHn * Tn) g_rowsum[i] = 0.f;
    if (i < BHn * HDn) g_wtot[i] = 0.f;
    if (i < 8 * BHn) g_tots[i] = 0.f;
}

// ---------------- weights -> bf16 hi/lo ----------------
__global__ void conv_w_all(const float* __restrict__ w0, const float* __restrict__ w1,
                           const float* __restrict__ w2, const float* __restrict__ w3) {
    int idx = blockIdx.x * 256 + threadIdx.x;
    int e = idx * 4;
    if (e >= WTOTAL) return;
    const float* src;
    int K, N, local;
    if (e < WOFF_PRJ)       { src = w0; K = C1;  N = N3; local = e - WOFF_QKV; }
    else if (e < WOFF_FC)   { src = w1; K = Cn;  N = Cn; local = e - WOFF_PRJ; }
    else if (e < WOFF_FC2)  { src = w2; K = C1;  N = N4; local = e - WOFF_FC;  }
    else                    { src = w3; K = N4;  N = Cn; local = e - WOFF_FC2; }
    int row = local / N, col = local % N;
    float4 v = (row < K) ? *(const float4*)(src + (size_t)row * N + col)
                         : make_float4(0.f, 0.f, 0.f, 0.f);
    __nv_bfloat16 h0 = __float2bfloat16(v.x), h1 = __float2bfloat16(v.y);
    __nv_bfloat16 h2 = __float2bfloat16(v.z), h3 = __float2bfloat16(v.w);
    __nv_bfloat16 hbuf[4] = {h0, h1, h2, h3};
    __nv_bfloat16 lbuf[4] = {
        __float2bfloat16(v.x - __bfloat162float(h0)), __float2bfloat16(v.y - __bfloat162float(h1)),
        __float2bfloat16(v.z - __bfloat162float(h2)), __float2bfloat16(v.w - __bfloat162float(h3))};
    *(uint2*)(g_bh + e) = *(uint2*)hbuf;
    *(uint2*)(g_bl + e) = *(uint2*)lbuf;
}

// ---------------- LayerNorm -> bf16 hi/lo ----------------
__global__ void ln_bf(const float* __restrict__ x, const float* __restrict__ t,
                      const float* __restrict__ w, const float* __restrict__ bb,
                      __nv_bfloat16* __restrict__ oh, __nv_bfloat16* __restrict__ ol) {
    int row = blockIdx.x;
    int tid = threadIdx.x;
    __shared__ float sx[C1];
    __shared__ float red[256];
    float s1 = 0.f;
    for (int c = tid; c < C1; c += 256) {
        float v = (c < Cn) ? x[(size_t)row * Cn + c] : t[0];
        sx[c] = v;
        s1 += v;
    }
    red[tid] = s1; __syncthreads();
    for (int o = 128; o > 0; o >>= 1) { if (tid < o) red[tid] += red[tid + o]; __syncthreads(); }
    float mean = red[0] * (1.f / C1);
    __syncthreads();
    float s2 = 0.f;
    for (int c = tid; c < C1; c += 256) { float d = sx[c] - mean; s2 += d * d; }
    red[tid] = s2; __syncthreads();
    for (int o = 128; o > 0; o >>= 1) { if (tid < o) red[tid] += red[tid + o]; __syncthreads(); }
    float rs = rsqrtf(red[0] * (1.f / C1) + 1e-5f);
    for (int c = tid; c < C1; c += 256) {
        float v = (sx[c] - mean) * rs * w[c] + bb[c];
        __nv_bfloat16 hi = __float2bfloat16(v);
        oh[(size_t)row * KA_LN + c] = hi;
        ol[(size_t)row * KA_LN + c] = __float2bfloat16(v - __bfloat162float(hi));
    }
    if (tid < KA_LN - C1) {
        oh[(size_t)row * KA_LN + C1 + tid] = __float2bfloat16(0.f);
        ol[(size_t)row * KA_LN + C1 + tid] = __float2bfloat16(0.f);
    }
}

// ---------------- unified pipelined bf16 GEMM, 64x128 tile ----------------
// obf=0: fp32 out. obf=1: gelu(if act) + bf16 hi/lo out. obf=2: fp32 out + q/k bf16 split.
__global__ void __launch_bounds__(256) gemm64u(const __nv_bfloat16* __restrict__ Ah,
                                               const __nv_bfloat16* __restrict__ Al,
                                               const __nv_bfloat16* __restrict__ Bh,
                                               const __nv_bfloat16* __restrict__ Bl,
                                               const float* __restrict__ bias,
                                               float* __restrict__ outF,
                                               __nv_bfloat16* __restrict__ oAh,
                                               __nv_bfloat16* __restrict__ oAl,
                                               int M, int N, int Ka, int act, int obf) {
    extern __shared__ __nv_bfloat16 dyn[];
    __nv_bfloat16* sA = dyn;               // 2 stages x 2 hl x 2560
    __nv_bfloat16* sB = dyn + 4 * 2560;    // 2 stages x 2 hl x 4352
    int tid = threadIdx.x;
    int wid = tid >> 5, lane = tid & 31;
    int wm = wid & 1, wn = wid >> 1;       // 2 m-warps x 4 n-warps
    int bm = blockIdx.y * 64, bn = blockIdx.x * 128;
    float acc[2][4][4] = {};
    unsigned sAu = (unsigned)__cvta_generic_to_shared(sA);
    unsigned sBu = (unsigned)__cvta_generic_to_shared(sB);

    int nk = Ka >> 5;
    auto load_stage = [&](int kt, int st) {
        unsigned aH = sAu + (st * 2 + 0) * 2560 * 2;
        unsigned aL = sAu + (st * 2 + 1) * 2560 * 2;
        unsigned bH = sBu + (st * 2 + 0) * 4352 * 2;
        unsigned bL = sBu + (st * 2 + 1) * 4352 * 2;
        int k0 = kt * 32;
        {
            int row = tid >> 2, cq = (tid & 3) * 8;
            cpa16(aH + (row * 40 + cq) * 2, Ah + (size_t)(bm + row) * Ka + k0 + cq);
            cpa16(aL + (row * 40 + cq) * 2, Al + (size_t)(bm + row) * Ka + k0 + cq);
        }
        #pragma unroll
        for (int z = 0; z < 2; z++) {
            int idx = z * 256 + tid;
            int row = idx >> 4, cq = (idx & 15) * 8;
            cpa16(bH + (row * 136 + cq) * 2, Bh + (size_t)(k0 + row) * N + bn + cq);
            cpa16(bL + (row * 136 + cq) * 2, Bl + (size_t)(k0 + row) * N + bn + cq);
        }
    };

    load_stage(0, 0);
    CPA_COMMIT;
    for (int kt = 0; kt < nk; kt++) {
        int cur = kt & 1;
        if (kt + 1 < nk) load_stage(kt + 1, cur ^ 1);
        CPA_COMMIT;
        CPA_WAIT1;
        __syncthreads();
        unsigned aH = sAu + (cur * 2 + 0) * 2560 * 2;
        unsigned aL = sAu + (cur * 2 + 1) * 2560 * 2;
        unsigned bH = sBu + (cur * 2 + 0) * 4352 * 2;
        unsigned bL = sBu + (cur * 2 + 1) * 4352 * 2;
        #pragma unroll
        for (int kh = 0; kh < 32; kh += 16) {
            unsigned ah[2][4], al[2][4];
            #pragma unroll
            for (int mt = 0; mt < 2; mt++) {
                unsigned off = ((unsigned)((wm * 32 + mt * 16 + (lane & 15)) * 40 + kh + (lane >> 4) * 8)) * 2;
                ldmx4(aH + off, ah[mt][0], ah[mt][1], ah[mt][2], ah[mt][3]);
                ldmx4(aL + off, al[mt][0], al[mt][1], al[mt][2], al[mt][3]);
            }
            #pragma unroll
            for (int np = 0; np < 2; np++) {
                int n0 = wn * 32 + np * 16;
                unsigned boff = ((unsigned)((kh + (lane & 7) + 8 * ((lane >> 3) & 1)) * 136 + n0 + 8 * (lane >> 4))) * 2;
                unsigned bh0, bh1, bh2, bh3, bl0, bl1, bl2, bl3;
                ldmx4t(bH + boff, bh0, bh1, bh2, bh3);
                ldmx4t(bL + boff, bl0, bl1, bl2, bl3);
                #pragma unroll
                for (int mt = 0; mt < 2; mt++) {
                    mma_bf16(acc[mt][2 * np],     ah[mt][0], ah[mt][1], ah[mt][2], ah[mt][3], bh0, bh1);
                    mma_bf16(acc[mt][2 * np],     ah[mt][0], ah[mt][1], ah[mt][2], ah[mt][3], bl0, bl1);
                    mma_bf16(acc[mt][2 * np],     al[mt][0], al[mt][1], al[mt][2], al[mt][3], bh0, bh1);
                    mma_bf16(acc[mt][2 * np + 1], ah[mt][0], ah[mt][1], ah[mt][2], ah[mt][3], bh2, bh3);
                    mma_bf16(acc[mt][2 * np + 1], ah[mt][0], ah[mt][1], ah[mt][2], ah[mt][3], bl2, bl3);
                    mma_bf16(acc[mt][2 * np + 1], al[mt][0], al[mt][1], al[mt][2], al[mt][3], bh2, bh3);
                }
            }
        }
        __syncthreads();
    }
    #pragma unroll
    for (int mt = 0; mt < 2; mt++) {
        #pragma unroll
        for (int nt = 0; nt < 4; nt++) {
            float* cc = acc[mt][nt];
            int r = bm + wm * 32 + mt * 16 + (lane >> 2);
            int cn = bn + wn * 32 + (nt >> 1) * 16 + (nt & 1) * 8 + (lane & 3) * 2;
            float b0 = bias[cn], b1 = bias[cn + 1];
            float v0 = cc[0] + b0, v1 = cc[1] + b1;
            float v2 = cc[2] + b0, v3 = cc[3] + b1;
            if (act == 1) {
                v0 = 0.5f * v0 * (1.f + erff(v0 * 0.70710678f));
                v1 = 0.5f * v1 * (1.f + erff(v1 * 0.70710678f));
                v2 = 0.5f * v2 * (1.f + erff(v2 * 0.70710678f));
                v3 = 0.5f * v3 * (1.f + erff(v3 * 0.70710678f));
            }
            if (obf == 1) {
                __nv_bfloat16 h0 = __float2bfloat16(v0), h1 = __float2bfloat16(v1);
                __nv_bfloat16 h2 = __float2bfloat16(v2), h3 = __float2bfloat16(v3);
                oAh[(size_t)r * N + cn] = h0;
                oAh[(size_t)r * N + cn + 1] = h1;
                oAh[(size_t)(r + 8) * N + cn] = h2;
                oAh[(size_t)(r + 8) * N + cn + 1] = h3;
                oAl[(size_t)r * N + cn] = __float2bfloat16(v0 - __bfloat162float(h0));
                oAl[(size_t)r * N + cn + 1] = __float2bfloat16(v1 - __bfloat162float(h1));
                oAl[(size_t)(r + 8) * N + cn] = __float2bfloat16(v2 - __bfloat162float(h2));
                oAl[(size_t)(r + 8) * N + cn + 1] = __float2bfloat16(v3 - __bfloat162float(h3));
            } else {
                outF[(size_t)r * N + cn] = v0;
                outF[(size_t)r * N + cn + 1] = v1;
                outF[(size_t)(r + 8) * N + cn] = v2;
                outF[(size_t)(r + 8) * N + cn + 1] = v3;
                if (obf == 2 && cn < 2 * Cn) {
                    int isK = cn >= Cn;
                    int c2 = cn - isK * Cn;
                    __nv_bfloat16* H = isK ? g_kh : g_qh;
                    __nv_bfloat16* L = isK ? g_kl : g_ql;
                    __nv_bfloat16 h0 = __float2bfloat16(v0), h1 = __float2bfloat16(v1);
                    __nv_bfloat16 h2 = __float2bfloat16(v2), h3 = __float2bfloat16(v3);
                    H[(size_t)r * Cn + c2] = h0;
                    H[(size_t)r * Cn + c2 + 1] = h1;
                    H[(size_t)(r + 8) * Cn + c2] = h2;
                    H[(size_t)(r + 8) * Cn + c2 + 1] = h3;
                    L[(size_t)r * Cn + c2] = __float2bfloat16(v0 - __bfloat162float(h0));
                    L[(size_t)r * Cn + c2 + 1] = __float2bfloat16(v1 - __bfloat162float(h1));
                    L[(size_t)(r + 8) * Cn + c2] = __float2bfloat16(v2 - __bfloat162float(h2));
                    L[(size_t)(r + 8) * Cn + c2 + 1] = __float2bfloat16(v3 - __bfloat162float(h3));
                }
            }
        }
    }
}

// ---------------- TC scores + fused exp + inline row sums (triangular grid) ----------------
__global__ void __launch_bounds__(256) score_tc() {
    int li = blockIdx.x, bh = blockIdx.y;
    int it = (int)((sqrtf(8.f * li + 1.f) - 1.f) * 0.5f);
    while ((it + 1) * (it + 2) / 2 <= li) it++;
    while (it * (it + 1) / 2 > li) it--;
    int jt = li - it * (it + 1) / 2;
    int b = bh / Hn, h = bh % Hn;
    __shared__ __nv_bfloat16 sQh[128][40], sQl[128][40], sKh[128][40], sKl[128][40];
    int tid = threadIdx.x, wid = tid >> 5, lane = tid & 31;
    int wm = wid & 3, wn = wid >> 2;
    float acc[2][8][4] = {};
    unsigned aQh = (unsigned)__cvta_generic_to_shared(&sQh[0][0]);
    unsigned aQl = (unsigned)__cvta_generic_to_shared(&sQl[0][0]);
    unsigned aKh = (unsigned)__cvta_generic_to_shared(&sKh[0][0]);
    unsigned aKl = (unsigned)__cvta_generic_to_shared(&sKl[0][0]);
    size_t qbase = ((size_t)(b * Tn + it * 128)) * Cn + h * HDn;
    size_t kbase = ((size_t)(b * Tn + jt * 128)) * Cn + h * HDn;

    for (int ks = 0; ks < 2; ks++) {
        if (ks) __syncthreads();
        #pragma unroll
        for (int z = 0; z < 2; z++) {
            int idx = z * 256 + tid;
            int r = idx >> 2, c8 = (idx & 3) * 8;
            *(uint4*)&sQh[r][c8] = *(const uint4*)(g_qh + qbase + (size_t)r * Cn + ks * 32 + c8);
            *(uint4*)&sQl[r][c8] = *(const uint4*)(g_ql + qbase + (size_t)r * Cn + ks * 32 + c8);
            *(uint4*)&sKh[r][c8] = *(const uint4*)(g_kh + kbase + (size_t)r * Cn + ks * 32 + c8);
            *(uint4*)&sKl[r][c8] = *(const uint4*)(g_kl + kbase + (size_t)r * Cn + ks * 32 + c8);
        }
        __syncthreads();
        #pragma unroll
        for (int kh = 0; kh < 32; kh += 16) {
            unsigned qh_[2][4], ql_[2][4];
            #pragma unroll
            for (int mt = 0; mt < 2; mt++) {
                unsigned off = ((unsigned)((wm * 32 + mt * 16 + (lane & 15)) * 40 + kh + 8 * (lane >> 4))) * 2;
                ldmx4(aQh + off, qh_[mt][0], qh_[mt][1], qh_[mt][2], qh_[mt][3]);
                ldmx4(aQl + off, ql_[mt][0], ql_[mt][1], ql_[mt][2], ql_[mt][3]);
            }
            #pragma unroll
            for (int nq = 0; nq < 4; nq++) {
                int n0 = wn * 64 + nq * 16;
                unsigned boff = ((unsigned)((n0 + (lane & 15)) * 40 + kh + 8 * (lane >> 4))) * 2;
                unsigned kh0, kh1, kh2, kh3, kl0, kl1, kl2, kl3;
                ldmx4(aKh + boff, kh0, kh1, kh2, kh3);
                ldmx4(aKl + boff, kl0, kl1, kl2, kl3);
                #pragma unroll
                for (int mt = 0; mt < 2; mt++) {
                    mma_bf16(acc[mt][2 * nq],     qh_[mt][0], qh_[mt][1], qh_[mt][2], qh_[mt][3], kh0, kh2);
                    mma_bf16(acc[mt][2 * nq],     qh_[mt][0], qh_[mt][1], qh_[mt][2], qh_[mt][3], kl0, kl2);
                    mma_bf16(acc[mt][2 * nq],     ql_[mt][0], ql_[mt][1], ql_[mt][2], ql_[mt][3], kh0, kh2);
                    mma_bf16(acc[mt][2 * nq + 1], qh_[mt][0], qh_[mt][1], qh_[mt][2], qh_[mt][3], kh1, kh3);
                    mma_bf16(acc[mt][2 * nq + 1], qh_[mt][0], qh_[mt][1], qh_[mt][2], qh_[mt][3], kl1, kl3);
                    mma_bf16(acc[mt][2 * nq + 1], ql_[mt][0], ql_[mt][1], ql_[mt][2], ql_[mt][3], kh1, kh3);
                }
            }
        }
    }
    __half* erow = g_e + (size_t)bh * Tn * Tn;
    float rsum[2][2] = {};
    int diag = (it == jt);
    #pragma unroll
    for (int mt = 0; mt < 2; mt++) {
        #pragma unroll
        for (int f = 0; f < 8; f++) {
            float* cc = acc[mt][f];
            int gi = it * 128 + wm * 32 + mt * 16 + (lane >> 2);
            int gj = jt * 128 + wn * 64 + (f >> 1) * 16 + (f & 1) * 8 + 2 * (lane & 3);
            float e0 = __expf(fminf(cc[0] * 0.125f, 11.f));
            float e1 = __expf(fminf(cc[1] * 0.125f, 11.f));
            float e2 = __expf(fminf(cc[2] * 0.125f, 11.f));
            float e3 = __expf(fminf(cc[3] * 0.125f, 11.f));
            if (diag) {
                if (gj > gi) e0 = 0.f;
                if (gj + 1 > gi) e1 = 0.f;
                if (gj > gi + 8) e2 = 0.f;
                if (gj + 1 > gi + 8) e3 = 0.f;
            }
            rsum[mt][0] += e0 + e1;
            rsum[mt][1] += e2 + e3;
            *(__half2*)(erow + (size_t)gi * Tn + gj) = __floats2half2_rn(e0, e1);
            *(__half2*)(erow + (size_t)(gi + 8) * Tn + gj) = __floats2half2_rn(e2, e3);
        }
    }
    #pragma unroll
    for (int mt = 0; mt < 2; mt++) {
        #pragma unroll
        for (int hh = 0; hh < 2; hh++) {
            float v = rsum[mt][hh];
            v += __shfl_xor_sync(0xffffffffu, v, 1);
            v += __shfl_xor_sync(0xffffffffu, v, 2);
            if ((lane & 3) == 0) {
                int gi = it * 128 + wm * 32 + mt * 16 + (lane >> 2) + hh * 8;
                atomicAdd(&g_rowsum[bh * Tn + gi], v);
            }
        }
    }
}

// ---------------- per row: Em1 = expm1(e/rowsum); eu; eutot -> slot0 ----------------
__global__ void em1_row() {
    int i = blockIdx.x, bh = blockIdx.y;
    int tid = threadIdx.x;
    int lane = tid & 31, wid = tid >> 5;
    float inv = 1.f / g_rowsum[bh * Tn + i];
    const uint4* src = (const uint4*)(g_e + ((size_t)bh * Tn + i) * Tn);
    uint4* dst = (uint4*)(g_c + ((size_t)bh * Tn + i) * Tn);
    int nv = ((i >> 7) + 1) << 4;
    float se = 0.f;
    if (tid < nv) {
        uint4 pk = src[tid];
        const __half2* hp = (const __half2*)&pk;
        uint4 outp;
        __half2* op = (__half2*)&outp;
        #pragma unroll
        for (int z = 0; z < 4; z++) {
            float2 f = __half22float2(hp[z]);
            float a = em1p(f.x * inv);
            float bb = em1p(f.y * inv);
            se += a + bb;
            op[z] = __floats2half2_rn(a, bb);
        }
        dst[tid] = outp;
    }
    se += __shfl_xor_sync(0xffffffffu, se, 16);
    se += __shfl_xor_sync(0xffffffffu, se, 8);
    se += __shfl_xor_sync(0xffffffffu, se, 4);
    se += __shfl_xor_sync(0xffffffffu, se, 2);
    se += __shfl_xor_sync(0xffffffffu, se, 1);
    __shared__ float red[8];
    if (lane == 0) red[wid] = se;
    __syncthreads();
    if (tid == 0) {
        float s = red[0] + red[1] + red[2] + red[3] + red[4] + red[5] + red[6] + red[7];
        float eu = __expf(-LOGT - __logf(s + (float)Tn));
        g_eu[bh * Tn + i] = eu;
        atomicAdd(&g_tots[bh], eu);
    }
}

// ---------------- Sinkhorn row pass: warp-per-row ----------------
__global__ void sink_row_f(int slot_in, int slot_out) {
    int r0 = blockIdx.x * 8, bh = blockIdx.y;
    int tid = threadIdx.x, lane = tid & 31, w = tid >> 5;
    __shared__ float sev[Tn];
    __shared__ float sred[8];
    int jmax = r0 + 8;
    for (int j = tid; j < jmax; j += 256) sev[j] = g_ev[bh * Tn + j];
    float evtot = g_tots[slot_in * BHn + bh];
    __syncthreads();
    int i = r0 + w;
    const uint4* cv = (const uint4*)(g_c + ((size_t)bh * Tn + i) * Tn);
    int nv = (i + 8) >> 3;
    float s = 0.f;
    for (int vi = lane; vi < nv; vi += 32) {
        uint4 pk = cv[vi];
        const __half2* hp = (const __half2*)&pk;
        int jb = vi * 8;
        #pragma unroll
        for (int z = 0; z < 4; z++) {
            float2 f = __half22float2(hp[z]);
            s += f.x * sev[jb + 2 * z] + f.y * sev[jb + 2 * z + 1];
        }
    }
    s += __shfl_xor_sync(0xffffffffu, s, 16);
    s += __shfl_xor_sync(0xffffffffu, s, 8);
    s += __shfl_xor_sync(0xffffffffu, s, 4);
    s += __shfl_xor_sync(0xffffffffu, s, 2);
    s += __shfl_xor_sync(0xffffffffu, s, 1);
    if (lane == 0) {
        float eu = __expf(-LOGT - __logf(s + evtot));
        g_eu[bh * Tn + i] = eu;
        sred[w] = eu;
    }
    __syncthreads();
    if (tid == 0)
        atomicAdd(&g_tots[slot_out * BHn + bh],
                  sred[0] + sred[1] + sred[2] + sred[3] + sred[4] + sred[5] + sred[6] + sred[7]);
}

// ---------------- Sinkhorn col pass: partial over i-chunks ----------------
__global__ void sink_col_part() {
    int cb = blockIdx.x;
    int ic = blockIdx.y;
    int bh = blockIdx.z;
    int tid = threadIdx.x;
    int j0 = cb * 512 + tid * 2;
    int is = ic * 256;
    float* part = g_cpart + (size_t)(ic * BHn + bh) * Tn;
    if (cb * 512 >= is + 256) {
        part[j0] = 0.f;
        part[j0 + 1] = 0.f;
        return;
    }
    __shared__ float seu[256];
    seu[tid] = g_eu[bh * Tn + is + tid];
    __syncthreads();
    const __half* base = g_c + (size_t)bh * Tn * Tn + j0;
    float s0 = 0.f, s1 = 0.f;
    #pragma unroll 4
    for (int r = 0; r < 256; r++) {
        __half2 hh = *(const __half2*)(base + (size_t)(is + r) * Tn);
        float2 f = __half22float2(hh);
        float ui = seu[r];
        s0 += f.x * ui;
        s1 += f.y * ui;
    }
    part[j0] = s0;
    part[j0 + 1] = s1;
}

// ---------------- mid col finalize ----------------
__global__ void sink_col_fin(int slot_in, int slot_out) {
    int bh = blockIdx.y;
    int tid = threadIdx.x;
    int j = blockIdx.x * 256 + tid;
    float s = 0.f;
    #pragma unroll
    for (int ic = 0; ic < 8; ic++)
        s += g_cpart[(size_t)(ic * BHn + bh) * Tn + j];
    float ev = __expf(-LOGT - __logf(s + g_tots[slot_in * BHn + bh]));
    g_ev[bh * Tn + j] = ev;
    __shared__ float red[256];
    red[tid] = ev; __syncthreads();
    for (int o = 128; o > 0; o >>= 1) { if (tid < o) red[tid] += red[tid + o]; __syncthreads(); }
    if (tid == 0) atomicAdd(&g_tots[slot_out * BHn + bh], red[0]);
}

// ---------------- final col pass fused with W build ----------------
__global__ void sink_col_finw(int slot_in) {
    int bh = blockIdx.y;
    int tid = threadIdx.x;
    int jb = blockIdx.x * 256;
    int j = jb + tid;
    int b = bh / Hn, h = bh % Hn;
    float s = 0.f;
    #pragma unroll
    for (int ic = 0; ic < 8; ic++)
        s += g_cpart[(size_t)(ic * BHn + bh) * Tn + j];
    float ev = __expf(-LOGT - __logf(s + g_tots[slot_in * BHn + bh]));
    __shared__ float sev[256];
    sev[tid] = ev;
    __syncthreads();
    int d = tid & 63, rr = tid >> 6;
    const float* Vbase = g_qkv + (size_t)b * Tn * N3 + 2 * Cn + h * HDn + d;
    float part = 0.f;
    for (int r = rr; r < 256; r += 4) {
        int jj = jb + r;
        float w = sev[r] * Vbase[(size_t)jj * N3];
        part += w;
        float ws = fminf(fmaxf(w * WSCALE, -32768.f), 32768.f);
        __half hi = __float2half(ws);
        g_wh[((size_t)bh * Tn + jj) * HDn + d] = hi;
        g_wl[((size_t)bh * Tn + jj) * HDn + d] = __float2half(ws - __half2float(hi));
    }
    __shared__ float red[256];
    red[tid] = part;
    __syncthreads();
    if (tid < 128) red[tid] += red[tid + 128];
    __syncthreads();
    if (tid < 64) atomicAdd(&g_wtot[bh * HDn + tid], red[tid] + red[tid + 64]);
}

// ---------------- pi@V via fp16 TC; y written as bf16 hi/lo ----------------
__global__ void __launch_bounds__(256) pi_v_tc() {
    int bh = blockIdx.y;
    int b = bh / Hn, h = bh % Hn;
    int it = gridDim.x - 1 - blockIdx.x;
    int i0 = it * 128;
    __shared__ __half sA[128][72];
    __shared__ __half sWh[64][72], sWl[64][72];
    int tid = threadIdx.x, wid = tid >> 5, lane = tid & 31;
    int wm = wid & 3, wn = wid >> 2;
    float acc[2][4][4] = {};
    unsigned aA = (unsigned)__cvta_generic_to_shared(&sA[0][0]);
    unsigned aWh = (unsigned)__cvta_generic_to_shared(&sWh[0][0]);
    unsigned aWl = (unsigned)__cvta_generic_to_shared(&sWl[0][0]);

    for (int jc = 0; jc < i0 + 128; jc += 64) {
        if (jc) __syncthreads();
        #pragma unroll
        for (int z = 0; z < 4; z++) {
            int idx = z * 256 + tid;
            int r = idx >> 3, c8 = (idx & 7) * 8;
            *(uint4*)&sA[r][c8] = *(const uint4*)(g_c + ((size_t)bh * Tn + i0 + r) * Tn + jc + c8);
        }
        #pragma unroll
        for (int z = 0; z < 2; z++) {
            int idx = z * 256 + tid;
            int r = idx >> 3, c8 = (idx & 7) * 8;
            *(uint4*)&sWh[r][c8] = *(const uint4*)(g_wh + ((size_t)bh * Tn + jc + r) * HDn + c8);
            *(uint4*)&sWl[r][c8] = *(const uint4*)(g_wl + ((size_t)bh * Tn + jc + r) * HDn + c8);
        }
        __syncthreads();
        #pragma unroll
        for (int kh = 0; kh < 64; kh += 16) {
            unsigned a_[2][4];
            #pragma unroll
            for (int mt = 0; mt < 2; mt++) {
                unsigned off = ((unsigned)((wm * 32 + mt * 16 + (lane & 15)) * 72 + kh + 8 * (lane >> 4))) * 2;
                ldmx4(aA + off, a_[mt][0], a_[mt][1], a_[mt][2], a_[mt][3]);
            }
            #pragma unroll
            for (int nq = 0; nq < 2; nq++) {
                int n0 = wn * 32 + nq * 16;
                unsigned boff = ((unsigned)((kh + (lane & 7) + 8 * ((lane >> 3) & 1)) * 72 + n0 + 8 * (lane >> 4))) * 2;
                unsigned bh0, bh1, bh2, bh3, bl0, bl1, bl2, bl3;
                ldmx4t(aWh + boff, bh0, bh1, bh2, bh3);
                ldmx4t(aWl + boff, bl0, bl1, bl2, bl3);
                #pragma unroll
                for (int mt = 0; mt < 2; mt++) {
                    mma_f16(acc[mt][2 * nq],     a_[mt][0], a_[mt][1], a_[mt][2], a_[mt][3], bh0, bh1);
                    mma_f16(acc[mt][2 * nq],     a_[mt][0], a_[mt][1], a_[mt][2], a_[mt][3], bl0, bl1);
                    mma_f16(acc[mt][2 * nq + 1], a_[mt][0], a_[mt][1], a_[mt][2], a_[mt][3], bh2, bh3);
                    mma_f16(acc[mt][2 * nq + 1], a_[mt][0], a_[mt][1], a_[mt][2], a_[mt][3], bl2, bl3);
                }
            }
        }
    }
    #pragma unroll
    for (int mt = 0; mt < 2; mt++) {
        #pragma unroll
        for (int f = 0; f < 4; f++) {
            float* cc = acc[mt][f];
            int r = i0 + wm * 32 + mt * 16 + (lane >> 2);
            int d = wn * 32 + f * 8 + 2 * (lane & 3);
            float wt0 = g_wtot[bh * HDn + d], wt1 = g_wtot[bh * HDn + d + 1];
            float eu0 = g_eu[bh * Tn + r] * 2048.f;
            float eu1 = g_eu[bh * Tn + r + 8] * 2048.f;
            float y0 = (cc[0] * WINV + wt0) * eu0;
            float y1 = (cc[1] * WINV + wt1) * eu0;
            float y2 = (cc[2] * WINV + wt0) * eu1;
            float y3 = (cc[3] * WINV + wt1) * eu1;
            size_t base = ((size_t)(b * Tn) + r) * Cn + h * HDn + d;
            __nv_bfloat16 h0 = __float2bfloat16(y0), h1 = __float2bfloat16(y1);
            __nv_bfloat16 h2 = __float2bfloat16(y2), h3 = __float2bfloat16(y3);
            g_ah[base] = h0;
            g_ah[base + 1] = h1;
            g_ah[base + (size_t)8 * Cn] = h2;
            g_ah[base + (size_t)8 * Cn + 1] = h3;
            g_al[base] = __float2bfloat16(y0 - __bfloat162float(h0));
            g_al[base + 1] = __float2bfloat16(y1 - __bfloat162float(h1));
            g_al[base + (size_t)8 * Cn] = __float2bfloat16(y2 - __bfloat162float(h2));
            g_al[base + (size_t)8 * Cn + 1] = __float2bfloat16(y3 - __bfloat162float(h3));
        }
    }
}

// ---------------- launch ----------------
extern "C" void kernel_launch(void* const* d_in, const int* in_sizes, int n_in,
                              void* d_out, int out_size) {
    const float* x      = (const float*)d_in[0];
    const float* t      = (const float*)d_in[1];
    const float* ln1_w  = (const float*)d_in[2];
    const float* ln1_b  = (const float*)d_in[3];
    const float* attn_w = (const float*)d_in[4];
    const float* attn_b = (const float*)d_in[5];
    const float* proj_w = (const float*)d_in[6];
    const float* proj_b = (const float*)d_in[7];
    const float* ln2_w  = (const float*)d_in[8];
    const float* ln2_b  = (const float*)d_in[9];
    const float* fc_w   = (const float*)d_in[10];
    const float* fc_b   = (const float*)d_in[11];
    const float* fc2_w  = (const float*)d_in[12];
    const float* fc2_b  = (const float*)d_in[13];
    float* out = (float*)d_out;

    float *p_qkv, *p_h;
    __nv_bfloat16 *p_ah, *p_al, *p_a2h, *p_a2l, *p_bh, *p_bl;
    cudaGetSymbolAddress((void**)&p_qkv, g_qkv);
    cudaGetSymbolAddress((void**)&p_h,   g_h);
    cudaGetSymbolAddress((void**)&p_ah,  g_ah);
    cudaGetSymbolAddress((void**)&p_al,  g_al);
    cudaGetSymbolAddress((void**)&p_a2h, g_a2h);
    cudaGetSymbolAddress((void**)&p_a2l, g_a2l);
    cudaGetSymbolAddress((void**)&p_bh,  g_bh);
    cudaGetSymbolAddress((void**)&p_bl,  g_bl);

    static int smem_set = 0;
    const int GSM64 = 55296;
    if (!smem_set) {
        cudaFuncSetAttribute(gemm64u, cudaFuncAttributeMaxDynamicSharedMemorySize, GSM64);
        smem_set = 1;
    }

    // ---- setup ----
    zero_misc<<<96, 256>>>();
    conv_w_all<<<(WTOTAL / 4 + 255) / 256, 256>>>(attn_w, proj_w, fc_w, fc2_w);

    // ---- attention sub-block ----
    ln_bf<<<ROWS, 256>>>(x, t, ln1_w, ln1_b, p_ah, p_al);
    gemm64u<<<dim3(N3 / 128, ROWS / 64), 256, GSM64>>>(p_ah, p_al, p_bh + WOFF_QKV, p_bl + WOFF_QKV, attn_b,
                                                       p_qkv, nullptr, nullptr, ROWS, N3, KA_LN, 0, 2);
    score_tc<<<dim3(136, BHn), 256>>>();
    em1_row<<<dim3(Tn, BHn), 256>>>();

    // sinkhorn remaining 5 passes
    sink_col_part<<<dim3(4, 8, BHn), 256>>>();
    sink_col_fin<<<dim3(8, BHn), 256>>>(0, 1);
    sink_row_f<<<dim3(Tn / 8, BHn), 256>>>(1, 2);
    sink_col_part<<<dim3(4, 8, BHn), 256>>>();
    sink_col_fin<<<dim3(8, BHn), 256>>>(2, 3);
    sink_row_f<<<dim3(Tn / 8, BHn), 256>>>(3, 4);
    sink_col_part<<<dim3(4, 8, BHn), 256>>>();
    sink_col_finw<<<dim3(8, BHn), 256>>>(4);

    pi_v_tc<<<dim3(Tn / 128, BHn), 256>>>();

    // proj
    gemm64u<<<dim3(Cn / 128, ROWS / 64), 256, GSM64>>>(p_ah, p_al, p_bh + WOFF_PRJ, p_bl + WOFF_PRJ, proj_b,
                                                       p_h, nullptr, nullptr, ROWS, Cn, Cn, 0, 0);

    // ---- MLP sub-block ----
    ln_bf<<<ROWS, 256>>>(p_h, t, ln2_w, ln2_b, p_ah, p_al);
    gemm64u<<<dim3(N4 / 128, ROWS / 64), 256, GSM64>>>(p_ah, p_al, p_bh + WOFF_FC, p_bl + WOFF_FC, fc_b,
                                                       nullptr, p_a2h, p_a2l, ROWS, N4, KA_LN, 1, 1);
    gemm64u<<<dim3(Cn / 128, ROWS / 64), 256, GSM64>>>(p_a2h, p_a2l, p_bh + WOFF_FC2, p_bl + WOFF_FC2, fc2_b,
                                                       out, nullptr, nullptr, ROWS, Cn, N4, 0, 0);
}